// round 2
// baseline (speedup 1.0000x reference)
#include <cuda_runtime.h>

// Problem constants
#define NB    32      // batch
#define NHH   32      // H
#define NWW   32      // W
#define NCIN  256     // input channels
#define NCOUT 256     // output channels per group
#define NG    4       // groups
#define CING  64      // input channels per group
#define NCH   1024    // NG * NCOUT (BN channels)
#define HW    1024    // H*W
#define COC   8       // couts per conv block
#define PST   34      // padded plane row stride

typedef unsigned long long u64;

// Device scratch (no allocations allowed)
__device__ float  g_alpha[NCOUT];
__device__ u64    g_sgn2[(size_t)NCOUT * NCIN * 9];  // packed (s,s) per tap, 18.9MB... (256*256*9*8=4.7MB)
__device__ float  g_bconv[(size_t)NB * NCH * HW];    // 134 MB: [((b*G+g)*COUT+co)*HW + px]
__device__ double g_sum[NCH];
__device__ double g_sumsq[NCH];
__device__ float  g_cA[NCH];
__device__ float  g_cB[NCH];

// ---- f32x2 packed helpers (Blackwell FFMA2 path; ptxas never auto-fuses) ----
__device__ __forceinline__ u64 pk2(float lo, float hi) {
    u64 r; asm("mov.b64 %0, {%1, %2};" : "=l"(r) : "f"(lo), "f"(hi)); return r;
}
__device__ __forceinline__ void upk2(u64 v, float& lo, float& hi) {
    asm("mov.b64 {%0, %1}, %2;" : "=f"(lo), "=f"(hi) : "l"(v));
}
__device__ __forceinline__ u64 mul2(u64 a, u64 b) {
    u64 d; asm("mul.rn.f32x2 %0, %1, %2;" : "=l"(d) : "l"(a), "l"(b)); return d;
}
__device__ __forceinline__ u64 fma2(u64 a, u64 b, u64 c) {
    u64 d; asm("fma.rn.f32x2 %0, %1, %2, %3;" : "=l"(d) : "l"(a), "l"(b), "l"(c)); return d;
}
__device__ __forceinline__ u64 add2(u64 a, u64 b) {
    u64 d; asm("add.rn.f32x2 %0, %1, %2;" : "=l"(d) : "l"(a), "l"(b)); return d;
}

// ---------------------------------------------------------------------------
// Kernel 0: per-cout alpha = mean|w|, packed-sign extraction, stats zeroing
// grid: 256 blocks (one per cout), 256 threads
// ---------------------------------------------------------------------------
__global__ void prep_kernel(const float* __restrict__ w) {
    const int co = blockIdx.x;
    const int t  = threadIdx.x;

    if (t < 4) {
        g_sum[co * 4 + t]   = 0.0;
        g_sumsq[co * 4 + t] = 0.0;
    }

    const float* wc = w + (size_t)co * NCIN * 9;

    float s = 0.0f;
    for (int i = t; i < NCIN * 9; i += 256) s += fabsf(wc[i]);

    __shared__ float red[256];
    red[t] = s;
    __syncthreads();
    for (int o = 128; o > 0; o >>= 1) {
        if (t < o) red[t] += red[t + o];
        __syncthreads();
    }
    if (t == 0) g_alpha[co] = red[0] / 2304.0f;

    // packed signs: (s, s) per tap, layout [co][ci][9]
    for (int i = t; i < NCIN * 9; i += 256) {
        float sv = (wc[i] >= 0.0f) ? 1.0f : -1.0f;
        g_sgn2[(size_t)co * (NCIN * 9) + i] = pk2(sv, sv);
    }
}

// ---------------------------------------------------------------------------
// Kernel 1: binary-weight grouped conv via packed f32x2 FMA.
// Each block: (co_chunk of 8, g, b), full 32x32 plane, loop over 64 in-chans.
// Thread owns 4 pixels (2 f32x2 pairs) of one row.
// Fused per-channel sum/sumsq block reduction -> fp64 atomics.
// grid: (32, 4, 32), 256 threads.
// ---------------------------------------------------------------------------
__global__ void __launch_bounds__(256) conv_kernel(const float* __restrict__ x) {
    const int t   = threadIdx.x;
    const int co0 = blockIdx.x * COC;   // 0..255 step 8
    const int g   = blockIdx.y;         // 0..3
    const int b   = blockIdx.z;         // 0..31

    __shared__ float sp[PST * PST];          // padded input plane (4.6 KB)
    __shared__ u64   ss2[COC * CING * 9];    // packed signs (36.9 KB)
    __shared__ float red1[COC][8];
    __shared__ float red2[COC][8];

    // zero padded plane (border stays zero for SAME padding)
    for (int i = t; i < PST * PST; i += 256) sp[i] = 0.0f;

    // load packed signs for this (co chunk, group)
    for (int i = t; i < COC * CING * 9; i += 256) {
        int coi = i / (CING * 9);
        int rem = i - coi * (CING * 9);
        ss2[i] = g_sgn2[(size_t)(co0 + coi) * (NCIN * 9) + (size_t)g * (CING * 9) + rem];
    }

    u64 acc01[COC], acc23[COC];
#pragma unroll
    for (int a = 0; a < COC; a++) { acc01[a] = 0ULL; acc23[a] = 0ULL; }

    const int h  = t >> 3;          // 0..31
    const int w0 = (t & 7) * 4;     // 0,4,...,28
    const float* xb = x + ((size_t)b * NCIN + (size_t)g * CING) * HW;

    __syncthreads();

    for (int c = 0; c < CING; c++) {
        __syncthreads();   // previous iteration's reads done
        for (int i = t; i < HW; i += 256) {
            sp[(1 + (i >> 5)) * PST + 1 + (i & 31)] = xb[(size_t)c * HW + i];
        }
        __syncthreads();

        float r0[6], r1[6], r2[6];
#pragma unroll
        for (int i = 0; i < 6; i++) {
            r0[i] = sp[(h    ) * PST + w0 + i];
            r1[i] = sp[(h + 1) * PST + w0 + i];
            r2[i] = sp[(h + 2) * PST + w0 + i];
        }

        // packed sliding windows, shared across all couts:
        // p[j] = (r[j], r[j+1]); pair01 uses p[j], pair23 uses p[j+2]
        u64 p0[5], p1[5], p2[5];
#pragma unroll
        for (int j = 0; j < 5; j++) {
            p0[j] = pk2(r0[j], r0[j + 1]);
            p1[j] = pk2(r1[j], r1[j + 1]);
            p2[j] = pk2(r2[j], r2[j + 1]);
        }

        const u64* scbase = ss2 + c * 9;
#pragma unroll
        for (int co = 0; co < COC; co++) {
            const u64* s = scbase + co * (CING * 9);
            const u64 s0 = s[0], s1 = s[1], s2 = s[2];
            const u64 s3 = s[3], s4 = s[4], s5 = s[5];
            const u64 s6 = s[6], s7 = s[7], s8 = s[8];

            // two-level accumulation: 9-tap partial, then one add
            u64 t01 = mul2(s0, p0[0]);
            t01 = fma2(s1, p0[1], t01);
            t01 = fma2(s2, p0[2], t01);
            t01 = fma2(s3, p1[0], t01);
            t01 = fma2(s4, p1[1], t01);
            t01 = fma2(s5, p1[2], t01);
            t01 = fma2(s6, p2[0], t01);
            t01 = fma2(s7, p2[1], t01);
            t01 = fma2(s8, p2[2], t01);

            u64 t23 = mul2(s0, p0[2]);
            t23 = fma2(s1, p0[3], t23);
            t23 = fma2(s2, p0[4], t23);
            t23 = fma2(s3, p1[2], t23);
            t23 = fma2(s4, p1[3], t23);
            t23 = fma2(s5, p1[4], t23);
            t23 = fma2(s6, p2[2], t23);
            t23 = fma2(s7, p2[3], t23);
            t23 = fma2(s8, p2[4], t23);

            acc01[co] = add2(acc01[co], t01);
            acc23[co] = add2(acc23[co], t23);
        }
    }

    // unpack accumulators
    float av[COC][4];
#pragma unroll
    for (int co = 0; co < COC; co++) {
        upk2(acc01[co], av[co][0], av[co][1]);
        upk2(acc23[co], av[co][2], av[co][3]);
    }

    // store bconv (float4, perfectly coalesced)
    const size_t outbase = (((size_t)b * NG + g) * NCOUT + co0) * HW + (size_t)h * NWW + w0;
#pragma unroll
    for (int co = 0; co < COC; co++) {
        float4 v = make_float4(av[co][0], av[co][1], av[co][2], av[co][3]);
        *reinterpret_cast<float4*>(&g_bconv[outbase + (size_t)co * HW]) = v;
    }

    // fused BN stats: block partials then fp64 atomics
    const int lane = t & 31;
    const int wid  = t >> 5;
#pragma unroll
    for (int co = 0; co < COC; co++) {
        float s1 = av[co][0] + av[co][1] + av[co][2] + av[co][3];
        float s2 = av[co][0] * av[co][0] + av[co][1] * av[co][1]
                 + av[co][2] * av[co][2] + av[co][3] * av[co][3];
#pragma unroll
        for (int o = 16; o > 0; o >>= 1) {
            s1 += __shfl_xor_sync(0xFFFFFFFFu, s1, o);
            s2 += __shfl_xor_sync(0xFFFFFFFFu, s2, o);
        }
        if (lane == 0) { red1[co][wid] = s1; red2[co][wid] = s2; }
    }
    __syncthreads();
    if (t < COC) {
        float s1 = 0.0f, s2 = 0.0f;
#pragma unroll
        for (int wdx = 0; wdx < 8; wdx++) { s1 += red1[t][wdx]; s2 += red2[t][wdx]; }
        const int ch = g * NCOUT + co0 + t;
        atomicAdd(&g_sum[ch],   (double)s1);
        atomicAdd(&g_sumsq[ch], (double)s2);
    }
}

// ---------------------------------------------------------------------------
// Kernel 2: finalize per-channel BN affine in fp64.
// ---------------------------------------------------------------------------
__global__ void finalize_kernel(const float* __restrict__ gamma,
                                const float* __restrict__ beta) {
    const int ch = blockIdx.x * 256 + threadIdx.x;   // 0..1023
    if (ch >= NCH) return;
    const int co = ch & (NCOUT - 1);
    const double N = (double)NB * (double)HW;        // 32768
    const double mean_b = g_sum[ch] / N;
    const double var_b  = g_sumsq[ch] / N - mean_b * mean_b;
    const double a      = (double)g_alpha[co];
    const double var_p  = a * a * var_b;
    const double inv    = rsqrt(var_p + 1e-5) * (double)gamma[ch];
    g_cA[ch] = (float)(a * inv);
    g_cB[ch] = (float)((double)beta[ch] - a * mean_b * inv);
}

// ---------------------------------------------------------------------------
// Kernel 3: sign + group merge + qrelu quantization.
// y in {-4,-2,0,2,4} -> q in {0, 32/15, 4} (round-half-even on 7.5 -> 8)
// ---------------------------------------------------------------------------
__global__ void merge_kernel(float* __restrict__ out) {
    const size_t i   = (size_t)blockIdx.x * 256 + threadIdx.x;  // float4 index
    const size_t px4 = i & 255;           // HW/4 = 256 float4 per plane
    const size_t bc  = i >> 8;
    const size_t co  = bc & (NCOUT - 1);
    const size_t b   = bc >> 8;

    int y0 = 0, y1 = 0, y2 = 0, y3 = 0;
#pragma unroll
    for (int g = 0; g < NG; g++) {
        const size_t idx = (((b * NG + g) * NCOUT + co) * (HW / 4)) + px4;
        const float4 v = reinterpret_cast<const float4*>(g_bconv)[idx];
        const int ch = g * NCOUT + (int)co;
        const float cA = g_cA[ch];
        const float cB = g_cB[ch];
        y0 += (fmaf(v.x, cA, cB) >= 0.0f) ? 1 : -1;
        y1 += (fmaf(v.y, cA, cB) >= 0.0f) ? 1 : -1;
        y2 += (fmaf(v.z, cA, cB) >= 0.0f) ? 1 : -1;
        y3 += (fmaf(v.w, cA, cB) >= 0.0f) ? 1 : -1;
    }

    const float QMID = (8.0f / 15.0f) * 4.0f;   // 2.1333334
    float4 o;
    o.x = (y0 >= 4) ? 4.0f : ((y0 >= 2) ? QMID : 0.0f);
    o.y = (y1 >= 4) ? 4.0f : ((y1 >= 2) ? QMID : 0.0f);
    o.z = (y2 >= 4) ? 4.0f : ((y2 >= 2) ? QMID : 0.0f);
    o.w = (y3 >= 4) ? 4.0f : ((y3 >= 2) ? QMID : 0.0f);
    reinterpret_cast<float4*>(out)[i] = o;
}

// ---------------------------------------------------------------------------
extern "C" void kernel_launch(void* const* d_in, const int* in_sizes, int n_in,
                              void* d_out, int out_size) {
    (void)in_sizes; (void)n_in; (void)out_size;
    const float* x     = (const float*)d_in[0];
    const float* w     = (const float*)d_in[1];
    const float* gamma = (const float*)d_in[2];
    const float* beta  = (const float*)d_in[3];
    float* out = (float*)d_out;

    prep_kernel<<<256, 256>>>(w);
    dim3 gconv(NCOUT / COC, NG, NB);   // (32, 4, 32)
    conv_kernel<<<gconv, 256>>>(x);
    finalize_kernel<<<4, 256>>>(gamma, beta);
    merge_kernel<<<(NB * NCOUT * HW / 4) / 256, 256>>>(out);   // 8192 blocks
}

// round 4
// speedup vs baseline: 1.8489x; 1.8489x over previous
#include <cuda_runtime.h>

// Problem constants
#define NB    32      // batch
#define NHH   32      // H
#define NWW   32      // W
#define NCIN  256     // input channels
#define NCOUT 256     // output channels per group
#define NG    4       // groups
#define CING  64      // input channels per group
#define NCH   1024    // NG * NCOUT (BN channels)
#define HW    1024    // H*W
#define COC   8       // couts per conv block
#define PST   34      // padded plane row stride
#define CCH   8       // channel chunk for two-level accumulation

// Device scratch (no allocations allowed)
__device__ float  g_alpha[NCOUT];
__device__ float  g_U[(size_t)NCOUT * NCIN * 16];    // Winograd weights G s G^T (exact dyadic), 4 MB
__device__ float  g_bconv[(size_t)NB * NCH * HW];    // 134 MB
__device__ double g_sum[NCH];
__device__ double g_sumsq[NCH];
__device__ float  g_cA[NCH];
__device__ float  g_cB[NCH];

// ---------------------------------------------------------------------------
// Kernel 0: per-cout alpha = mean|w|, Winograd weight transform, stats zeroing
// ---------------------------------------------------------------------------
__global__ void prep_kernel(const float* __restrict__ w) {
    const int co = blockIdx.x;
    const int t  = threadIdx.x;

    if (t < 4) {
        g_sum[co * 4 + t]   = 0.0;
        g_sumsq[co * 4 + t] = 0.0;
    }

    const float* wc = w + (size_t)co * NCIN * 9;

    float s = 0.0f;
    for (int i = t; i < NCIN * 9; i += 256) s += fabsf(wc[i]);
    __shared__ float red[256];
    red[t] = s;
    __syncthreads();
    for (int o = 128; o > 0; o >>= 1) {
        if (t < o) red[t] += red[t + o];
        __syncthreads();
    }
    if (t == 0) g_alpha[co] = red[0] / 2304.0f;

    // Winograd weight transform (exact: signs are +-1, G entries {1, 1/2})
    {
        const int ci = t;
        const float* wp = wc + (size_t)ci * 9;
        float sg[3][3];
#pragma unroll
        for (int i = 0; i < 3; i++)
#pragma unroll
            for (int j = 0; j < 3; j++)
                sg[i][j] = (wp[i * 3 + j] >= 0.0f) ? 1.0f : -1.0f;

        float T[4][3];
#pragma unroll
        for (int j = 0; j < 3; j++) {
            T[0][j] = sg[0][j];
            T[1][j] = 0.5f * (sg[0][j] + sg[1][j] + sg[2][j]);
            T[2][j] = 0.5f * (sg[0][j] - sg[1][j] + sg[2][j]);
            T[3][j] = sg[2][j];
        }
        float U[4][4];
#pragma unroll
        for (int i = 0; i < 4; i++) {
            U[i][0] = T[i][0];
            U[i][1] = 0.5f * (T[i][0] + T[i][1] + T[i][2]);
            U[i][2] = 0.5f * (T[i][0] - T[i][1] + T[i][2]);
            U[i][3] = T[i][2];
        }
        float4* dst = reinterpret_cast<float4*>(&g_U[((size_t)co * NCIN + ci) * 16]);
#pragma unroll
        for (int i = 0; i < 4; i++)
            dst[i] = make_float4(U[i][0], U[i][1], U[i][2], U[i][3]);
    }
}

// ---------------------------------------------------------------------------
// Kernel 1: Winograd F(2x2,3x3) with chunked accumulation (chunk=8 channels).
// Per chunk: accumulate Mc in transform domain, inverse-transform, accumulate
// into yA. Double-buffered input plane, one __syncthreads per channel.
// grid: (32, 4, 32), 256 threads = 16x16 grid of 2x2 output tiles.
// ---------------------------------------------------------------------------
__global__ void __launch_bounds__(256, 1) conv_kernel(const float* __restrict__ x) {
    const int t   = threadIdx.x;
    const int co0 = blockIdx.x * COC;   // 0..255 step 8
    const int g   = blockIdx.y;         // 0..3
    const int b   = blockIdx.z;         // 0..31

    __shared__ float sp[2][PST * PST];       // double-buffered padded plane (9.2 KB)
    __shared__ float ss[COC * CING * 16];    // Winograd U tiles (32 KB)
    __shared__ float red1[COC][8];
    __shared__ float red2[COC][8];

    // zero both padded planes (borders stay zero)
    for (int i = t; i < 2 * PST * PST; i += 256)
        (&sp[0][0])[i] = 0.0f;

    // load U tiles for this (co chunk, group): [coi][c][16]
    {
        const float4* src0 = reinterpret_cast<const float4*>(
            &g_U[((size_t)co0 * NCIN + (size_t)g * CING) * 16]);
        float4* dst = reinterpret_cast<float4*>(ss);
        for (int i = t; i < COC * CING * 4; i += 256) {
            int coi = i / (CING * 4);
            int rem = i - coi * (CING * 4);
            dst[coi * (CING * 4) + rem] = src0[(size_t)coi * (NCIN * 4) + rem];
        }
    }

    float yA[COC][4];
#pragma unroll
    for (int a = 0; a < COC; a++)
#pragma unroll
        for (int p = 0; p < 4; p++) yA[a][p] = 0.0f;

    const int th = t >> 4;          // tile row 0..15
    const int tw = t & 15;          // tile col 0..15
    const float* xb = x + ((size_t)b * NCIN + (size_t)g * CING) * HW;

    // preload channel 0 into buffer 0
    {
        float pre[4];
#pragma unroll
        for (int k = 0; k < 4; k++) pre[k] = xb[t + 256 * k];
#pragma unroll
        for (int k = 0; k < 4; k++) {
            int idx = t + 256 * k;
            sp[0][(1 + (idx >> 5)) * PST + 1 + (idx & 31)] = pre[k];
        }
    }

    for (int c8 = 0; c8 < CING / CCH; c8++) {
        float Mc[COC][16];
#pragma unroll
        for (int a = 0; a < COC; a++)
#pragma unroll
            for (int k = 0; k < 16; k++) Mc[a][k] = 0.0f;

        for (int ci = 0; ci < CCH; ci++) {
            const int c   = c8 * CCH + ci;
            const int cur = c & 1;

            __syncthreads();   // cur-buffer writes visible; prev reads of other buffer done

            // prefetch next channel (latency hidden under compute)
            float pre[4];
            if (c < CING - 1) {
#pragma unroll
                for (int k = 0; k < 4; k++)
                    pre[k] = xb[(size_t)(c + 1) * HW + t + 256 * k];
            }

            const float* spc = sp[cur];

            // load 4x4 patch, forward transform V = B^T d B
            float d[4][4];
#pragma unroll
            for (int i = 0; i < 4; i++)
#pragma unroll
                for (int j = 0; j < 4; j++)
                    d[i][j] = spc[(2 * th + i) * PST + 2 * tw + j];

            float W[4][4];
#pragma unroll
            for (int j = 0; j < 4; j++) {
                W[0][j] = d[0][j] - d[2][j];
                W[1][j] = d[1][j] + d[2][j];
                W[2][j] = d[2][j] - d[1][j];
                W[3][j] = d[1][j] - d[3][j];
            }
            float V[4][4];
#pragma unroll
            for (int i = 0; i < 4; i++) {
                V[i][0] = W[i][0] - W[i][2];
                V[i][1] = W[i][1] + W[i][2];
                V[i][2] = W[i][2] - W[i][1];
                V[i][3] = W[i][1] - W[i][3];
            }

            // Mc[co] += U[co][c] .* V (warp-uniform LDS.128 broadcasts)
            const float4* ub = reinterpret_cast<const float4*>(ss + c * 16);
#pragma unroll
            for (int co = 0; co < COC; co++) {
                const float4* U4 = ub + co * (CING * 4);
                const float4 u0 = U4[0], u1 = U4[1], u2 = U4[2], u3 = U4[3];
                Mc[co][ 0] = fmaf(u0.x, V[0][0], Mc[co][ 0]);
                Mc[co][ 1] = fmaf(u0.y, V[0][1], Mc[co][ 1]);
                Mc[co][ 2] = fmaf(u0.z, V[0][2], Mc[co][ 2]);
                Mc[co][ 3] = fmaf(u0.w, V[0][3], Mc[co][ 3]);
                Mc[co][ 4] = fmaf(u1.x, V[1][0], Mc[co][ 4]);
                Mc[co][ 5] = fmaf(u1.y, V[1][1], Mc[co][ 5]);
                Mc[co][ 6] = fmaf(u1.z, V[1][2], Mc[co][ 6]);
                Mc[co][ 7] = fmaf(u1.w, V[1][3], Mc[co][ 7]);
                Mc[co][ 8] = fmaf(u2.x, V[2][0], Mc[co][ 8]);
                Mc[co][ 9] = fmaf(u2.y, V[2][1], Mc[co][ 9]);
                Mc[co][10] = fmaf(u2.z, V[2][2], Mc[co][10]);
                Mc[co][11] = fmaf(u2.w, V[2][3], Mc[co][11]);
                Mc[co][12] = fmaf(u3.x, V[3][0], Mc[co][12]);
                Mc[co][13] = fmaf(u3.y, V[3][1], Mc[co][13]);
                Mc[co][14] = fmaf(u3.z, V[3][2], Mc[co][14]);
                Mc[co][15] = fmaf(u3.w, V[3][3], Mc[co][15]);
            }

            // write prefetched plane into the other buffer
            if (c < CING - 1) {
#pragma unroll
                for (int k = 0; k < 4; k++) {
                    int idx = t + 256 * k;
                    sp[cur ^ 1][(1 + (idx >> 5)) * PST + 1 + (idx & 31)] = pre[k];
                }
            }
        }

        // chunk inverse transform Y = A^T Mc A, accumulate into yA
#pragma unroll
        for (int co = 0; co < COC; co++) {
            float Z0[4], Z1[4];
#pragma unroll
            for (int j = 0; j < 4; j++) {
                Z0[j] = Mc[co][0 * 4 + j] + Mc[co][1 * 4 + j] + Mc[co][2 * 4 + j];
                Z1[j] = Mc[co][1 * 4 + j] - Mc[co][2 * 4 + j] - Mc[co][3 * 4 + j];
            }
            yA[co][0] += Z0[0] + Z0[1] + Z0[2];
            yA[co][1] += Z0[1] - Z0[2] - Z0[3];
            yA[co][2] += Z1[0] + Z1[1] + Z1[2];
            yA[co][3] += Z1[1] - Z1[2] - Z1[3];
        }
    }

    // store bconv + stats
    const size_t outbase = (((size_t)b * NG + g) * NCOUT + co0) * HW
                         + (size_t)(2 * th) * NWW + 2 * tw;
    const int lane = t & 31;
    const int wid  = t >> 5;

#pragma unroll
    for (int co = 0; co < COC; co++) {
        const float y00 = yA[co][0], y01 = yA[co][1];
        const float y10 = yA[co][2], y11 = yA[co][3];

        float* op = &g_bconv[outbase + (size_t)co * HW];
        *reinterpret_cast<float2*>(op)       = make_float2(y00, y01);
        *reinterpret_cast<float2*>(op + NWW) = make_float2(y10, y11);

        float s1 = y00 + y01 + y10 + y11;
        float s2 = y00 * y00 + y01 * y01 + y10 * y10 + y11 * y11;
#pragma unroll
        for (int o = 16; o > 0; o >>= 1) {
            s1 += __shfl_xor_sync(0xFFFFFFFFu, s1, o);
            s2 += __shfl_xor_sync(0xFFFFFFFFu, s2, o);
        }
        if (lane == 0) { red1[co][wid] = s1; red2[co][wid] = s2; }
    }
    __syncthreads();
    if (t < COC) {
        float s1 = 0.0f, s2 = 0.0f;
#pragma unroll
        for (int wdx = 0; wdx < 8; wdx++) { s1 += red1[t][wdx]; s2 += red2[t][wdx]; }
        const int ch = g * NCOUT + co0 + t;
        atomicAdd(&g_sum[ch],   (double)s1);
        atomicAdd(&g_sumsq[ch], (double)s2);
    }
}

// ---------------------------------------------------------------------------
// Kernel 2: finalize per-channel BN affine in fp64.
// ---------------------------------------------------------------------------
__global__ void finalize_kernel(const float* __restrict__ gamma,
                                const float* __restrict__ beta) {
    const int ch = blockIdx.x * 256 + threadIdx.x;   // 0..1023
    if (ch >= NCH) return;
    const int co = ch & (NCOUT - 1);
    const double N = (double)NB * (double)HW;        // 32768
    const double mean_b = g_sum[ch] / N;
    const double var_b  = g_sumsq[ch] / N - mean_b * mean_b;
    const double a      = (double)g_alpha[co];
    const double var_p  = a * a * var_b;
    const double inv    = rsqrt(var_p + 1e-5) * (double)gamma[ch];
    g_cA[ch] = (float)(a * inv);
    g_cB[ch] = (float)((double)beta[ch] - a * mean_b * inv);
}

// ---------------------------------------------------------------------------
// Kernel 3: sign + group merge + qrelu quantization.
// ---------------------------------------------------------------------------
__global__ void merge_kernel(float* __restrict__ out) {
    const size_t i   = (size_t)blockIdx.x * 256 + threadIdx.x;  // float4 index
    const size_t px4 = i & 255;
    const size_t bc  = i >> 8;
    const size_t co  = bc & (NCOUT - 1);
    const size_t b   = bc >> 8;

    int y0 = 0, y1 = 0, y2 = 0, y3 = 0;
#pragma unroll
    for (int g = 0; g < NG; g++) {
        const size_t idx = (((b * NG + g) * NCOUT + co) * (HW / 4)) + px4;
        const float4 v = reinterpret_cast<const float4*>(g_bconv)[idx];
        const int ch = g * NCOUT + (int)co;
        const float cA = g_cA[ch];
        const float cB = g_cB[ch];
        y0 += (fmaf(v.x, cA, cB) >= 0.0f) ? 1 : -1;
        y1 += (fmaf(v.y, cA, cB) >= 0.0f) ? 1 : -1;
        y2 += (fmaf(v.z, cA, cB) >= 0.0f) ? 1 : -1;
        y3 += (fmaf(v.w, cA, cB) >= 0.0f) ? 1 : -1;
    }

    const float QMID = (8.0f / 15.0f) * 4.0f;   // 2.1333334
    float4 o;
    o.x = (y0 >= 4) ? 4.0f : ((y0 >= 2) ? QMID : 0.0f);
    o.y = (y1 >= 4) ? 4.0f : ((y1 >= 2) ? QMID : 0.0f);
    o.z = (y2 >= 4) ? 4.0f : ((y2 >= 2) ? QMID : 0.0f);
    o.w = (y3 >= 4) ? 4.0f : ((y3 >= 2) ? QMID : 0.0f);
    reinterpret_cast<float4*>(out)[i] = o;
}

// ---------------------------------------------------------------------------
extern "C" void kernel_launch(void* const* d_in, const int* in_sizes, int n_in,
                              void* d_out, int out_size) {
    (void)in_sizes; (void)n_in; (void)out_size;
    const float* x     = (const float*)d_in[0];
    const float* w     = (const float*)d_in[1];
    const float* gamma = (const float*)d_in[2];
    const float* beta  = (const float*)d_in[3];
    float* out = (float*)d_out;

    prep_kernel<<<256, 256>>>(w);
    dim3 gconv(NCOUT / COC, NG, NB);   // (32, 4, 32)
    conv_kernel<<<gconv, 256>>>(x);
    finalize_kernel<<<4, 256>>>(gamma, beta);
    merge_kernel<<<(NB * NCOUT * HW / 4) / 256, 256>>>(out);   // 8192 blocks
}

// round 7
// speedup vs baseline: 2.0880x; 1.1293x over previous
#include <cuda_runtime.h>
#include <cuda_fp16.h>
#include <cstdint>

// Problem constants
#define NB    32
#define NG    4
#define NCOUT 256     // output channels per group
#define CING  64      // input channels per group
#define NCH   1024
#define HW    1024
#define NIMG  128     // NB*NG
#define HPAD  34      // padded rows (hp = 0..33 <-> xh = hp-1)
#define XROW  2048    // 32 w * 64 ch halves per padded row
#define IMGSZ (HPAD * XROW)   // 69632 halves per image per copy
#define SROW  72      // smem row stride in halves (64 + 8 pad)

// Device scratch (no allocations allowed)
__device__ float  g_alpha[NCOUT];
__device__ __align__(16) __half g_A[NG * 9 * NCOUT * CING];        // [g][tap][co][ch], +-1
__device__ __align__(16) __half g_xs[(size_t)6 * NIMG * IMGSZ];    // [split*3+dj][img][hp][w][ch]
__device__ float  g_bconv[(size_t)NB * NCH * HW];                  // 134 MB
__device__ double g_sum[NCH];
__device__ double g_sumsq[NCH];
__device__ float  g_cA[NCH];
__device__ float  g_cB[NCH];

__device__ __forceinline__ uint32_t smem_u32(const void* p) {
    uint32_t a;
    asm("{ .reg .u64 t; cvta.to.shared.u64 t, %1; cvt.u32.u64 %0, t; }" : "=r"(a) : "l"(p));
    return a;
}
__device__ __forceinline__ void ldsm_x4(uint32_t& r0, uint32_t& r1, uint32_t& r2, uint32_t& r3,
                                        uint32_t addr) {
    asm volatile("ldmatrix.sync.aligned.m8n8.x4.shared.b16 {%0,%1,%2,%3}, [%4];"
                 : "=r"(r0), "=r"(r1), "=r"(r2), "=r"(r3) : "r"(addr));
}
// accumulate: D = A*B + D
__device__ __forceinline__ void mma16816(float& c0, float& c1, float& c2, float& c3,
                                         uint32_t a0, uint32_t a1, uint32_t a2, uint32_t a3,
                                         uint32_t b0, uint32_t b1) {
    asm volatile(
        "mma.sync.aligned.m16n8k16.row.col.f32.f16.f16.f32 "
        "{%0,%1,%2,%3}, {%4,%5,%6,%7}, {%8,%9}, {%0,%1,%2,%3};"
        : "+f"(c0), "+f"(c1), "+f"(c2), "+f"(c3)
        : "r"(a0), "r"(a1), "r"(a2), "r"(a3), "r"(b0), "r"(b1));
}
// overwrite: D = A*B + 0  (fresh per-tap sub-accumulator, no explicit zeroing)
__device__ __forceinline__ void mma16816_z(float& c0, float& c1, float& c2, float& c3,
                                           uint32_t a0, uint32_t a1, uint32_t a2, uint32_t a3,
                                           uint32_t b0, uint32_t b1) {
    asm volatile(
        "mma.sync.aligned.m16n8k16.row.col.f32.f16.f16.f32 "
        "{%0,%1,%2,%3}, {%4,%5,%6,%7}, {%8,%9}, {%10,%10,%10,%10};"
        : "=f"(c0), "=f"(c1), "=f"(c2), "=f"(c3)
        : "r"(a0), "r"(a1), "r"(a2), "r"(a3), "r"(b0), "r"(b1), "f"(0.0f));
}

// ---------------------------------------------------------------------------
// Kernel 0: alpha = mean|w| per cout; sign tiles A[g][tap][co][ch] in fp16.
// ---------------------------------------------------------------------------
__global__ void prep_w_kernel(const float* __restrict__ w) {
    const int co = blockIdx.x;
    const int t  = threadIdx.x;
    const float* wc = w + (size_t)co * 256 * 9;

    float s = 0.0f;
    for (int i = t; i < 256 * 9; i += 256) s += fabsf(wc[i]);
    __shared__ float red[256];
    red[t] = s;
    __syncthreads();
    for (int o = 128; o > 0; o >>= 1) {
        if (t < o) red[t] += red[t + o];
        __syncthreads();
    }
    if (t == 0) g_alpha[co] = red[0] / 2304.0f;

    for (int i = t; i < 256 * 9; i += 256) {
        int ci = i / 9, tap = i - ci * 9;
        int g = ci >> 6, ch = ci & 63;
        __half v = (wc[i] >= 0.0f) ? __float2half_rn(1.0f) : __float2half_rn(-1.0f);
        g_A[((size_t)(g * 9 + tap) * NCOUT + co) * CING + ch] = v;
    }
}

// ---------------------------------------------------------------------------
// Kernel 1: build shifted/split x copies (fp16 hi/lo two-term split).
// copy c = split*3+dj at [img][hp][w][ch] = split(x[b, g*64+ch, hp-1, w+dj-1])
// grid (34, 128), 256 threads.
// ---------------------------------------------------------------------------
__global__ void prep_x_kernel(const float* __restrict__ x) {
    const int hp  = blockIdx.x;
    const int img = blockIdx.y;
    const int g   = img & 3;
    const int b   = img >> 2;
    const int t   = threadIdx.x;
    const int xh  = hp - 1;

    __shared__ float sx[CING * 32];   // [ch][w]
    if (xh >= 0 && xh < 32) {
        const float4* src = reinterpret_cast<const float4*>(x) +
                            ((size_t)(b * 256 + g * 64) * 1024 + (size_t)xh * 32) / 4;
        for (int i = t; i < 512; i += 256) {
            int ch = i >> 3, j = i & 7;
            reinterpret_cast<float4*>(sx)[ch * 8 + j] = src[(size_t)ch * 256 + j];
        }
    } else {
        for (int i = t; i < CING * 32 / 4; i += 256)
            reinterpret_cast<float4*>(sx)[i] = make_float4(0.f, 0.f, 0.f, 0.f);
    }
    __syncthreads();

    for (int i = t; i < 6 * 1024; i += 256) {
        int c  = i >> 10;
        int r  = i & 1023;
        int wq = r >> 5;
        int c2 = (r & 31) * 2;
        int split = c / 3, dj = c - split * 3;
        int xw = wq + dj - 1;
        float v0 = 0.f, v1 = 0.f;
        if (xh >= 0 && xh < 32 && xw >= 0 && xw < 32) {
            v0 = sx[c2 * 32 + xw];
            v1 = sx[(c2 + 1) * 32 + xw];
        }
        __half h0, h1;
        if (split == 0) {
            h0 = __float2half_rn(v0);
            h1 = __float2half_rn(v1);
        } else {
            h0 = __float2half_rn(v0 - __half2float(__float2half_rn(v0)));
            h1 = __float2half_rn(v1 - __half2float(__float2half_rn(v1)));
        }
        size_t off = ((size_t)c * NIMG + img) * IMGSZ + (size_t)hp * XROW + wq * 64 + c2;
        *reinterpret_cast<__half2*>(&g_xs[off]) = __halves2half2(h0, h1);
    }
}

// ---------------------------------------------------------------------------
// Kernel 2: HMMA implicit GEMM with per-tap sub-accumulator flush.
// CTA = (cohalf | ptile) x g x b. M=128 co, N=128 px (4 image rows),
// K = 9 taps x 2 splits x 64 ch. 8 warps (4M x 2N), warp tile 32x64.
// acc: one tap (chain 8, 1/3 magnitude). acc2: 9-deep full-magnitude chain.
// ---------------------------------------------------------------------------
__global__ void __launch_bounds__(256) conv_mma_kernel() {
    __shared__ __half sA[128 * SROW];   // 18.4 KB
    __shared__ __half sB[128 * SROW];   // 18.4 KB

    const int t      = threadIdx.x;
    const int wid    = t >> 5;
    const int lane   = t & 31;
    const int cohalf = blockIdx.x & 1;
    const int ptile  = blockIdx.x >> 1;    // 0..7 (4 image rows each)
    const int g      = blockIdx.y;
    const int b      = blockIdx.z;
    const int img    = b * 4 + g;
    const int px0    = ptile * 128;

    const int wm = (wid >> 1) * 32;        // warp M offset (co)
    const int wn = (wid & 1) * 64;         // warp N offset (px)

    const uint32_t sAu = smem_u32(sA);
    const uint32_t sBu = smem_u32(sB);

    const int aRow = lane & 15;
    const int aCol = (lane >> 4) * 8;
    const int bRow = (lane & 7) + ((lane >> 4) & 1) * 8;
    const int bCol = ((lane >> 3) & 1) * 8;

    float acc[16][4];    // per-tap sub-accumulator (overwritten by mma16816_z)
    float acc2[16][4];   // cross-tap accumulator
#pragma unroll
    for (int i = 0; i < 16; i++)
#pragma unroll
        for (int j = 0; j < 4; j++) acc2[i][j] = 0.0f;

    for (int tap = 0; tap < 9; tap++) {
        const int di = tap / 3, dj = tap - di * 3;

        __syncthreads();   // previous tap's reads done
        // stage A [128 co][64 ch] -> sA (row stride 72 halves)
        {
            const float4* srcA = reinterpret_cast<const float4*>(
                g_A + ((size_t)(g * 9 + tap) * NCOUT + cohalf * 128) * CING);
            for (int i = t; i < 1024; i += 256) {
                int row = i >> 3, j = i & 7;
                *reinterpret_cast<float4*>(sA + row * SROW + j * 8) = srcA[i];
            }
        }

#pragma unroll
        for (int split = 0; split < 2; split++) {
            if (split == 1) __syncthreads();   // hi-split reads done before restage
            // stage B [128 px][64 ch] -> sB
            {
                const float4* srcB = reinterpret_cast<const float4*>(
                    g_xs + ((size_t)(split * 3 + dj) * NIMG + img) * IMGSZ
                         + (size_t)(ptile * 4 + di) * XROW);
                for (int i = t; i < 1024; i += 256) {
                    int row = i >> 3, j = i & 7;
                    *reinterpret_cast<float4*>(sB + row * SROW + j * 8) = srcB[i];
                }
            }
            __syncthreads();

#pragma unroll
            for (int k = 0; k < 4; k++) {
                uint32_t a0[4], a1[4];
                ldsm_x4(a0[0], a0[1], a0[2], a0[3],
                        sAu + ((wm + 0  + aRow) * SROW + k * 16 + aCol) * 2);
                ldsm_x4(a1[0], a1[1], a1[2], a1[3],
                        sAu + ((wm + 16 + aRow) * SROW + k * 16 + aCol) * 2);
#pragma unroll
                for (int nb = 0; nb < 4; nb++) {
                    uint32_t r0, r1, r2, r3;
                    ldsm_x4(r0, r1, r2, r3,
                            sBu + ((wn + nb * 16 + bRow) * SROW + k * 16 + bCol) * 2);
                    if (split == 0 && k == 0) {
                        mma16816_z(acc[nb * 2][0], acc[nb * 2][1],
                                   acc[nb * 2][2], acc[nb * 2][3],
                                   a0[0], a0[1], a0[2], a0[3], r0, r1);
                        mma16816_z(acc[nb * 2 + 1][0], acc[nb * 2 + 1][1],
                                   acc[nb * 2 + 1][2], acc[nb * 2 + 1][3],
                                   a0[0], a0[1], a0[2], a0[3], r2, r3);
                        mma16816_z(acc[8 + nb * 2][0], acc[8 + nb * 2][1],
                                   acc[8 + nb * 2][2], acc[8 + nb * 2][3],
                                   a1[0], a1[1], a1[2], a1[3], r0, r1);
                        mma16816_z(acc[8 + nb * 2 + 1][0], acc[8 + nb * 2 + 1][1],
                                   acc[8 + nb * 2 + 1][2], acc[8 + nb * 2 + 1][3],
                                   a1[0], a1[1], a1[2], a1[3], r2, r3);
                    } else {
                        mma16816(acc[nb * 2][0], acc[nb * 2][1],
                                 acc[nb * 2][2], acc[nb * 2][3],
                                 a0[0], a0[1], a0[2], a0[3], r0, r1);
                        mma16816(acc[nb * 2 + 1][0], acc[nb * 2 + 1][1],
                                 acc[nb * 2 + 1][2], acc[nb * 2 + 1][3],
                                 a0[0], a0[1], a0[2], a0[3], r2, r3);
                        mma16816(acc[8 + nb * 2][0], acc[8 + nb * 2][1],
                                 acc[8 + nb * 2][2], acc[8 + nb * 2][3],
                                 a1[0], a1[1], a1[2], a1[3], r0, r1);
                        mma16816(acc[8 + nb * 2 + 1][0], acc[8 + nb * 2 + 1][1],
                                 acc[8 + nb * 2 + 1][2], acc[8 + nb * 2 + 1][3],
                                 a1[0], a1[1], a1[2], a1[3], r2, r3);
                    }
                }
            }
        }
        __syncthreads();   // lo-split reads done before next tap restages A/B

        // flush tap sub-accumulator into cross-tap bank (chain 9 at full mag)
#pragma unroll
        for (int i = 0; i < 16; i++)
#pragma unroll
            for (int j = 0; j < 4; j++) acc2[i][j] += acc[i][j];
    }

    // Epilogue: direct float2 stores (full 32B sectors)
    const int coBase = cohalf * 128 + wm;
#pragma unroll
    for (int mi = 0; mi < 2; mi++) {
#pragma unroll
        for (int ni = 0; ni < 8; ni++) {
            const int co_r = coBase + mi * 16 + (lane >> 2);
            const int px_c = px0 + wn + ni * 8 + (lane & 3) * 2;
            float* p0 = &g_bconv[((size_t)img * NCOUT + co_r) * HW + px_c];
            *reinterpret_cast<float2*>(p0) =
                make_float2(acc2[mi * 8 + ni][0], acc2[mi * 8 + ni][1]);
            *reinterpret_cast<float2*>(p0 + 8 * HW) =
                make_float2(acc2[mi * 8 + ni][2], acc2[mi * 8 + ni][3]);
        }
    }
}

// ---------------------------------------------------------------------------
// Kernel 3: BN stats per channel (atomic-free; one block per BN channel).
// ---------------------------------------------------------------------------
__global__ void stats_kernel() {
    const int ch = blockIdx.x;       // 0..1023 = g*256+co
    const int t  = threadIdx.x;
    double s1 = 0.0, s2 = 0.0;
    for (int b = 0; b < NB; b++) {
        const float4 v = reinterpret_cast<const float4*>(g_bconv)
                         [((size_t)(b * 1024 + ch)) * 256 + t];
        s1 += (double)v.x; s2 += (double)v.x * v.x;
        s1 += (double)v.y; s2 += (double)v.y * v.y;
        s1 += (double)v.z; s2 += (double)v.z * v.z;
        s1 += (double)v.w; s2 += (double)v.w * v.w;
    }
    __shared__ double r1[256], r2[256];
    r1[t] = s1; r2[t] = s2;
    __syncthreads();
    for (int o = 128; o > 0; o >>= 1) {
        if (t < o) { r1[t] += r1[t + o]; r2[t] += r2[t + o]; }
        __syncthreads();
    }
    if (t == 0) { g_sum[ch] = r1[0]; g_sumsq[ch] = r2[0]; }
}

// ---------------------------------------------------------------------------
// Kernel 4: finalize per-channel BN affine in fp64.
// ---------------------------------------------------------------------------
__global__ void finalize_kernel(const float* __restrict__ gamma,
                                const float* __restrict__ beta) {
    const int ch = blockIdx.x * 256 + threadIdx.x;
    if (ch >= NCH) return;
    const int co = ch & (NCOUT - 1);
    const double N = (double)NB * (double)HW;
    const double mean_b = g_sum[ch] / N;
    const double var_b  = g_sumsq[ch] / N - mean_b * mean_b;
    const double a      = (double)g_alpha[co];
    const double inv    = rsqrt(a * a * var_b + 1e-5) * (double)gamma[ch];
    g_cA[ch] = (float)(a * inv);
    g_cB[ch] = (float)((double)beta[ch] - a * mean_b * inv);
}

// ---------------------------------------------------------------------------
// Kernel 5: sign + group merge + qrelu quantization.
// ---------------------------------------------------------------------------
__global__ void merge_kernel(float* __restrict__ out) {
    const size_t i   = (size_t)blockIdx.x * 256 + threadIdx.x;
    const size_t px4 = i & 255;
    const size_t bc  = i >> 8;
    const size_t co  = bc & (NCOUT - 1);
    const size_t b   = bc >> 8;

    int y0 = 0, y1 = 0, y2 = 0, y3 = 0;
#pragma unroll
    for (int g = 0; g < NG; g++) {
        const size_t idx = (((b * NG + g) * NCOUT + co) * (HW / 4)) + px4;
        const float4 v = reinterpret_cast<const float4*>(g_bconv)[idx];
        const int ch = g * NCOUT + (int)co;
        const float cA = g_cA[ch];
        const float cB = g_cB[ch];
        y0 += (fmaf(v.x, cA, cB) >= 0.0f) ? 1 : -1;
        y1 += (fmaf(v.y, cA, cB) >= 0.0f) ? 1 : -1;
        y2 += (fmaf(v.z, cA, cB) >= 0.0f) ? 1 : -1;
        y3 += (fmaf(v.w, cA, cB) >= 0.0f) ? 1 : -1;
    }
    const float QMID = (8.0f / 15.0f) * 4.0f;
    float4 o;
    o.x = (y0 >= 4) ? 4.0f : ((y0 >= 2) ? QMID : 0.0f);
    o.y = (y1 >= 4) ? 4.0f : ((y1 >= 2) ? QMID : 0.0f);
    o.z = (y2 >= 4) ? 4.0f : ((y2 >= 2) ? QMID : 0.0f);
    o.w = (y3 >= 4) ? 4.0f : ((y3 >= 2) ? QMID : 0.0f);
    reinterpret_cast<float4*>(out)[i] = o;
}

// ---------------------------------------------------------------------------
extern "C" void kernel_launch(void* const* d_in, const int* in_sizes, int n_in,
                              void* d_out, int out_size) {
    (void)in_sizes; (void)n_in; (void)out_size;
    const float* x     = (const float*)d_in[0];
    const float* w     = (const float*)d_in[1];
    const float* gamma = (const float*)d_in[2];
    const float* beta  = (const float*)d_in[3];
    float* out = (float*)d_out;

    prep_w_kernel<<<256, 256>>>(w);
    prep_x_kernel<<<dim3(HPAD, NIMG), 256>>>(x);
    conv_mma_kernel<<<dim3(16, NG, NB), 256>>>();
    stats_kernel<<<NCH, 256>>>();
    finalize_kernel<<<4, 256>>>(gamma, beta);
    merge_kernel<<<(NB * NCOUT * HW / 4) / 256, 256>>>(out);
}

// round 8
// speedup vs baseline: 2.1005x; 1.0060x over previous
#include <cuda_runtime.h>
#include <cuda_fp16.h>
#include <cstdint>

// Problem constants
#define NB    32
#define NG    4
#define NCOUT 256     // output channels per group
#define CING  64      // input channels per group
#define NCH   1024
#define HW    1024
#define NIMG  128     // NB*NG
#define HPAD  34      // padded rows (hp = 0..33 <-> xh = hp-1)
#define XROW  2048    // 32 w * 64 ch halves per padded row
#define IMGSZ (HPAD * XROW)   // 69632 halves per image per copy
#define SROW  72      // smem row stride in halves (64 + 8 pad)

// Device scratch (no allocations allowed)
__device__ float  g_alpha[NCOUT];
__device__ __align__(16) __half g_A[NG * 9 * NCOUT * CING];        // [g][tap][co][ch], +-1
__device__ __align__(16) __half g_xs[(size_t)6 * NIMG * IMGSZ];    // [split*3+dj][img][hp][w][ch]
__device__ float  g_bconv[(size_t)NB * NCH * HW];                  // 134 MB
__device__ double g_sum[NCH];
__device__ double g_sumsq[NCH];
__device__ float  g_cA[NCH];
__device__ float  g_cB[NCH];

__device__ __forceinline__ uint32_t smem_u32(const void* p) {
    uint32_t a;
    asm("{ .reg .u64 t; cvta.to.shared.u64 t, %1; cvt.u32.u64 %0, t; }" : "=r"(a) : "l"(p));
    return a;
}
__device__ __forceinline__ void ldsm_x4(uint32_t& r0, uint32_t& r1, uint32_t& r2, uint32_t& r3,
                                        uint32_t addr) {
    asm volatile("ldmatrix.sync.aligned.m8n8.x4.shared.b16 {%0,%1,%2,%3}, [%4];"
                 : "=r"(r0), "=r"(r1), "=r"(r2), "=r"(r3) : "r"(addr));
}
// accumulate: D = A*B + D
__device__ __forceinline__ void mma16816(float& c0, float& c1, float& c2, float& c3,
                                         uint32_t a0, uint32_t a1, uint32_t a2, uint32_t a3,
                                         uint32_t b0, uint32_t b1) {
    asm volatile(
        "mma.sync.aligned.m16n8k16.row.col.f32.f16.f16.f32 "
        "{%0,%1,%2,%3}, {%4,%5,%6,%7}, {%8,%9}, {%0,%1,%2,%3};"
        : "+f"(c0), "+f"(c1), "+f"(c2), "+f"(c3)
        : "r"(a0), "r"(a1), "r"(a2), "r"(a3), "r"(b0), "r"(b1));
}
// overwrite: D = A*B + 0  (fresh per-tap sub-accumulator, no explicit zeroing)
__device__ __forceinline__ void mma16816_z(float& c0, float& c1, float& c2, float& c3,
                                           uint32_t a0, uint32_t a1, uint32_t a2, uint32_t a3,
                                           uint32_t b0, uint32_t b1) {
    asm volatile(
        "mma.sync.aligned.m16n8k16.row.col.f32.f16.f16.f32 "
        "{%0,%1,%2,%3}, {%4,%5,%6,%7}, {%8,%9}, {%10,%10,%10,%10};"
        : "=f"(c0), "=f"(c1), "=f"(c2), "=f"(c3)
        : "r"(a0), "r"(a1), "r"(a2), "r"(a3), "r"(b0), "r"(b1), "f"(0.0f));
}

// ---------------------------------------------------------------------------
// Kernel 0: alpha = mean|w| per cout; sign tiles A[g][tap][co][ch] in fp16.
// ---------------------------------------------------------------------------
__global__ void prep_w_kernel(const float* __restrict__ w) {
    const int co = blockIdx.x;
    const int t  = threadIdx.x;
    const float* wc = w + (size_t)co * 256 * 9;

    float s = 0.0f;
    for (int i = t; i < 256 * 9; i += 256) s += fabsf(wc[i]);
    __shared__ float red[256];
    red[t] = s;
    __syncthreads();
    for (int o = 128; o > 0; o >>= 1) {
        if (t < o) red[t] += red[t + o];
        __syncthreads();
    }
    if (t == 0) g_alpha[co] = red[0] / 2304.0f;

    for (int i = t; i < 256 * 9; i += 256) {
        int ci = i / 9, tap = i - ci * 9;
        int g = ci >> 6, ch = ci & 63;
        __half v = (wc[i] >= 0.0f) ? __float2half_rn(1.0f) : __float2half_rn(-1.0f);
        g_A[((size_t)(g * 9 + tap) * NCOUT + co) * CING + ch] = v;
    }
}

// ---------------------------------------------------------------------------
// Kernel 1: build shifted/split x copies (fp16 hi/lo two-term split).
// copy c = split*3+dj at [img][hp][w][ch] = split(x[b, g*64+ch, hp-1, w+dj-1])
// grid (34, 128), 256 threads.
// ---------------------------------------------------------------------------
__global__ void prep_x_kernel(const float* __restrict__ x) {
    const int hp  = blockIdx.x;
    const int img = blockIdx.y;
    const int g   = img & 3;
    const int b   = img >> 2;
    const int t   = threadIdx.x;
    const int xh  = hp - 1;

    __shared__ float sx[CING * 32];   // [ch][w]
    if (xh >= 0 && xh < 32) {
        const float4* src = reinterpret_cast<const float4*>(x) +
                            ((size_t)(b * 256 + g * 64) * 1024 + (size_t)xh * 32) / 4;
        for (int i = t; i < 512; i += 256) {
            int ch = i >> 3, j = i & 7;
            reinterpret_cast<float4*>(sx)[ch * 8 + j] = src[(size_t)ch * 256 + j];
        }
    } else {
        for (int i = t; i < CING * 32 / 4; i += 256)
            reinterpret_cast<float4*>(sx)[i] = make_float4(0.f, 0.f, 0.f, 0.f);
    }
    __syncthreads();

    for (int i = t; i < 6 * 1024; i += 256) {
        int c  = i >> 10;
        int r  = i & 1023;
        int wq = r >> 5;
        int c2 = (r & 31) * 2;
        int split = c / 3, dj = c - split * 3;
        int xw = wq + dj - 1;
        float v0 = 0.f, v1 = 0.f;
        if (xh >= 0 && xh < 32 && xw >= 0 && xw < 32) {
            v0 = sx[c2 * 32 + xw];
            v1 = sx[(c2 + 1) * 32 + xw];
        }
        __half h0, h1;
        if (split == 0) {
            h0 = __float2half_rn(v0);
            h1 = __float2half_rn(v1);
        } else {
            h0 = __float2half_rn(v0 - __half2float(__float2half_rn(v0)));
            h1 = __float2half_rn(v1 - __half2float(__float2half_rn(v1)));
        }
        size_t off = ((size_t)c * NIMG + img) * IMGSZ + (size_t)hp * XROW + wq * 64 + c2;
        *reinterpret_cast<__half2*>(&g_xs[off]) = __halves2half2(h0, h1);
    }
}

// ---------------------------------------------------------------------------
// Kernel 2: HMMA implicit GEMM with per-tap sub-accumulator flush.
// CTA = (cohalf | ptile) x g x b. M=128 co, N=128 px (4 image rows),
// K = 9 taps x 2 splits x 64 ch. 8 warps (4M x 2N), warp tile 32x64.
// acc: one tap (chain 8, 1/3 magnitude). acc2: 9-deep full-magnitude chain.
// ---------------------------------------------------------------------------
__global__ void __launch_bounds__(256) conv_mma_kernel() {
    __shared__ __half sA[128 * SROW];   // 18.4 KB
    __shared__ __half sB[128 * SROW];   // 18.4 KB

    const int t      = threadIdx.x;
    const int wid    = t >> 5;
    const int lane   = t & 31;
    const int cohalf = blockIdx.x & 1;
    const int ptile  = blockIdx.x >> 1;    // 0..7 (4 image rows each)
    const int g      = blockIdx.y;
    const int b      = blockIdx.z;
    const int img    = b * 4 + g;
    const int px0    = ptile * 128;

    const int wm = (wid >> 1) * 32;        // warp M offset (co)
    const int wn = (wid & 1) * 64;         // warp N offset (px)

    const uint32_t sAu = smem_u32(sA);
    const uint32_t sBu = smem_u32(sB);

    const int aRow = lane & 15;
    const int aCol = (lane >> 4) * 8;
    const int bRow = (lane & 7) + ((lane >> 4) & 1) * 8;
    const int bCol = ((lane >> 3) & 1) * 8;

    float acc[16][4];    // per-tap sub-accumulator (overwritten by mma16816_z)
    float acc2[16][4];   // cross-tap accumulator
#pragma unroll
    for (int i = 0; i < 16; i++)
#pragma unroll
        for (int j = 0; j < 4; j++) acc2[i][j] = 0.0f;

    for (int tap = 0; tap < 9; tap++) {
        const int di = tap / 3, dj = tap - di * 3;

        __syncthreads();   // previous tap's reads done
        // stage A [128 co][64 ch] -> sA (row stride 72 halves)
        {
            const float4* srcA = reinterpret_cast<const float4*>(
                g_A + ((size_t)(g * 9 + tap) * NCOUT + cohalf * 128) * CING);
            for (int i = t; i < 1024; i += 256) {
                int row = i >> 3, j = i & 7;
                *reinterpret_cast<float4*>(sA + row * SROW + j * 8) = srcA[i];
            }
        }

#pragma unroll
        for (int split = 0; split < 2; split++) {
            if (split == 1) __syncthreads();   // hi-split reads done before restage
            // stage B [128 px][64 ch] -> sB
            {
                const float4* srcB = reinterpret_cast<const float4*>(
                    g_xs + ((size_t)(split * 3 + dj) * NIMG + img) * IMGSZ
                         + (size_t)(ptile * 4 + di) * XROW);
                for (int i = t; i < 1024; i += 256) {
                    int row = i >> 3, j = i & 7;
                    *reinterpret_cast<float4*>(sB + row * SROW + j * 8) = srcB[i];
                }
            }
            __syncthreads();

#pragma unroll
            for (int k = 0; k < 4; k++) {
                uint32_t a0[4], a1[4];
                ldsm_x4(a0[0], a0[1], a0[2], a0[3],
                        sAu + ((wm + 0  + aRow) * SROW + k * 16 + aCol) * 2);
                ldsm_x4(a1[0], a1[1], a1[2], a1[3],
                        sAu + ((wm + 16 + aRow) * SROW + k * 16 + aCol) * 2);
#pragma unroll
                for (int nb = 0; nb < 4; nb++) {
                    uint32_t r0, r1, r2, r3;
                    ldsm_x4(r0, r1, r2, r3,
                            sBu + ((wn + nb * 16 + bRow) * SROW + k * 16 + bCol) * 2);
                    if (split == 0 && k == 0) {
                        mma16816_z(acc[nb * 2][0], acc[nb * 2][1],
                                   acc[nb * 2][2], acc[nb * 2][3],
                                   a0[0], a0[1], a0[2], a0[3], r0, r1);
                        mma16816_z(acc[nb * 2 + 1][0], acc[nb * 2 + 1][1],
                                   acc[nb * 2 + 1][2], acc[nb * 2 + 1][3],
                                   a0[0], a0[1], a0[2], a0[3], r2, r3);
                        mma16816_z(acc[8 + nb * 2][0], acc[8 + nb * 2][1],
                                   acc[8 + nb * 2][2], acc[8 + nb * 2][3],
                                   a1[0], a1[1], a1[2], a1[3], r0, r1);
                        mma16816_z(acc[8 + nb * 2 + 1][0], acc[8 + nb * 2 + 1][1],
                                   acc[8 + nb * 2 + 1][2], acc[8 + nb * 2 + 1][3],
                                   a1[0], a1[1], a1[2], a1[3], r2, r3);
                    } else {
                        mma16816(acc[nb * 2][0], acc[nb * 2][1],
                                 acc[nb * 2][2], acc[nb * 2][3],
                                 a0[0], a0[1], a0[2], a0[3], r0, r1);
                        mma16816(acc[nb * 2 + 1][0], acc[nb * 2 + 1][1],
                                 acc[nb * 2 + 1][2], acc[nb * 2 + 1][3],
                                 a0[0], a0[1], a0[2], a0[3], r2, r3);
                        mma16816(acc[8 + nb * 2][0], acc[8 + nb * 2][1],
                                 acc[8 + nb * 2][2], acc[8 + nb * 2][3],
                                 a1[0], a1[1], a1[2], a1[3], r0, r1);
                        mma16816(acc[8 + nb * 2 + 1][0], acc[8 + nb * 2 + 1][1],
                                 acc[8 + nb * 2 + 1][2], acc[8 + nb * 2 + 1][3],
                                 a1[0], a1[1], a1[2], a1[3], r2, r3);
                    }
                }
            }
        }
        __syncthreads();   // lo-split reads done before next tap restages A/B

        // flush tap sub-accumulator into cross-tap bank (chain 9 at full mag)
#pragma unroll
        for (int i = 0; i < 16; i++)
#pragma unroll
            for (int j = 0; j < 4; j++) acc2[i][j] += acc[i][j];
    }

    // Epilogue: direct float2 stores (full 32B sectors)
    const int coBase = cohalf * 128 + wm;
#pragma unroll
    for (int mi = 0; mi < 2; mi++) {
#pragma unroll
        for (int ni = 0; ni < 8; ni++) {
            const int co_r = coBase + mi * 16 + (lane >> 2);
            const int px_c = px0 + wn + ni * 8 + (lane & 3) * 2;
            float* p0 = &g_bconv[((size_t)img * NCOUT + co_r) * HW + px_c];
            *reinterpret_cast<float2*>(p0) =
                make_float2(acc2[mi * 8 + ni][0], acc2[mi * 8 + ni][1]);
            *reinterpret_cast<float2*>(p0 + 8 * HW) =
                make_float2(acc2[mi * 8 + ni][2], acc2[mi * 8 + ni][3]);
        }
    }
}

// ---------------------------------------------------------------------------
// Kernel 3: BN stats per channel (atomic-free; one block per BN channel).
// ---------------------------------------------------------------------------
__global__ void stats_kernel() {
    const int ch = blockIdx.x;       // 0..1023 = g*256+co
    const int t  = threadIdx.x;
    double s1 = 0.0, s2 = 0.0;
    for (int b = 0; b < NB; b++) {
        const float4 v = reinterpret_cast<const float4*>(g_bconv)
                         [((size_t)(b * 1024 + ch)) * 256 + t];
        s1 += (double)v.x; s2 += (double)v.x * v.x;
        s1 += (double)v.y; s2 += (double)v.y * v.y;
        s1 += (double)v.z; s2 += (double)v.z * v.z;
        s1 += (double)v.w; s2 += (double)v.w * v.w;
    }
    __shared__ double r1[256], r2[256];
    r1[t] = s1; r2[t] = s2;
    __syncthreads();
    for (int o = 128; o > 0; o >>= 1) {
        if (t < o) { r1[t] += r1[t + o]; r2[t] += r2[t + o]; }
        __syncthreads();
    }
    if (t == 0) { g_sum[ch] = r1[0]; g_sumsq[ch] = r2[0]; }
}

// ---------------------------------------------------------------------------
// Kernel 4: finalize per-channel BN affine in fp64.
// ---------------------------------------------------------------------------
__global__ void finalize_kernel(const float* __restrict__ gamma,
                                const float* __restrict__ beta) {
    const int ch = blockIdx.x * 256 + threadIdx.x;
    if (ch >= NCH) return;
    const int co = ch & (NCOUT - 1);
    const double N = (double)NB * (double)HW;
    const double mean_b = g_sum[ch] / N;
    const double var_b  = g_sumsq[ch] / N - mean_b * mean_b;
    const double a      = (double)g_alpha[co];
    const double inv    = rsqrt(a * a * var_b + 1e-5) * (double)gamma[ch];
    g_cA[ch] = (float)(a * inv);
    g_cB[ch] = (float)((double)beta[ch] - a * mean_b * inv);
}

// ---------------------------------------------------------------------------
// Kernel 5: sign + group merge + qrelu quantization.
// ---------------------------------------------------------------------------
__global__ void merge_kernel(float* __restrict__ out) {
    const size_t i   = (size_t)blockIdx.x * 256 + threadIdx.x;
    const size_t px4 = i & 255;
    const size_t bc  = i >> 8;
    const size_t co  = bc & (NCOUT - 1);
    const size_t b   = bc >> 8;

    int y0 = 0, y1 = 0, y2 = 0, y3 = 0;
#pragma unroll
    for (int g = 0; g < NG; g++) {
        const size_t idx = (((b * NG + g) * NCOUT + co) * (HW / 4)) + px4;
        const float4 v = reinterpret_cast<const float4*>(g_bconv)[idx];
        const int ch = g * NCOUT + (int)co;
        const float cA = g_cA[ch];
        const float cB = g_cB[ch];
        y0 += (fmaf(v.x, cA, cB) >= 0.0f) ? 1 : -1;
        y1 += (fmaf(v.y, cA, cB) >= 0.0f) ? 1 : -1;
        y2 += (fmaf(v.z, cA, cB) >= 0.0f) ? 1 : -1;
        y3 += (fmaf(v.w, cA, cB) >= 0.0f) ? 1 : -1;
    }
    const float QMID = (8.0f / 15.0f) * 4.0f;
    float4 o;
    o.x = (y0 >= 4) ? 4.0f : ((y0 >= 2) ? QMID : 0.0f);
    o.y = (y1 >= 4) ? 4.0f : ((y1 >= 2) ? QMID : 0.0f);
    o.z = (y2 >= 4) ? 4.0f : ((y2 >= 2) ? QMID : 0.0f);
    o.w = (y3 >= 4) ? 4.0f : ((y3 >= 2) ? QMID : 0.0f);
    reinterpret_cast<float4*>(out)[i] = o;
}

// ---------------------------------------------------------------------------
extern "C" void kernel_launch(void* const* d_in, const int* in_sizes, int n_in,
                              void* d_out, int out_size) {
    (void)in_sizes; (void)n_in; (void)out_size;
    const float* x     = (const float*)d_in[0];
    const float* w     = (const float*)d_in[1];
    const float* gamma = (const float*)d_in[2];
    const float* beta  = (const float*)d_in[3];
    float* out = (float*)d_out;

    prep_w_kernel<<<256, 256>>>(w);
    prep_x_kernel<<<dim3(HPAD, NIMG), 256>>>(x);
    conv_mma_kernel<<<dim3(16, NG, NB), 256>>>();
    stats_kernel<<<NCH, 256>>>();
    finalize_kernel<<<4, 256>>>(gamma, beta);
    merge_kernel<<<(NB * NCOUT * HW / 4) / 256, 256>>>(out);
}

// round 9
// speedup vs baseline: 3.3868x; 1.6124x over previous
#include <cuda_runtime.h>
#include <cuda_fp16.h>
#include <cstdint>

// Problem constants
#define NB    32
#define NG    4
#define NCOUT 256     // output channels per group
#define CING  64      // input channels per group
#define NCH   1024
#define HW    1024
#define NIMG  128     // NB*NG
#define HPAD  34      // padded rows (hp = 0..33 <-> xh = hp-1)
#define WROW  2176    // 34 wp * 64 ch halves per padded row
#define IMGSZ2 (HPAD * WROW)  // 73984 halves per image per split
#define SROW  72      // smem row stride in halves (64 + 8 pad)

// Device scratch (no allocations allowed)
__device__ float  g_alpha[NCOUT];
__device__ __align__(16) __half g_A[NG * 9 * NCOUT * CING];         // [g][tap][co][ch], +-1
__device__ __align__(16) __half g_xs[(size_t)2 * NIMG * IMGSZ2];    // [split][img][hp][wp][ch], 37.9MB
__device__ float  g_bconv[(size_t)NB * NCH * HW];                   // 134 MB
__device__ double g_sum[NCH];
__device__ double g_sumsq[NCH];
__device__ float  g_cA[NCH];
__device__ float  g_cB[NCH];

__device__ __forceinline__ uint32_t smem_u32(const void* p) {
    uint32_t a;
    asm("{ .reg .u64 t; cvta.to.shared.u64 t, %1; cvt.u32.u64 %0, t; }" : "=r"(a) : "l"(p));
    return a;
}
__device__ __forceinline__ void ldsm_x4(uint32_t& r0, uint32_t& r1, uint32_t& r2, uint32_t& r3,
                                        uint32_t addr) {
    asm volatile("ldmatrix.sync.aligned.m8n8.x4.shared.b16 {%0,%1,%2,%3}, [%4];"
                 : "=r"(r0), "=r"(r1), "=r"(r2), "=r"(r3) : "r"(addr));
}
// accumulate: D = A*B + D
__device__ __forceinline__ void mma16816(float& c0, float& c1, float& c2, float& c3,
                                         uint32_t a0, uint32_t a1, uint32_t a2, uint32_t a3,
                                         uint32_t b0, uint32_t b1) {
    asm volatile(
        "mma.sync.aligned.m16n8k16.row.col.f32.f16.f16.f32 "
        "{%0,%1,%2,%3}, {%4,%5,%6,%7}, {%8,%9}, {%0,%1,%2,%3};"
        : "+f"(c0), "+f"(c1), "+f"(c2), "+f"(c3)
        : "r"(a0), "r"(a1), "r"(a2), "r"(a3), "r"(b0), "r"(b1));
}
// overwrite: D = A*B + 0
__device__ __forceinline__ void mma16816_z(float& c0, float& c1, float& c2, float& c3,
                                           uint32_t a0, uint32_t a1, uint32_t a2, uint32_t a3,
                                           uint32_t b0, uint32_t b1) {
    asm volatile(
        "mma.sync.aligned.m16n8k16.row.col.f32.f16.f16.f32 "
        "{%0,%1,%2,%3}, {%4,%5,%6,%7}, {%8,%9}, {%10,%10,%10,%10};"
        : "=f"(c0), "=f"(c1), "=f"(c2), "=f"(c3)
        : "r"(a0), "r"(a1), "r"(a2), "r"(a3), "r"(b0), "r"(b1), "f"(0.0f));
}

// ---------------------------------------------------------------------------
// Kernel 0: alpha = mean|w|; sign tiles A[g][tap][co][ch] fp16; zero stats.
// ---------------------------------------------------------------------------
__global__ void prep_w_kernel(const float* __restrict__ w) {
    const int co = blockIdx.x;
    const int t  = threadIdx.x;
    const float* wc = w + (size_t)co * 256 * 9;

    if (t < 4) {
        g_sum[co * 4 + t]   = 0.0;
        g_sumsq[co * 4 + t] = 0.0;
    }

    float s = 0.0f;
    for (int i = t; i < 256 * 9; i += 256) s += fabsf(wc[i]);
    __shared__ float red[256];
    red[t] = s;
    __syncthreads();
    for (int o = 128; o > 0; o >>= 1) {
        if (t < o) red[t] += red[t + o];
        __syncthreads();
    }
    if (t == 0) g_alpha[co] = red[0] / 2304.0f;

    for (int i = t; i < 256 * 9; i += 256) {
        int ci = i / 9, tap = i - ci * 9;
        int g = ci >> 6, ch = ci & 63;
        __half v = (wc[i] >= 0.0f) ? __float2half_rn(1.0f) : __float2half_rn(-1.0f);
        g_A[((size_t)(g * 9 + tap) * NCOUT + co) * CING + ch] = v;
    }
}

// ---------------------------------------------------------------------------
// Kernel 1: build hi/lo split copies with padded w (wp = w+1, zeros at 0/33).
// g_xs[split][img][hp][wp][ch] = split(x[b, g*64+ch, hp-1, wp-1])
// grid (34, 128), 256 threads.
// ---------------------------------------------------------------------------
__global__ void prep_x_kernel(const float* __restrict__ x) {
    const int hp  = blockIdx.x;
    const int img = blockIdx.y;
    const int g   = img & 3;
    const int b   = img >> 2;
    const int t   = threadIdx.x;
    const int xh  = hp - 1;
    const bool hin = (xh >= 0) && (xh < 32);

    __shared__ float sx[CING * 32];   // [ch][w]
    if (hin) {
        const float4* src = reinterpret_cast<const float4*>(x) +
                            ((size_t)(b * 256 + g * 64) * 1024 + (size_t)xh * 32) / 4;
        for (int i = t; i < 512; i += 256) {
            int ch = i >> 3, j = i & 7;
            reinterpret_cast<float4*>(sx)[ch * 8 + j] = src[(size_t)ch * 256 + j];
        }
    } else {
        for (int i = t; i < CING * 32 / 4; i += 256)
            reinterpret_cast<float4*>(sx)[i] = make_float4(0.f, 0.f, 0.f, 0.f);
    }
    __syncthreads();

    // 2 splits x 34 wp x 32 ch-pairs = 2176 half2
    for (int i = t; i < 2 * 34 * 32; i += 256) {
        int split = (i >= 1088) ? 1 : 0;
        int r  = i - split * 1088;
        int wp = r >> 5;             // 0..33
        int c2 = (r & 31) * 2;       // ch pair
        int xw = wp - 1;
        float v0 = 0.f, v1 = 0.f;
        if (hin && xw >= 0 && xw < 32) {
            v0 = sx[c2 * 32 + xw];
            v1 = sx[(c2 + 1) * 32 + xw];
        }
        __half h0, h1;
        if (split == 0) {
            h0 = __float2half_rn(v0);
            h1 = __float2half_rn(v1);
        } else {
            h0 = __float2half_rn(v0 - __half2float(__float2half_rn(v0)));
            h1 = __float2half_rn(v1 - __half2float(__float2half_rn(v1)));
        }
        size_t off = ((size_t)split * NIMG + img) * IMGSZ2 + (size_t)hp * WROW + wp * 64 + c2;
        *reinterpret_cast<__half2*>(&g_xs[off]) = __halves2half2(h0, h1);
    }
}

// ---------------------------------------------------------------------------
// Kernel 2: HMMA implicit GEMM with per-tap sub-accumulator flush.
// CTA = (cohalf | ptile) x g x b. M=128 co, N=128 px (4 image rows),
// K = 9 taps x 2 splits x 64 ch. 8 warps (4M x 2N), warp tile 32x64.
// Tap shift: di = row offset, dj = 64-half base offset into padded-w layout.
// ---------------------------------------------------------------------------
__global__ void __launch_bounds__(256) conv_mma_kernel() {
    __shared__ __half sA[128 * SROW];   // 18.4 KB
    __shared__ __half sB[128 * SROW];   // 18.4 KB

    const int t      = threadIdx.x;
    const int wid    = t >> 5;
    const int lane   = t & 31;
    const int cohalf = blockIdx.x & 1;
    const int ptile  = blockIdx.x >> 1;    // 0..7 (4 image rows each)
    const int g      = blockIdx.y;
    const int b      = blockIdx.z;
    const int img    = b * 4 + g;
    const int px0    = ptile * 128;

    const int wm = (wid >> 1) * 32;        // warp M offset (co)
    const int wn = (wid & 1) * 64;         // warp N offset (px)

    const uint32_t sAu = smem_u32(sA);
    const uint32_t sBu = smem_u32(sB);

    const int aRow = lane & 15;
    const int aCol = (lane >> 4) * 8;
    const int bRow = (lane & 7) + ((lane >> 4) & 1) * 8;
    const int bCol = ((lane >> 3) & 1) * 8;

    float acc[16][4];    // per-tap sub-accumulator
    float acc2[16][4];   // cross-tap accumulator
#pragma unroll
    for (int i = 0; i < 16; i++)
#pragma unroll
        for (int j = 0; j < 4; j++) acc2[i][j] = 0.0f;

    for (int tap = 0; tap < 9; tap++) {
        const int di = tap / 3, dj = tap - di * 3;

        __syncthreads();   // previous tap's reads done
        // stage A [128 co][64 ch] -> sA
        {
            const float4* srcA = reinterpret_cast<const float4*>(
                g_A + ((size_t)(g * 9 + tap) * NCOUT + cohalf * 128) * CING);
            for (int i = t; i < 1024; i += 256) {
                int row = i >> 3, j = i & 7;
                *reinterpret_cast<float4*>(sA + row * SROW + j * 8) = srcA[i];
            }
        }

#pragma unroll
        for (int split = 0; split < 2; split++) {
            if (split == 1) __syncthreads();   // hi-split reads done before restage
            // stage B [128 px][64 ch] -> sB. px row r: hp = ptile*4+di+(r>>5), w = r&31,
            // shifted column via dj*64 base offset (wp = w + dj).
            {
                const __half* srcB = g_xs + ((size_t)split * NIMG + img) * IMGSZ2
                                   + (size_t)(ptile * 4 + di) * WROW + dj * 64;
                for (int i = t; i < 1024; i += 256) {
                    int row = i >> 3, j = i & 7;
                    float4 v = *reinterpret_cast<const float4*>(
                        srcB + (row >> 5) * WROW + (row & 31) * 64 + j * 8);
                    *reinterpret_cast<float4*>(sB + row * SROW + j * 8) = v;
                }
            }
            __syncthreads();

#pragma unroll
            for (int k = 0; k < 4; k++) {
                uint32_t a0[4], a1[4];
                ldsm_x4(a0[0], a0[1], a0[2], a0[3],
                        sAu + ((wm + 0  + aRow) * SROW + k * 16 + aCol) * 2);
                ldsm_x4(a1[0], a1[1], a1[2], a1[3],
                        sAu + ((wm + 16 + aRow) * SROW + k * 16 + aCol) * 2);
#pragma unroll
                for (int nb = 0; nb < 4; nb++) {
                    uint32_t r0, r1, r2, r3;
                    ldsm_x4(r0, r1, r2, r3,
                            sBu + ((wn + nb * 16 + bRow) * SROW + k * 16 + bCol) * 2);
                    if (split == 0 && k == 0) {
                        mma16816_z(acc[nb * 2][0], acc[nb * 2][1],
                                   acc[nb * 2][2], acc[nb * 2][3],
                                   a0[0], a0[1], a0[2], a0[3], r0, r1);
                        mma16816_z(acc[nb * 2 + 1][0], acc[nb * 2 + 1][1],
                                   acc[nb * 2 + 1][2], acc[nb * 2 + 1][3],
                                   a0[0], a0[1], a0[2], a0[3], r2, r3);
                        mma16816_z(acc[8 + nb * 2][0], acc[8 + nb * 2][1],
                                   acc[8 + nb * 2][2], acc[8 + nb * 2][3],
                                   a1[0], a1[1], a1[2], a1[3], r0, r1);
                        mma16816_z(acc[8 + nb * 2 + 1][0], acc[8 + nb * 2 + 1][1],
                                   acc[8 + nb * 2 + 1][2], acc[8 + nb * 2 + 1][3],
                                   a1[0], a1[1], a1[2], a1[3], r2, r3);
                    } else {
                        mma16816(acc[nb * 2][0], acc[nb * 2][1],
                                 acc[nb * 2][2], acc[nb * 2][3],
                                 a0[0], a0[1], a0[2], a0[3], r0, r1);
                        mma16816(acc[nb * 2 + 1][0], acc[nb * 2 + 1][1],
                                 acc[nb * 2 + 1][2], acc[nb * 2 + 1][3],
                                 a0[0], a0[1], a0[2], a0[3], r2, r3);
                        mma16816(acc[8 + nb * 2][0], acc[8 + nb * 2][1],
                                 acc[8 + nb * 2][2], acc[8 + nb * 2][3],
                                 a1[0], a1[1], a1[2], a1[3], r0, r1);
                        mma16816(acc[8 + nb * 2 + 1][0], acc[8 + nb * 2 + 1][1],
                                 acc[8 + nb * 2 + 1][2], acc[8 + nb * 2 + 1][3],
                                 a1[0], a1[1], a1[2], a1[3], r2, r3);
                    }
                }
            }
        }
        __syncthreads();   // lo-split reads done before next tap restages A/B

        // flush tap sub-accumulator into cross-tap bank
#pragma unroll
        for (int i = 0; i < 16; i++)
#pragma unroll
            for (int j = 0; j < 4; j++) acc2[i][j] += acc[i][j];
    }

    // Epilogue: direct float2 stores (full 32B sectors)
    const int coBase = cohalf * 128 + wm;
#pragma unroll
    for (int mi = 0; mi < 2; mi++) {
#pragma unroll
        for (int ni = 0; ni < 8; ni++) {
            const int co_r = coBase + mi * 16 + (lane >> 2);
            const int px_c = px0 + wn + ni * 8 + (lane & 3) * 2;
            float* p0 = &g_bconv[((size_t)img * NCOUT + co_r) * HW + px_c];
            *reinterpret_cast<float2*>(p0) =
                make_float2(acc2[mi * 8 + ni][0], acc2[mi * 8 + ni][1]);
            *reinterpret_cast<float2*>(p0 + 8 * HW) =
                make_float2(acc2[mi * 8 + ni][2], acc2[mi * 8 + ni][3]);
        }
    }
}

// ---------------------------------------------------------------------------
// Kernel 3: BN stats — bandwidth-bound version.
// grid (1024 ch, 8 b-slices), 256 threads; 4 independent b-partials per
// thread (MLP=4, fp32), block reduce, one fp64 atomic per block.
// ---------------------------------------------------------------------------
__global__ void __launch_bounds__(256) stats_kernel() {
    const int ch = blockIdx.x;       // 0..1023 = g*256+co
    const int bs = blockIdx.y;       // 0..7
    const int t  = threadIdx.x;
    const int lane = t & 31;
    const int wid  = t >> 5;

    float p1[4], p2[4];
#pragma unroll
    for (int bb = 0; bb < 4; bb++) {
        const float4 v = reinterpret_cast<const float4*>(g_bconv)
                         [((size_t)((bs * 4 + bb) * 1024 + ch)) * 256 + t];
        p1[bb] = (v.x + v.y) + (v.z + v.w);
        p2[bb] = (v.x * v.x + v.y * v.y) + (v.z * v.z + v.w * v.w);
    }
    float s1 = (p1[0] + p1[1]) + (p1[2] + p1[3]);
    float s2 = (p2[0] + p2[1]) + (p2[2] + p2[3]);

#pragma unroll
    for (int o = 16; o > 0; o >>= 1) {
        s1 += __shfl_xor_sync(0xFFFFFFFFu, s1, o);
        s2 += __shfl_xor_sync(0xFFFFFFFFu, s2, o);
    }
    __shared__ float r1[8], r2[8];
    if (lane == 0) { r1[wid] = s1; r2[wid] = s2; }
    __syncthreads();
    if (t == 0) {
        float t1 = 0.f, t2 = 0.f;
#pragma unroll
        for (int i = 0; i < 8; i++) { t1 += r1[i]; t2 += r2[i]; }
        atomicAdd(&g_sum[ch],   (double)t1);
        atomicAdd(&g_sumsq[ch], (double)t2);
    }
}

// ---------------------------------------------------------------------------
// Kernel 4: finalize per-channel BN affine in fp64.
// ---------------------------------------------------------------------------
__global__ void finalize_kernel(const float* __restrict__ gamma,
                                const float* __restrict__ beta) {
    const int ch = blockIdx.x * 256 + threadIdx.x;
    if (ch >= NCH) return;
    const int co = ch & (NCOUT - 1);
    const double N = (double)NB * (double)HW;
    const double mean_b = g_sum[ch] / N;
    const double var_b  = g_sumsq[ch] / N - mean_b * mean_b;
    const double a      = (double)g_alpha[co];
    const double inv    = rsqrt(a * a * var_b + 1e-5) * (double)gamma[ch];
    g_cA[ch] = (float)(a * inv);
    g_cB[ch] = (float)((double)beta[ch] - a * mean_b * inv);
}

// ---------------------------------------------------------------------------
// Kernel 5: sign + group merge + qrelu quantization.
// ---------------------------------------------------------------------------
__global__ void merge_kernel(float* __restrict__ out) {
    const size_t i   = (size_t)blockIdx.x * 256 + threadIdx.x;
    const size_t px4 = i & 255;
    const size_t bc  = i >> 8;
    const size_t co  = bc & (NCOUT - 1);
    const size_t b   = bc >> 8;

    int y0 = 0, y1 = 0, y2 = 0, y3 = 0;
#pragma unroll
    for (int g = 0; g < NG; g++) {
        const size_t idx = (((b * NG + g) * NCOUT + co) * (HW / 4)) + px4;
        const float4 v = reinterpret_cast<const float4*>(g_bconv)[idx];
        const int ch = g * NCOUT + (int)co;
        const float cA = g_cA[ch];
        const float cB = g_cB[ch];
        y0 += (fmaf(v.x, cA, cB) >= 0.0f) ? 1 : -1;
        y1 += (fmaf(v.y, cA, cB) >= 0.0f) ? 1 : -1;
        y2 += (fmaf(v.z, cA, cB) >= 0.0f) ? 1 : -1;
        y3 += (fmaf(v.w, cA, cB) >= 0.0f) ? 1 : -1;
    }
    const float QMID = (8.0f / 15.0f) * 4.0f;
    float4 o;
    o.x = (y0 >= 4) ? 4.0f : ((y0 >= 2) ? QMID : 0.0f);
    o.y = (y1 >= 4) ? 4.0f : ((y1 >= 2) ? QMID : 0.0f);
    o.z = (y2 >= 4) ? 4.0f : ((y2 >= 2) ? QMID : 0.0f);
    o.w = (y3 >= 4) ? 4.0f : ((y3 >= 2) ? QMID : 0.0f);
    reinterpret_cast<float4*>(out)[i] = o;
}

// ---------------------------------------------------------------------------
extern "C" void kernel_launch(void* const* d_in, const int* in_sizes, int n_in,
                              void* d_out, int out_size) {
    (void)in_sizes; (void)n_in; (void)out_size;
    const float* x     = (const float*)d_in[0];
    const float* w     = (const float*)d_in[1];
    const float* gamma = (const float*)d_in[2];
    const float* beta  = (const float*)d_in[3];
    float* out = (float*)d_out;

    prep_w_kernel<<<256, 256>>>(w);
    prep_x_kernel<<<dim3(HPAD, NIMG), 256>>>(x);
    conv_mma_kernel<<<dim3(16, NG, NB), 256>>>();
    stats_kernel<<<dim3(NCH, 8), 256>>>();
    finalize_kernel<<<4, 256>>>(gamma, beta);
    merge_kernel<<<(NB * NCOUT * HW / 4) / 256, 256>>>(out);
}

// round 10
// speedup vs baseline: 4.2318x; 1.2495x over previous
#include <cuda_runtime.h>
#include <cuda_fp16.h>
#include <cstdint>

// Problem constants
#define NB    32
#define NG    4
#define NCOUT 256     // output channels per group
#define CING  64      // input channels per group
#define NCH   1024
#define HW    1024
#define NIMG  128     // NB*NG
#define HPAD  34      // padded rows (hp = 0..33 <-> xh = hp-1)
#define WROW  2176    // 34 wp * 64 ch halves per padded row (gmem)
#define IMGSZ2 (HPAD * WROW)  // 73984 halves per image per split
#define SROW  72      // A smem row stride in halves (64 + 8 pad)
#define CHS   72      // B smem per-pixel stride in halves (64 + 8 pad)
#define BROW  (34 * CHS)      // 2448 halves per image row in smem
#define BSPL  (6 * BROW)      // 14688 halves per split (6 halo rows)

// Dynamic smem layout (bytes)
#define SM_B   0                      // bigB: 2 splits * 14688 halves = 58752 B
#define SM_A0  58752                  // A buf 0: 128*72*2 = 18432 B
#define SM_A1  77184                  // A buf 1
#define SM_TOT 95616

// Device scratch (no allocations allowed)
__device__ float  g_alpha[NCOUT];
__device__ __align__(16) __half g_A[NG * 9 * NCOUT * CING];         // [g][tap][co][ch], +-1
__device__ __align__(16) __half g_xs[(size_t)2 * NIMG * IMGSZ2];    // [split][img][hp][wp][ch]
__device__ float  g_bconv[(size_t)NB * NCH * HW];                   // 134 MB
__device__ double g_sum[NCH];
__device__ double g_sumsq[NCH];
__device__ float  g_cA[NCH];
__device__ float  g_cB[NCH];

__device__ __forceinline__ uint32_t smem_u32(const void* p) {
    uint32_t a;
    asm("{ .reg .u64 t; cvta.to.shared.u64 t, %1; cvt.u32.u64 %0, t; }" : "=r"(a) : "l"(p));
    return a;
}
__device__ __forceinline__ void ldsm_x4(uint32_t& r0, uint32_t& r1, uint32_t& r2, uint32_t& r3,
                                        uint32_t addr) {
    asm volatile("ldmatrix.sync.aligned.m8n8.x4.shared.b16 {%0,%1,%2,%3}, [%4];"
                 : "=r"(r0), "=r"(r1), "=r"(r2), "=r"(r3) : "r"(addr));
}
// accumulate: D = A*B + D
__device__ __forceinline__ void mma16816(float& c0, float& c1, float& c2, float& c3,
                                         uint32_t a0, uint32_t a1, uint32_t a2, uint32_t a3,
                                         uint32_t b0, uint32_t b1) {
    asm volatile(
        "mma.sync.aligned.m16n8k16.row.col.f32.f16.f16.f32 "
        "{%0,%1,%2,%3}, {%4,%5,%6,%7}, {%8,%9}, {%0,%1,%2,%3};"
        : "+f"(c0), "+f"(c1), "+f"(c2), "+f"(c3)
        : "r"(a0), "r"(a1), "r"(a2), "r"(a3), "r"(b0), "r"(b1));
}
// overwrite: D = A*B + 0
__device__ __forceinline__ void mma16816_z(float& c0, float& c1, float& c2, float& c3,
                                           uint32_t a0, uint32_t a1, uint32_t a2, uint32_t a3,
                                           uint32_t b0, uint32_t b1) {
    asm volatile(
        "mma.sync.aligned.m16n8k16.row.col.f32.f16.f16.f32 "
        "{%0,%1,%2,%3}, {%4,%5,%6,%7}, {%8,%9}, {%10,%10,%10,%10};"
        : "=f"(c0), "=f"(c1), "=f"(c2), "=f"(c3)
        : "r"(a0), "r"(a1), "r"(a2), "r"(a3), "r"(b0), "r"(b1), "f"(0.0f));
}

// ---------------------------------------------------------------------------
// Kernel 0: alpha = mean|w|; sign tiles A[g][tap][co][ch] fp16; zero stats.
// ---------------------------------------------------------------------------
__global__ void prep_w_kernel(const float* __restrict__ w) {
    const int co = blockIdx.x;
    const int t  = threadIdx.x;
    const float* wc = w + (size_t)co * 256 * 9;

    if (t < 4) {
        g_sum[co * 4 + t]   = 0.0;
        g_sumsq[co * 4 + t] = 0.0;
    }

    float s = 0.0f;
    for (int i = t; i < 256 * 9; i += 256) s += fabsf(wc[i]);
    __shared__ float red[256];
    red[t] = s;
    __syncthreads();
    for (int o = 128; o > 0; o >>= 1) {
        if (t < o) red[t] += red[t + o];
        __syncthreads();
    }
    if (t == 0) g_alpha[co] = red[0] / 2304.0f;

    for (int i = t; i < 256 * 9; i += 256) {
        int ci = i / 9, tap = i - ci * 9;
        int g = ci >> 6, ch = ci & 63;
        __half v = (wc[i] >= 0.0f) ? __float2half_rn(1.0f) : __float2half_rn(-1.0f);
        g_A[((size_t)(g * 9 + tap) * NCOUT + co) * CING + ch] = v;
    }
}

// ---------------------------------------------------------------------------
// Kernel 1: build hi/lo split copies with padded w (wp = w+1, zeros at 0/33).
// g_xs[split][img][hp][wp][ch] = split(x[b, g*64+ch, hp-1, wp-1])
// grid (34, 128), 256 threads.
// ---------------------------------------------------------------------------
__global__ void prep_x_kernel(const float* __restrict__ x) {
    const int hp  = blockIdx.x;
    const int img = blockIdx.y;
    const int g   = img & 3;
    const int b   = img >> 2;
    const int t   = threadIdx.x;
    const int xh  = hp - 1;
    const bool hin = (xh >= 0) && (xh < 32);

    __shared__ float sx[CING * 32];   // [ch][w]
    if (hin) {
        const float4* src = reinterpret_cast<const float4*>(x) +
                            ((size_t)(b * 256 + g * 64) * 1024 + (size_t)xh * 32) / 4;
        for (int i = t; i < 512; i += 256) {
            int ch = i >> 3, j = i & 7;
            reinterpret_cast<float4*>(sx)[ch * 8 + j] = src[(size_t)ch * 256 + j];
        }
    } else {
        for (int i = t; i < CING * 32 / 4; i += 256)
            reinterpret_cast<float4*>(sx)[i] = make_float4(0.f, 0.f, 0.f, 0.f);
    }
    __syncthreads();

    for (int i = t; i < 2 * 34 * 32; i += 256) {
        int split = (i >= 1088) ? 1 : 0;
        int r  = i - split * 1088;
        int wp = r >> 5;
        int c2 = (r & 31) * 2;
        int xw = wp - 1;
        float v0 = 0.f, v1 = 0.f;
        if (hin && xw >= 0 && xw < 32) {
            v0 = sx[c2 * 32 + xw];
            v1 = sx[(c2 + 1) * 32 + xw];
        }
        __half h0, h1;
        if (split == 0) {
            h0 = __float2half_rn(v0);
            h1 = __float2half_rn(v1);
        } else {
            h0 = __float2half_rn(v0 - __half2float(__float2half_rn(v0)));
            h1 = __float2half_rn(v1 - __half2float(__float2half_rn(v1)));
        }
        size_t off = ((size_t)split * NIMG + img) * IMGSZ2 + (size_t)hp * WROW + wp * 64 + c2;
        *reinterpret_cast<__half2*>(&g_xs[off]) = __halves2half2(h0, h1);
    }
}

// ---------------------------------------------------------------------------
// Kernel 2: HMMA implicit GEMM, halo-resident B (staged ONCE per CTA),
// double-buffered A, per-tap sub-accumulator flush.
// CTA = (cohalf | ptile) x g x b. M=128 co, N=128 px (4 image rows).
// Tap shift = pure ldsm addressing into bigB.
// ---------------------------------------------------------------------------
__global__ void __launch_bounds__(256) conv_mma_kernel() {
    extern __shared__ char smem[];
    __half* bigB = reinterpret_cast<__half*>(smem + SM_B);

    const int t      = threadIdx.x;
    const int wid    = t >> 5;
    const int lane   = t & 31;
    const int cohalf = blockIdx.x & 1;
    const int ptile  = blockIdx.x >> 1;    // 0..7 (4 image rows each)
    const int g      = blockIdx.y;
    const int b      = blockIdx.z;
    const int img    = b * 4 + g;
    const int px0    = ptile * 128;

    const int wm = (wid >> 1) * 32;        // warp M offset (co)
    const int wn = (wid & 1) * 64;         // warp N offset (px)

    const uint32_t sB  = smem_u32(bigB);
    const uint32_t sA0 = smem_u32(smem + SM_A0);
    const uint32_t sA1 = smem_u32(smem + SM_A1);

    const int aRow = lane & 15;
    const int aCol = (lane >> 4) * 8;
    const int bRow = (lane & 7) + ((lane >> 4) & 1) * 8;
    const int bCol = ((lane >> 3) & 1) * 8;

    // Stage bigB once: [split][row 0..5][wp 0..33][ch 0..63] -> stride CHS=72
    {
        for (int i = t; i < 3264; i += 256) {       // 2*6*34*8 float4
            int split = (i >= 1632) ? 1 : 0;
            int rem = i - split * 1632;
            int row = rem / 272;
            int r2  = rem - row * 272;
            int wp  = r2 >> 3;
            int j   = r2 & 7;
            const float4 v = *reinterpret_cast<const float4*>(
                g_xs + ((size_t)split * NIMG + img) * IMGSZ2
                     + (size_t)(ptile * 4 + row) * WROW + wp * 64 + j * 8);
            *reinterpret_cast<float4*>(
                bigB + split * BSPL + row * BROW + wp * CHS + j * 8) = v;
        }
    }
    // Stage A(tap=0) into buf0
    {
        const float4* srcA = reinterpret_cast<const float4*>(
            g_A + ((size_t)(g * 9 + 0) * NCOUT + cohalf * 128) * CING);
        __half* dst = reinterpret_cast<__half*>(smem + SM_A0);
        for (int i = t; i < 1024; i += 256) {
            int row = i >> 3, j = i & 7;
            *reinterpret_cast<float4*>(dst + row * SROW + j * 8) = srcA[i];
        }
    }
    __syncthreads();

    float acc[16][4];    // per-tap sub-accumulator
    float acc2[16][4];   // cross-tap accumulator
#pragma unroll
    for (int i = 0; i < 16; i++)
#pragma unroll
        for (int j = 0; j < 4; j++) acc2[i][j] = 0.0f;

    // Per-lane B pixel decomposition (px = wn + nb*16 + bRow)
    const int pxb = wn + bRow;

    for (int tap = 0; tap < 9; tap++) {
        const int di = tap / 3, dj = tap - di * 3;
        const uint32_t sAcur = (tap & 1) ? sA1 : sA0;

        // prefetch A(tap+1) into the other buffer (overlaps with mma below)
        if (tap < 8) {
            const float4* srcA = reinterpret_cast<const float4*>(
                g_A + ((size_t)(g * 9 + tap + 1) * NCOUT + cohalf * 128) * CING);
            __half* dst = reinterpret_cast<__half*>(smem + ((tap & 1) ? SM_A0 : SM_A1));
            for (int i = t; i < 1024; i += 256) {
                int row = i >> 3, j = i & 7;
                *reinterpret_cast<float4*>(dst + row * SROW + j * 8) = srcA[i];
            }
        }

#pragma unroll
        for (int split = 0; split < 2; split++) {
#pragma unroll
            for (int k = 0; k < 4; k++) {
                uint32_t a0[4], a1[4];
                ldsm_x4(a0[0], a0[1], a0[2], a0[3],
                        sAcur + ((wm + 0  + aRow) * SROW + k * 16 + aCol) * 2);
                ldsm_x4(a1[0], a1[1], a1[2], a1[3],
                        sAcur + ((wm + 16 + aRow) * SROW + k * 16 + aCol) * 2);
#pragma unroll
                for (int nb = 0; nb < 4; nb++) {
                    const int px = pxb + nb * 16;
                    const int h  = px >> 5;
                    const int w  = px & 31;
                    uint32_t r0, r1, r2, r3;
                    ldsm_x4(r0, r1, r2, r3,
                            sB + (split * BSPL + (h + di) * BROW + (w + dj) * CHS
                                  + k * 16 + bCol) * 2);
                    if (split == 0 && k == 0) {
                        mma16816_z(acc[nb * 2][0], acc[nb * 2][1],
                                   acc[nb * 2][2], acc[nb * 2][3],
                                   a0[0], a0[1], a0[2], a0[3], r0, r1);
                        mma16816_z(acc[nb * 2 + 1][0], acc[nb * 2 + 1][1],
                                   acc[nb * 2 + 1][2], acc[nb * 2 + 1][3],
                                   a0[0], a0[1], a0[2], a0[3], r2, r3);
                        mma16816_z(acc[8 + nb * 2][0], acc[8 + nb * 2][1],
                                   acc[8 + nb * 2][2], acc[8 + nb * 2][3],
                                   a1[0], a1[1], a1[2], a1[3], r0, r1);
                        mma16816_z(acc[8 + nb * 2 + 1][0], acc[8 + nb * 2 + 1][1],
                                   acc[8 + nb * 2 + 1][2], acc[8 + nb * 2 + 1][3],
                                   a1[0], a1[1], a1[2], a1[3], r2, r3);
                    } else {
                        mma16816(acc[nb * 2][0], acc[nb * 2][1],
                                 acc[nb * 2][2], acc[nb * 2][3],
                                 a0[0], a0[1], a0[2], a0[3], r0, r1);
                        mma16816(acc[nb * 2 + 1][0], acc[nb * 2 + 1][1],
                                 acc[nb * 2 + 1][2], acc[nb * 2 + 1][3],
                                 a0[0], a0[1], a0[2], a0[3], r2, r3);
                        mma16816(acc[8 + nb * 2][0], acc[8 + nb * 2][1],
                                 acc[8 + nb * 2][2], acc[8 + nb * 2][3],
                                 a1[0], a1[1], a1[2], a1[3], r0, r1);
                        mma16816(acc[8 + nb * 2 + 1][0], acc[8 + nb * 2 + 1][1],
                                 acc[8 + nb * 2 + 1][2], acc[8 + nb * 2 + 1][3],
                                 a1[0], a1[1], a1[2], a1[3], r2, r3);
                    }
                }
            }
        }
        __syncthreads();   // A prefetch visible; this tap's A reads done

        // flush tap sub-accumulator into cross-tap bank
#pragma unroll
        for (int i = 0; i < 16; i++)
#pragma unroll
            for (int j = 0; j < 4; j++) acc2[i][j] += acc[i][j];
    }

    // Epilogue: direct float2 stores (full 32B sectors)
    const int coBase = cohalf * 128 + wm;
#pragma unroll
    for (int mi = 0; mi < 2; mi++) {
#pragma unroll
        for (int ni = 0; ni < 8; ni++) {
            const int co_r = coBase + mi * 16 + (lane >> 2);
            const int px_c = px0 + wn + ni * 8 + (lane & 3) * 2;
            float* p0 = &g_bconv[((size_t)img * NCOUT + co_r) * HW + px_c];
            *reinterpret_cast<float2*>(p0) =
                make_float2(acc2[mi * 8 + ni][0], acc2[mi * 8 + ni][1]);
            *reinterpret_cast<float2*>(p0 + 8 * HW) =
                make_float2(acc2[mi * 8 + ni][2], acc2[mi * 8 + ni][3]);
        }
    }
}

// ---------------------------------------------------------------------------
// Kernel 3: BN stats — bandwidth-bound (grid 1024 ch x 8 b-slices).
// ---------------------------------------------------------------------------
__global__ void __launch_bounds__(256) stats_kernel() {
    const int ch = blockIdx.x;
    const int bs = blockIdx.y;
    const int t  = threadIdx.x;
    const int lane = t & 31;
    const int wid  = t >> 5;

    float p1[4], p2[4];
#pragma unroll
    for (int bb = 0; bb < 4; bb++) {
        const float4 v = reinterpret_cast<const float4*>(g_bconv)
                         [((size_t)((bs * 4 + bb) * 1024 + ch)) * 256 + t];
        p1[bb] = (v.x + v.y) + (v.z + v.w);
        p2[bb] = (v.x * v.x + v.y * v.y) + (v.z * v.z + v.w * v.w);
    }
    float s1 = (p1[0] + p1[1]) + (p1[2] + p1[3]);
    float s2 = (p2[0] + p2[1]) + (p2[2] + p2[3]);

#pragma unroll
    for (int o = 16; o > 0; o >>= 1) {
        s1 += __shfl_xor_sync(0xFFFFFFFFu, s1, o);
        s2 += __shfl_xor_sync(0xFFFFFFFFu, s2, o);
    }
    __shared__ float r1[8], r2[8];
    if (lane == 0) { r1[wid] = s1; r2[wid] = s2; }
    __syncthreads();
    if (t == 0) {
        float t1 = 0.f, t2 = 0.f;
#pragma unroll
        for (int i = 0; i < 8; i++) { t1 += r1[i]; t2 += r2[i]; }
        atomicAdd(&g_sum[ch],   (double)t1);
        atomicAdd(&g_sumsq[ch], (double)t2);
    }
}

// ---------------------------------------------------------------------------
// Kernel 4: finalize per-channel BN affine in fp64.
// ---------------------------------------------------------------------------
__global__ void finalize_kernel(const float* __restrict__ gamma,
                                const float* __restrict__ beta) {
    const int ch = blockIdx.x * 256 + threadIdx.x;
    if (ch >= NCH) return;
    const int co = ch & (NCOUT - 1);
    const double N = (double)NB * (double)HW;
    const double mean_b = g_sum[ch] / N;
    const double var_b  = g_sumsq[ch] / N - mean_b * mean_b;
    const double a      = (double)g_alpha[co];
    const double inv    = rsqrt(a * a * var_b + 1e-5) * (double)gamma[ch];
    g_cA[ch] = (float)(a * inv);
    g_cB[ch] = (float)((double)beta[ch] - a * mean_b * inv);
}

// ---------------------------------------------------------------------------
// Kernel 5: sign + group merge + qrelu quantization.
// ---------------------------------------------------------------------------
__global__ void merge_kernel(float* __restrict__ out) {
    const size_t i   = (size_t)blockIdx.x * 256 + threadIdx.x;
    const size_t px4 = i & 255;
    const size_t bc  = i >> 8;
    const size_t co  = bc & (NCOUT - 1);
    const size_t b   = bc >> 8;

    int y0 = 0, y1 = 0, y2 = 0, y3 = 0;
#pragma unroll
    for (int g = 0; g < NG; g++) {
        const size_t idx = (((b * NG + g) * NCOUT + co) * (HW / 4)) + px4;
        const float4 v = reinterpret_cast<const float4*>(g_bconv)[idx];
        const int ch = g * NCOUT + (int)co;
        const float cA = g_cA[ch];
        const float cB = g_cB[ch];
        y0 += (fmaf(v.x, cA, cB) >= 0.0f) ? 1 : -1;
        y1 += (fmaf(v.y, cA, cB) >= 0.0f) ? 1 : -1;
        y2 += (fmaf(v.z, cA, cB) >= 0.0f) ? 1 : -1;
        y3 += (fmaf(v.w, cA, cB) >= 0.0f) ? 1 : -1;
    }
    const float QMID = (8.0f / 15.0f) * 4.0f;
    float4 o;
    o.x = (y0 >= 4) ? 4.0f : ((y0 >= 2) ? QMID : 0.0f);
    o.y = (y1 >= 4) ? 4.0f : ((y1 >= 2) ? QMID : 0.0f);
    o.z = (y2 >= 4) ? 4.0f : ((y2 >= 2) ? QMID : 0.0f);
    o.w = (y3 >= 4) ? 4.0f : ((y3 >= 2) ? QMID : 0.0f);
    reinterpret_cast<float4*>(out)[i] = o;
}

// ---------------------------------------------------------------------------
extern "C" void kernel_launch(void* const* d_in, const int* in_sizes, int n_in,
                              void* d_out, int out_size) {
    (void)in_sizes; (void)n_in; (void)out_size;
    const float* x     = (const float*)d_in[0];
    const float* w     = (const float*)d_in[1];
    const float* gamma = (const float*)d_in[2];
    const float* beta  = (const float*)d_in[3];
    float* out = (float*)d_out;

    // Host-side attribute set (idempotent, no device work, capture-safe)
    cudaFuncSetAttribute(conv_mma_kernel,
                         cudaFuncAttributeMaxDynamicSharedMemorySize, SM_TOT);

    prep_w_kernel<<<256, 256>>>(w);
    prep_x_kernel<<<dim3(HPAD, NIMG), 256>>>(x);
    conv_mma_kernel<<<dim3(16, NG, NB), 256, SM_TOT>>>();
    stats_kernel<<<dim3(NCH, 8), 256>>>();
    finalize_kernel<<<4, 256>>>(gamma, beta);
    merge_kernel<<<(NB * NCOUT * HW / 4) / 256, 256>>>(out);
}

// round 11
// speedup vs baseline: 5.3570x; 1.2659x over previous
#include <cuda_runtime.h>
#include <cuda_fp16.h>
#include <cstdint>

// Problem constants
#define NB    32
#define NG    4
#define NCOUT 256     // output channels per group
#define CING  64      // input channels per group
#define NCH   1024
#define HW    1024
#define NIMG  128     // NB*NG
#define HPAD  34      // padded rows (hp = 0..33 <-> xh = hp-1)
#define WROW  2176    // 34 wp * 64 ch halves per padded row (gmem)
#define IMGSZ2 (HPAD * WROW)  // 73984 halves per image per split
#define SROW  72      // A smem row stride in halves (64 + 8 pad)
#define CHS   72      // B smem per-pixel stride in halves (64 + 8 pad)
#define BROW  (34 * CHS)      // 2448 halves per image row in smem
#define BSPL  (6 * BROW)      // 14688 halves per split (6 halo rows)

// Dynamic smem layout (bytes)
#define SM_B    0                     // bigB: 2 * 14688 halves = 58752 B
#define SM_A    58752                 // 9 A tiles, 18432 B each = 165888 B
#define A_TILE  18432
#define SM_TOT  224640                // 219.4 KB <= 227 KB cap

// Device scratch (no allocations allowed)
__device__ float  g_alpha[NCOUT];
__device__ __align__(16) __half g_A[NG * 9 * NCOUT * CING];         // [g][tap][co][ch], +-1
__device__ __align__(16) __half g_xs[(size_t)2 * NIMG * IMGSZ2];    // [split][img][hp][wp][ch]
__device__ float  g_bconv[(size_t)NB * NCH * HW];                   // 134 MB
__device__ double g_sum[NCH];
__device__ double g_sumsq[NCH];
__device__ float  g_cA[NCH];
__device__ float  g_cB[NCH];

__device__ __forceinline__ uint32_t smem_u32(const void* p) {
    uint32_t a;
    asm("{ .reg .u64 t; cvta.to.shared.u64 t, %1; cvt.u32.u64 %0, t; }" : "=r"(a) : "l"(p));
    return a;
}
__device__ __forceinline__ void ldsm_x4(uint32_t& r0, uint32_t& r1, uint32_t& r2, uint32_t& r3,
                                        uint32_t addr) {
    asm volatile("ldmatrix.sync.aligned.m8n8.x4.shared.b16 {%0,%1,%2,%3}, [%4];"
                 : "=r"(r0), "=r"(r1), "=r"(r2), "=r"(r3) : "r"(addr));
}
// accumulate: D = A*B + D
__device__ __forceinline__ void mma16816(float& c0, float& c1, float& c2, float& c3,
                                         uint32_t a0, uint32_t a1, uint32_t a2, uint32_t a3,
                                         uint32_t b0, uint32_t b1) {
    asm volatile(
        "mma.sync.aligned.m16n8k16.row.col.f32.f16.f16.f32 "
        "{%0,%1,%2,%3}, {%4,%5,%6,%7}, {%8,%9}, {%0,%1,%2,%3};"
        : "+f"(c0), "+f"(c1), "+f"(c2), "+f"(c3)
        : "r"(a0), "r"(a1), "r"(a2), "r"(a3), "r"(b0), "r"(b1));
}
// overwrite: D = A*B + 0
__device__ __forceinline__ void mma16816_z(float& c0, float& c1, float& c2, float& c3,
                                           uint32_t a0, uint32_t a1, uint32_t a2, uint32_t a3,
                                           uint32_t b0, uint32_t b1) {
    asm volatile(
        "mma.sync.aligned.m16n8k16.row.col.f32.f16.f16.f32 "
        "{%0,%1,%2,%3}, {%4,%5,%6,%7}, {%8,%9}, {%10,%10,%10,%10};"
        : "=f"(c0), "=f"(c1), "=f"(c2), "=f"(c3)
        : "r"(a0), "r"(a1), "r"(a2), "r"(a3), "r"(b0), "r"(b1), "f"(0.0f));
}

// ---------------------------------------------------------------------------
// Kernel 0: alpha = mean|w|; sign tiles A[g][tap][co][ch] fp16; zero stats.
// ---------------------------------------------------------------------------
__global__ void prep_w_kernel(const float* __restrict__ w) {
    const int co = blockIdx.x;
    const int t  = threadIdx.x;
    const float* wc = w + (size_t)co * 256 * 9;

    if (t < 4) {
        g_sum[co * 4 + t]   = 0.0;
        g_sumsq[co * 4 + t] = 0.0;
    }

    float s = 0.0f;
    for (int i = t; i < 256 * 9; i += 256) s += fabsf(wc[i]);
    __shared__ float red[256];
    red[t] = s;
    __syncthreads();
    for (int o = 128; o > 0; o >>= 1) {
        if (t < o) red[t] += red[t + o];
        __syncthreads();
    }
    if (t == 0) g_alpha[co] = red[0] / 2304.0f;

    for (int i = t; i < 256 * 9; i += 256) {
        int ci = i / 9, tap = i - ci * 9;
        int g = ci >> 6, ch = ci & 63;
        __half v = (wc[i] >= 0.0f) ? __float2half_rn(1.0f) : __float2half_rn(-1.0f);
        g_A[((size_t)(g * 9 + tap) * NCOUT + co) * CING + ch] = v;
    }
}

// ---------------------------------------------------------------------------
// Kernel 1: build hi/lo split copies with padded w (wp = w+1, zeros at 0/33).
// g_xs[split][img][hp][wp][ch] = split(x[b, g*64+ch, hp-1, wp-1])
// grid (34, 128), 256 threads.
// ---------------------------------------------------------------------------
__global__ void prep_x_kernel(const float* __restrict__ x) {
    const int hp  = blockIdx.x;
    const int img = blockIdx.y;
    const int g   = img & 3;
    const int b   = img >> 2;
    const int t   = threadIdx.x;
    const int xh  = hp - 1;
    const bool hin = (xh >= 0) && (xh < 32);

    __shared__ float sx[CING * 32];   // [ch][w]
    if (hin) {
        const float4* src = reinterpret_cast<const float4*>(x) +
                            ((size_t)(b * 256 + g * 64) * 1024 + (size_t)xh * 32) / 4;
        for (int i = t; i < 512; i += 256) {
            int ch = i >> 3, j = i & 7;
            reinterpret_cast<float4*>(sx)[ch * 8 + j] = src[(size_t)ch * 256 + j];
        }
    } else {
        for (int i = t; i < CING * 32 / 4; i += 256)
            reinterpret_cast<float4*>(sx)[i] = make_float4(0.f, 0.f, 0.f, 0.f);
    }
    __syncthreads();

    for (int i = t; i < 2 * 34 * 32; i += 256) {
        int split = (i >= 1088) ? 1 : 0;
        int r  = i - split * 1088;
        int wp = r >> 5;
        int c2 = (r & 31) * 2;
        int xw = wp - 1;
        float v0 = 0.f, v1 = 0.f;
        if (hin && xw >= 0 && xw < 32) {
            v0 = sx[c2 * 32 + xw];
            v1 = sx[(c2 + 1) * 32 + xw];
        }
        __half h0, h1;
        if (split == 0) {
            h0 = __float2half_rn(v0);
            h1 = __float2half_rn(v1);
        } else {
            h0 = __float2half_rn(v0 - __half2float(__float2half_rn(v0)));
            h1 = __float2half_rn(v1 - __half2float(__float2half_rn(v1)));
        }
        size_t off = ((size_t)split * NIMG + img) * IMGSZ2 + (size_t)hp * WROW + wp * 64 + c2;
        *reinterpret_cast<__half2*>(&g_xs[off]) = __halves2half2(h0, h1);
    }
}

// ---------------------------------------------------------------------------
// Kernel 2: HMMA implicit GEMM, everything staged ONCE (B halo + all 9 A
// tiles, 219.4 KB smem, 1 CTA/SM), zero mainloop syncs, per-tap
// sub-accumulator flush, BN stats fused into the epilogue.
// CTA = (cohalf | ptile) x g x b. M=128 co, N=128 px (4 image rows).
// ---------------------------------------------------------------------------
__global__ void __launch_bounds__(256) conv_mma_kernel() {
    extern __shared__ char smem[];
    __half* bigB = reinterpret_cast<__half*>(smem + SM_B);

    const int t      = threadIdx.x;
    const int wid    = t >> 5;
    const int lane   = t & 31;
    const int cohalf = blockIdx.x & 1;
    const int ptile  = blockIdx.x >> 1;    // 0..7 (4 image rows each)
    const int g      = blockIdx.y;
    const int b      = blockIdx.z;
    const int img    = b * 4 + g;
    const int px0    = ptile * 128;

    const int wm = (wid >> 1) * 32;        // warp M offset (co)
    const int wn = (wid & 1) * 64;         // warp N offset (px)

    const uint32_t sB  = smem_u32(bigB);
    const uint32_t sA  = smem_u32(smem + SM_A);

    const int aRow = lane & 15;
    const int aCol = (lane >> 4) * 8;
    const int bRow = (lane & 7) + ((lane >> 4) & 1) * 8;
    const int bCol = ((lane >> 3) & 1) * 8;

    // Stage bigB once: [split][row 0..5][wp 0..33][ch] stride CHS=72
    for (int i = t; i < 3264; i += 256) {       // 2*6*34*8 float4
        int split = (i >= 1632) ? 1 : 0;
        int rem = i - split * 1632;
        int row = rem / 272;
        int r2  = rem - row * 272;
        int wp  = r2 >> 3;
        int j   = r2 & 7;
        const float4 v = *reinterpret_cast<const float4*>(
            g_xs + ((size_t)split * NIMG + img) * IMGSZ2
                 + (size_t)(ptile * 4 + row) * WROW + wp * 64 + j * 8);
        *reinterpret_cast<float4*>(
            bigB + split * BSPL + row * BROW + wp * CHS + j * 8) = v;
    }
    // Stage ALL 9 A tiles once: tile tap at SM_A + tap*A_TILE, row stride 72
    {
        __half* dstA = reinterpret_cast<__half*>(smem + SM_A);
        const float4* srcA = reinterpret_cast<const float4*>(
            g_A + ((size_t)(g * 9) * NCOUT + cohalf * 128) * CING);
        // gmem per tap: contiguous 128*64 halves = 1024 float4; tap stride = 256*64/8
        for (int i = t; i < 9216; i += 256) {
            int tap = i >> 10;
            int rem = i & 1023;
            int row = rem >> 3, j = rem & 7;
            float4 v = srcA[(size_t)tap * (NCOUT * CING / 8) + rem];
            *reinterpret_cast<float4*>(
                dstA + tap * (A_TILE / 2) + row * SROW + j * 8) = v;
        }
    }
    __syncthreads();   // the ONLY pre-epilogue sync

    float acc[16][4];    // per-tap sub-accumulator
    float acc2[16][4];   // cross-tap accumulator
#pragma unroll
    for (int i = 0; i < 16; i++)
#pragma unroll
        for (int j = 0; j < 4; j++) acc2[i][j] = 0.0f;

    const int pxb = wn + bRow;

    for (int tap = 0; tap < 9; tap++) {
        const int di = tap / 3, dj = tap - di * 3;
        const uint32_t sAcur = sA + tap * A_TILE;

#pragma unroll
        for (int split = 0; split < 2; split++) {
#pragma unroll
            for (int k = 0; k < 4; k++) {
                uint32_t a0[4], a1[4];
                ldsm_x4(a0[0], a0[1], a0[2], a0[3],
                        sAcur + ((wm + 0  + aRow) * SROW + k * 16 + aCol) * 2);
                ldsm_x4(a1[0], a1[1], a1[2], a1[3],
                        sAcur + ((wm + 16 + aRow) * SROW + k * 16 + aCol) * 2);
#pragma unroll
                for (int nb = 0; nb < 4; nb++) {
                    const int px = pxb + nb * 16;
                    const int h  = px >> 5;
                    const int w  = px & 31;
                    uint32_t r0, r1, r2, r3;
                    ldsm_x4(r0, r1, r2, r3,
                            sB + (split * BSPL + (h + di) * BROW + (w + dj) * CHS
                                  + k * 16 + bCol) * 2);
                    if (split == 0 && k == 0) {
                        mma16816_z(acc[nb * 2][0], acc[nb * 2][1],
                                   acc[nb * 2][2], acc[nb * 2][3],
                                   a0[0], a0[1], a0[2], a0[3], r0, r1);
                        mma16816_z(acc[nb * 2 + 1][0], acc[nb * 2 + 1][1],
                                   acc[nb * 2 + 1][2], acc[nb * 2 + 1][3],
                                   a0[0], a0[1], a0[2], a0[3], r2, r3);
                        mma16816_z(acc[8 + nb * 2][0], acc[8 + nb * 2][1],
                                   acc[8 + nb * 2][2], acc[8 + nb * 2][3],
                                   a1[0], a1[1], a1[2], a1[3], r0, r1);
                        mma16816_z(acc[8 + nb * 2 + 1][0], acc[8 + nb * 2 + 1][1],
                                   acc[8 + nb * 2 + 1][2], acc[8 + nb * 2 + 1][3],
                                   a1[0], a1[1], a1[2], a1[3], r2, r3);
                    } else {
                        mma16816(acc[nb * 2][0], acc[nb * 2][1],
                                 acc[nb * 2][2], acc[nb * 2][3],
                                 a0[0], a0[1], a0[2], a0[3], r0, r1);
                        mma16816(acc[nb * 2 + 1][0], acc[nb * 2 + 1][1],
                                 acc[nb * 2 + 1][2], acc[nb * 2 + 1][3],
                                 a0[0], a0[1], a0[2], a0[3], r2, r3);
                        mma16816(acc[8 + nb * 2][0], acc[8 + nb * 2][1],
                                 acc[8 + nb * 2][2], acc[8 + nb * 2][3],
                                 a1[0], a1[1], a1[2], a1[3], r0, r1);
                        mma16816(acc[8 + nb * 2 + 1][0], acc[8 + nb * 2 + 1][1],
                                 acc[8 + nb * 2 + 1][2], acc[8 + nb * 2 + 1][3],
                                 a1[0], a1[1], a1[2], a1[3], r2, r3);
                    }
                }
            }
        }
        // flush tap sub-accumulator into cross-tap bank
#pragma unroll
        for (int i = 0; i < 16; i++)
#pragma unroll
            for (int j = 0; j < 4; j++) acc2[i][j] += acc[i][j];
    }

    // --- Epilogue 1: bconv stores (full 32B sectors) ---
    const int coBase = cohalf * 128 + wm;
#pragma unroll
    for (int mi = 0; mi < 2; mi++) {
#pragma unroll
        for (int ni = 0; ni < 8; ni++) {
            const int co_r = coBase + mi * 16 + (lane >> 2);
            const int px_c = px0 + wn + ni * 8 + (lane & 3) * 2;
            float* p0 = &g_bconv[((size_t)img * NCOUT + co_r) * HW + px_c];
            *reinterpret_cast<float2*>(p0) =
                make_float2(acc2[mi * 8 + ni][0], acc2[mi * 8 + ni][1]);
            *reinterpret_cast<float2*>(p0 + 8 * HW) =
                make_float2(acc2[mi * 8 + ni][2], acc2[mi * 8 + ni][3]);
        }
    }

    // --- Epilogue 2: fused BN stats ---
    // per-thread partials: q = mi*2 + half; half 0 -> j 0/1 (co rowBase),
    // half 1 -> j 2/3 (co rowBase+8). 16 px per (thread, q).
    float st1[4], st2[4];
#pragma unroll
    for (int mi = 0; mi < 2; mi++) {
#pragma unroll
        for (int half = 0; half < 2; half++) {
            float s1 = 0.f, s2 = 0.f;
#pragma unroll
            for (int ni = 0; ni < 8; ni++) {
                const float a = acc2[mi * 8 + ni][half * 2 + 0];
                const float c = acc2[mi * 8 + ni][half * 2 + 1];
                s1 += a + c;
                s2 += a * a + c * c;
            }
            st1[mi * 2 + half] = s1;
            st2[mi * 2 + half] = s2;
        }
    }
    // reduce over the 4-lane group sharing the same co (lane ^ 1, lane ^ 2)
#pragma unroll
    for (int q = 0; q < 4; q++) {
#pragma unroll
        for (int o = 1; o <= 2; o <<= 1) {
            st1[q] += __shfl_xor_sync(0xFFFFFFFFu, st1[q], o);
            st2[q] += __shfl_xor_sync(0xFFFFFFFFu, st2[q], o);
        }
    }
    __syncthreads();   // all smem reads (ldsm) done; safe to reuse bigB space
    float* sbuf = reinterpret_cast<float*>(smem);   // [128 co][2 nwarp][2]
    if ((lane & 3) == 0) {
#pragma unroll
        for (int q = 0; q < 4; q++) {
            const int mi = q >> 1, half = q & 1;
            const int co_l = wm + mi * 16 + half * 8 + (lane >> 2);
            sbuf[(co_l * 2 + (wid & 1)) * 2 + 0] = st1[q];
            sbuf[(co_l * 2 + (wid & 1)) * 2 + 1] = st2[q];
        }
    }
    __syncthreads();
    if (t < 128) {
        const float s1 = sbuf[(t * 2 + 0) * 2 + 0] + sbuf[(t * 2 + 1) * 2 + 0];
        const float s2 = sbuf[(t * 2 + 0) * 2 + 1] + sbuf[(t * 2 + 1) * 2 + 1];
        const int ch = g * NCOUT + cohalf * 128 + t;
        atomicAdd(&g_sum[ch],   (double)s1);
        atomicAdd(&g_sumsq[ch], (double)s2);
    }
}

// ---------------------------------------------------------------------------
// Kernel 3: finalize per-channel BN affine in fp64.
// ---------------------------------------------------------------------------
__global__ void finalize_kernel(const float* __restrict__ gamma,
                                const float* __restrict__ beta) {
    const int ch = blockIdx.x * 256 + threadIdx.x;
    if (ch >= NCH) return;
    const int co = ch & (NCOUT - 1);
    const double N = (double)NB * (double)HW;
    const double mean_b = g_sum[ch] / N;
    const double var_b  = g_sumsq[ch] / N - mean_b * mean_b;
    const double a      = (double)g_alpha[co];
    const double inv    = rsqrt(a * a * var_b + 1e-5) * (double)gamma[ch];
    g_cA[ch] = (float)(a * inv);
    g_cB[ch] = (float)((double)beta[ch] - a * mean_b * inv);
}

// ---------------------------------------------------------------------------
// Kernel 4: sign + group merge + qrelu quantization.
// ---------------------------------------------------------------------------
__global__ void merge_kernel(float* __restrict__ out) {
    const size_t i   = (size_t)blockIdx.x * 256 + threadIdx.x;
    const size_t px4 = i & 255;
    const size_t bc  = i >> 8;
    const size_t co  = bc & (NCOUT - 1);
    const size_t b   = bc >> 8;

    int y0 = 0, y1 = 0, y2 = 0, y3 = 0;
#pragma unroll
    for (int g = 0; g < NG; g++) {
        const size_t idx = (((b * NG + g) * NCOUT + co) * (HW / 4)) + px4;
        const float4 v = reinterpret_cast<const float4*>(g_bconv)[idx];
        const int ch = g * NCOUT + (int)co;
        const float cA = g_cA[ch];
        const float cB = g_cB[ch];
        y0 += (fmaf(v.x, cA, cB) >= 0.0f) ? 1 : -1;
        y1 += (fmaf(v.y, cA, cB) >= 0.0f) ? 1 : -1;
        y2 += (fmaf(v.z, cA, cB) >= 0.0f) ? 1 : -1;
        y3 += (fmaf(v.w, cA, cB) >= 0.0f) ? 1 : -1;
    }
    const float QMID = (8.0f / 15.0f) * 4.0f;
    float4 o;
    o.x = (y0 >= 4) ? 4.0f : ((y0 >= 2) ? QMID : 0.0f);
    o.y = (y1 >= 4) ? 4.0f : ((y1 >= 2) ? QMID : 0.0f);
    o.z = (y2 >= 4) ? 4.0f : ((y2 >= 2) ? QMID : 0.0f);
    o.w = (y3 >= 4) ? 4.0f : ((y3 >= 2) ? QMID : 0.0f);
    reinterpret_cast<float4*>(out)[i] = o;
}

// ---------------------------------------------------------------------------
extern "C" void kernel_launch(void* const* d_in, const int* in_sizes, int n_in,
                              void* d_out, int out_size) {
    (void)in_sizes; (void)n_in; (void)out_size;
    const float* x     = (const float*)d_in[0];
    const float* w     = (const float*)d_in[1];
    const float* gamma = (const float*)d_in[2];
    const float* beta  = (const float*)d_in[3];
    float* out = (float*)d_out;

    // Host-side attribute set (idempotent, capture-safe, no device work)
    cudaFuncSetAttribute(conv_mma_kernel,
                         cudaFuncAttributeMaxDynamicSharedMemorySize, SM_TOT);

    prep_w_kernel<<<256, 256>>>(w);
    prep_x_kernel<<<dim3(HPAD, NIMG), 256>>>(x);
    conv_mma_kernel<<<dim3(16, NG, NB), 256, SM_TOT>>>();
    finalize_kernel<<<4, 256>>>(gamma, beta);
    merge_kernel<<<(NB * NCOUT * HW / 4) / 256, 256>>>(out);
}

// round 12
// speedup vs baseline: 5.3846x; 1.0051x over previous
#include <cuda_runtime.h>
#include <cuda_fp16.h>
#include <cstdint>

// Problem constants
#define NB    32
#define NG    4
#define NCOUT 256     // output channels per group
#define CING  64      // input channels per group
#define NCH   1024
#define HW    1024
#define NIMG  128     // NB*NG
#define HPAD  34      // padded rows (hp = 0..33 <-> xh = hp-1)
#define WROW  2176    // 34 wp * 64 ch halves per padded row (gmem)
#define IMGSZ2 (HPAD * WROW)  // 73984 halves per image per split
#define SROW  72      // A smem row stride in halves (64 + 8 pad)
#define CHS   72      // B smem per-pixel stride in halves (64 + 8 pad)
#define BROW  (34 * CHS)      // 2448 halves per image row in smem
#define BSPL  (6 * BROW)      // 14688 halves per split (6 halo rows)

// Dynamic smem layout (bytes)
#define SM_B    0                     // bigB: 2 * 14688 halves = 58752 B
#define SM_A    58752                 // 9 A tiles, 18432 B each = 165888 B
#define A_TILE  18432
#define SM_TOT  224640                // 219.4 KB <= 227 KB cap

// Device scratch (no allocations allowed)
__device__ float  g_alpha[NCOUT];
__device__ __align__(16) __half g_A[NG * 9 * NCOUT * CING];         // [g][tap][co][ch], +-1
__device__ __align__(16) __half g_xs[(size_t)2 * NIMG * IMGSZ2];    // [split][img][hp][wp][ch]
__device__ float  g_bconv[(size_t)NB * NCH * HW];                   // 134 MB
__device__ double g_sum[NCH];
__device__ double g_sumsq[NCH];

__device__ __forceinline__ uint32_t smem_u32(const void* p) {
    uint32_t a;
    asm("{ .reg .u64 t; cvta.to.shared.u64 t, %1; cvt.u32.u64 %0, t; }" : "=r"(a) : "l"(p));
    return a;
}
__device__ __forceinline__ void ldsm_x4(uint32_t& r0, uint32_t& r1, uint32_t& r2, uint32_t& r3,
                                        uint32_t addr) {
    asm volatile("ldmatrix.sync.aligned.m8n8.x4.shared.b16 {%0,%1,%2,%3}, [%4];"
                 : "=r"(r0), "=r"(r1), "=r"(r2), "=r"(r3) : "r"(addr));
}
// accumulate: D = A*B + D
__device__ __forceinline__ void mma16816(float& c0, float& c1, float& c2, float& c3,
                                         uint32_t a0, uint32_t a1, uint32_t a2, uint32_t a3,
                                         uint32_t b0, uint32_t b1) {
    asm volatile(
        "mma.sync.aligned.m16n8k16.row.col.f32.f16.f16.f32 "
        "{%0,%1,%2,%3}, {%4,%5,%6,%7}, {%8,%9}, {%0,%1,%2,%3};"
        : "+f"(c0), "+f"(c1), "+f"(c2), "+f"(c3)
        : "r"(a0), "r"(a1), "r"(a2), "r"(a3), "r"(b0), "r"(b1));
}
// overwrite: D = A*B + 0
__device__ __forceinline__ void mma16816_z(float& c0, float& c1, float& c2, float& c3,
                                           uint32_t a0, uint32_t a1, uint32_t a2, uint32_t a3,
                                           uint32_t b0, uint32_t b1) {
    asm volatile(
        "mma.sync.aligned.m16n8k16.row.col.f32.f16.f16.f32 "
        "{%0,%1,%2,%3}, {%4,%5,%6,%7}, {%8,%9}, {%10,%10,%10,%10};"
        : "=f"(c0), "=f"(c1), "=f"(c2), "=f"(c3)
        : "r"(a0), "r"(a1), "r"(a2), "r"(a3), "r"(b0), "r"(b1), "f"(0.0f));
}

// ---------------------------------------------------------------------------
// Kernel 0: alpha = mean|w|; sign tiles A[g][tap][co][ch] fp16; zero stats.
// ---------------------------------------------------------------------------
__global__ void prep_w_kernel(const float* __restrict__ w) {
    const int co = blockIdx.x;
    const int t  = threadIdx.x;
    const float* wc = w + (size_t)co * 256 * 9;

    if (t < 4) {
        g_sum[co * 4 + t]   = 0.0;
        g_sumsq[co * 4 + t] = 0.0;
    }

    float s = 0.0f;
    for (int i = t; i < 256 * 9; i += 256) s += fabsf(wc[i]);
    __shared__ float red[256];
    red[t] = s;
    __syncthreads();
    for (int o = 128; o > 0; o >>= 1) {
        if (t < o) red[t] += red[t + o];
        __syncthreads();
    }
    if (t == 0) g_alpha[co] = red[0] / 2304.0f;

    for (int i = t; i < 256 * 9; i += 256) {
        int ci = i / 9, tap = i - ci * 9;
        int g = ci >> 6, ch = ci & 63;
        __half v = (wc[i] >= 0.0f) ? __float2half_rn(1.0f) : __float2half_rn(-1.0f);
        g_A[((size_t)(g * 9 + tap) * NCOUT + co) * CING + ch] = v;
    }
}

// ---------------------------------------------------------------------------
// Kernel 1: build hi/lo split copies with padded w (wp = w+1, zeros at 0/33).
// g_xs[split][img][hp][wp][ch] = split(x[b, g*64+ch, hp-1, wp-1])
// grid (34, 128), 256 threads.
// ---------------------------------------------------------------------------
__global__ void prep_x_kernel(const float* __restrict__ x) {
    const int hp  = blockIdx.x;
    const int img = blockIdx.y;
    const int g   = img & 3;
    const int b   = img >> 2;
    const int t   = threadIdx.x;
    const int xh  = hp - 1;
    const bool hin = (xh >= 0) && (xh < 32);

    __shared__ float sx[CING * 32];   // [ch][w]
    if (hin) {
        const float4* src = reinterpret_cast<const float4*>(x) +
                            ((size_t)(b * 256 + g * 64) * 1024 + (size_t)xh * 32) / 4;
        for (int i = t; i < 512; i += 256) {
            int ch = i >> 3, j = i & 7;
            reinterpret_cast<float4*>(sx)[ch * 8 + j] = src[(size_t)ch * 256 + j];
        }
    } else {
        for (int i = t; i < CING * 32 / 4; i += 256)
            reinterpret_cast<float4*>(sx)[i] = make_float4(0.f, 0.f, 0.f, 0.f);
    }
    __syncthreads();

    for (int i = t; i < 2 * 34 * 32; i += 256) {
        int split = (i >= 1088) ? 1 : 0;
        int r  = i - split * 1088;
        int wp = r >> 5;
        int c2 = (r & 31) * 2;
        int xw = wp - 1;
        float v0 = 0.f, v1 = 0.f;
        if (hin && xw >= 0 && xw < 32) {
            v0 = sx[c2 * 32 + xw];
            v1 = sx[(c2 + 1) * 32 + xw];
        }
        __half h0, h1;
        if (split == 0) {
            h0 = __float2half_rn(v0);
            h1 = __float2half_rn(v1);
        } else {
            h0 = __float2half_rn(v0 - __half2float(__float2half_rn(v0)));
            h1 = __float2half_rn(v1 - __half2float(__float2half_rn(v1)));
        }
        size_t off = ((size_t)split * NIMG + img) * IMGSZ2 + (size_t)hp * WROW + wp * 64 + c2;
        *reinterpret_cast<__half2*>(&g_xs[off]) = __halves2half2(h0, h1);
    }
}

// ---------------------------------------------------------------------------
// Kernel 2: HMMA implicit GEMM, everything staged ONCE (B halo + all 9 A
// tiles, 219.4 KB smem, 1 CTA/SM), zero mainloop syncs, per-tap
// sub-accumulator flush, BN stats fused into the epilogue.
// A fragments hoisted out of the split loop (A identical for hi/lo);
// fully unrolled tap loop -> constant-folded smem addressing.
// CTA = (cohalf | ptile) x g x b. M=128 co, N=128 px (4 image rows).
// ---------------------------------------------------------------------------
__global__ void __launch_bounds__(256) conv_mma_kernel() {
    extern __shared__ char smem[];
    __half* bigB = reinterpret_cast<__half*>(smem + SM_B);

    const int t      = threadIdx.x;
    const int wid    = t >> 5;
    const int lane   = t & 31;
    const int cohalf = blockIdx.x & 1;
    const int ptile  = blockIdx.x >> 1;    // 0..7 (4 image rows each)
    const int g      = blockIdx.y;
    const int b      = blockIdx.z;
    const int img    = b * 4 + g;
    const int px0    = ptile * 128;

    const int wm = (wid >> 1) * 32;        // warp M offset (co)
    const int wn = (wid & 1) * 64;         // warp N offset (px)

    const uint32_t sB  = smem_u32(bigB);
    const uint32_t sA  = smem_u32(smem + SM_A);

    const int aRow = lane & 15;
    const int aCol = (lane >> 4) * 8;
    const int bRow = (lane & 7) + ((lane >> 4) & 1) * 8;
    const int bCol = ((lane >> 3) & 1) * 8;

    // Stage bigB once: [split][row 0..5][wp 0..33][ch] stride CHS=72
    for (int i = t; i < 3264; i += 256) {       // 2*6*34*8 float4
        int split = (i >= 1632) ? 1 : 0;
        int rem = i - split * 1632;
        int row = rem / 272;
        int r2  = rem - row * 272;
        int wp  = r2 >> 3;
        int j   = r2 & 7;
        const float4 v = *reinterpret_cast<const float4*>(
            g_xs + ((size_t)split * NIMG + img) * IMGSZ2
                 + (size_t)(ptile * 4 + row) * WROW + wp * 64 + j * 8);
        *reinterpret_cast<float4*>(
            bigB + split * BSPL + row * BROW + wp * CHS + j * 8) = v;
    }
    // Stage ALL 9 A tiles once: tile tap at SM_A + tap*A_TILE, row stride 72
    {
        __half* dstA = reinterpret_cast<__half*>(smem + SM_A);
        const float4* srcA = reinterpret_cast<const float4*>(
            g_A + ((size_t)(g * 9) * NCOUT + cohalf * 128) * CING);
        for (int i = t; i < 9216; i += 256) {
            int tap = i >> 10;
            int rem = i & 1023;
            int row = rem >> 3, j = rem & 7;
            float4 v = srcA[(size_t)tap * (NCOUT * CING / 8) + rem];
            *reinterpret_cast<float4*>(
                dstA + tap * (A_TILE / 2) + row * SROW + j * 8) = v;
        }
    }
    __syncthreads();   // the ONLY pre-epilogue sync

    float acc[16][4];    // per-tap sub-accumulator
    float acc2[16][4];   // cross-tap accumulator
#pragma unroll
    for (int i = 0; i < 16; i++)
#pragma unroll
        for (int j = 0; j < 4; j++) acc2[i][j] = 0.0f;

    const int pxb = wn + bRow;
    const uint32_t aAddrBase0 = sA + ((wm + 0  + aRow) * SROW + aCol) * 2;
    const uint32_t aAddrBase1 = sA + ((wm + 16 + aRow) * SROW + aCol) * 2;
    // per-nb B base (h,w fixed per lane & nb)
    uint32_t bBase[4];
#pragma unroll
    for (int nb = 0; nb < 4; nb++) {
        const int px = pxb + nb * 16;
        bBase[nb] = sB + (((px >> 5) * BROW) + (px & 31) * CHS + bCol) * 2;
    }

#pragma unroll
    for (int tap = 0; tap < 9; tap++) {
        const int di = tap / 3, dj = tap - di * 3;
        const uint32_t aOff = tap * A_TILE;
        const uint32_t bOff = (di * BROW + dj * CHS) * 2;

        // A fragments for all 4 k-steps (shared by both splits)
        uint32_t a0[4][4], a1[4][4];
#pragma unroll
        for (int k = 0; k < 4; k++) {
            ldsm_x4(a0[k][0], a0[k][1], a0[k][2], a0[k][3],
                    aAddrBase0 + aOff + k * 32);
            ldsm_x4(a1[k][0], a1[k][1], a1[k][2], a1[k][3],
                    aAddrBase1 + aOff + k * 32);
        }

#pragma unroll
        for (int split = 0; split < 2; split++) {
            const uint32_t bSplitOff = bOff + split * (BSPL * 2);
#pragma unroll
            for (int k = 0; k < 4; k++) {
#pragma unroll
                for (int nb = 0; nb < 4; nb++) {
                    uint32_t r0, r1, r2, r3;
                    ldsm_x4(r0, r1, r2, r3, bBase[nb] + bSplitOff + k * 32);
                    if (split == 0 && k == 0) {
                        mma16816_z(acc[nb * 2][0], acc[nb * 2][1],
                                   acc[nb * 2][2], acc[nb * 2][3],
                                   a0[k][0], a0[k][1], a0[k][2], a0[k][3], r0, r1);
                        mma16816_z(acc[nb * 2 + 1][0], acc[nb * 2 + 1][1],
                                   acc[nb * 2 + 1][2], acc[nb * 2 + 1][3],
                                   a0[k][0], a0[k][1], a0[k][2], a0[k][3], r2, r3);
                        mma16816_z(acc[8 + nb * 2][0], acc[8 + nb * 2][1],
                                   acc[8 + nb * 2][2], acc[8 + nb * 2][3],
                                   a1[k][0], a1[k][1], a1[k][2], a1[k][3], r0, r1);
                        mma16816_z(acc[8 + nb * 2 + 1][0], acc[8 + nb * 2 + 1][1],
                                   acc[8 + nb * 2 + 1][2], acc[8 + nb * 2 + 1][3],
                                   a1[k][0], a1[k][1], a1[k][2], a1[k][3], r2, r3);
                    } else {
                        mma16816(acc[nb * 2][0], acc[nb * 2][1],
                                 acc[nb * 2][2], acc[nb * 2][3],
                                 a0[k][0], a0[k][1], a0[k][2], a0[k][3], r0, r1);
                        mma16816(acc[nb * 2 + 1][0], acc[nb * 2 + 1][1],
                                 acc[nb * 2 + 1][2], acc[nb * 2 + 1][3],
                                 a0[k][0], a0[k][1], a0[k][2], a0[k][3], r2, r3);
                        mma16816(acc[8 + nb * 2][0], acc[8 + nb * 2][1],
                                 acc[8 + nb * 2][2], acc[8 + nb * 2][3],
                                 a1[k][0], a1[k][1], a1[k][2], a1[k][3], r0, r1);
                        mma16816(acc[8 + nb * 2 + 1][0], acc[8 + nb * 2 + 1][1],
                                 acc[8 + nb * 2 + 1][2], acc[8 + nb * 2 + 1][3],
                                 a1[k][0], a1[k][1], a1[k][2], a1[k][3], r2, r3);
                    }
                }
            }
        }
        // flush tap sub-accumulator into cross-tap bank
#pragma unroll
        for (int i = 0; i < 16; i++)
#pragma unroll
            for (int j = 0; j < 4; j++) acc2[i][j] += acc[i][j];
    }

    // --- Epilogue 1: bconv stores (full 32B sectors) ---
    const int coBase = cohalf * 128 + wm;
#pragma unroll
    for (int mi = 0; mi < 2; mi++) {
#pragma unroll
        for (int ni = 0; ni < 8; ni++) {
            const int co_r = coBase + mi * 16 + (lane >> 2);
            const int px_c = px0 + wn + ni * 8 + (lane & 3) * 2;
            float* p0 = &g_bconv[((size_t)img * NCOUT + co_r) * HW + px_c];
            *reinterpret_cast<float2*>(p0) =
                make_float2(acc2[mi * 8 + ni][0], acc2[mi * 8 + ni][1]);
            *reinterpret_cast<float2*>(p0 + 8 * HW) =
                make_float2(acc2[mi * 8 + ni][2], acc2[mi * 8 + ni][3]);
        }
    }

    // --- Epilogue 2: fused BN stats ---
    float st1[4], st2[4];
#pragma unroll
    for (int mi = 0; mi < 2; mi++) {
#pragma unroll
        for (int half = 0; half < 2; half++) {
            float s1 = 0.f, s2 = 0.f;
#pragma unroll
            for (int ni = 0; ni < 8; ni++) {
                const float a = acc2[mi * 8 + ni][half * 2 + 0];
                const float c = acc2[mi * 8 + ni][half * 2 + 1];
                s1 += a + c;
                s2 += a * a + c * c;
            }
            st1[mi * 2 + half] = s1;
            st2[mi * 2 + half] = s2;
        }
    }
#pragma unroll
    for (int q = 0; q < 4; q++) {
#pragma unroll
        for (int o = 1; o <= 2; o <<= 1) {
            st1[q] += __shfl_xor_sync(0xFFFFFFFFu, st1[q], o);
            st2[q] += __shfl_xor_sync(0xFFFFFFFFu, st2[q], o);
        }
    }
    __syncthreads();   // ldsm reads done; safe to reuse smem
    float* sbuf = reinterpret_cast<float*>(smem);   // [128 co][2 nwarp][2]
    if ((lane & 3) == 0) {
#pragma unroll
        for (int q = 0; q < 4; q++) {
            const int mi = q >> 1, half = q & 1;
            const int co_l = wm + mi * 16 + half * 8 + (lane >> 2);
            sbuf[(co_l * 2 + (wid & 1)) * 2 + 0] = st1[q];
            sbuf[(co_l * 2 + (wid & 1)) * 2 + 1] = st2[q];
        }
    }
    __syncthreads();
    if (t < 128) {
        const float s1 = sbuf[(t * 2 + 0) * 2 + 0] + sbuf[(t * 2 + 1) * 2 + 0];
        const float s2 = sbuf[(t * 2 + 0) * 2 + 1] + sbuf[(t * 2 + 1) * 2 + 1];
        const int ch = g * NCOUT + cohalf * 128 + t;
        atomicAdd(&g_sum[ch],   (double)s1);
        atomicAdd(&g_sumsq[ch], (double)s2);
    }
}

// ---------------------------------------------------------------------------
// Kernel 3: sign + group merge + qrelu, with BN affine finalize fused
// in-block. Each block serves one (b, co): threads 0..3 compute the 4
// channels' (cA, cB) in fp64 (identical expressions to the old finalize
// kernel -> bit-identical constants), broadcast via smem.
// ---------------------------------------------------------------------------
__global__ void merge_kernel(const float* __restrict__ gamma,
                             const float* __restrict__ beta,
                             float* __restrict__ out) {
    const int t  = threadIdx.x;
    const int bc = blockIdx.x;           // = b*256 + co
    const int co = bc & (NCOUT - 1);
    const int b  = bc >> 8;

    __shared__ float scA[4], scB[4];
    if (t < 4) {
        const int ch = t * NCOUT + co;   // g = t
        const double N = (double)NB * (double)HW;
        const double mean_b = g_sum[ch] / N;
        const double var_b  = g_sumsq[ch] / N - mean_b * mean_b;
        const double a      = (double)g_alpha[co];
        const double inv    = rsqrt(a * a * var_b + 1e-5) * (double)gamma[ch];
        scA[t] = (float)(a * inv);
        scB[t] = (float)((double)beta[ch] - a * mean_b * inv);
    }
    __syncthreads();

    const size_t px4 = t;                // 256 float4 per plane
    int y0 = 0, y1 = 0, y2 = 0, y3 = 0;
#pragma unroll
    for (int g = 0; g < NG; g++) {
        const size_t idx = ((((size_t)b * NG + g) * NCOUT + co) * (HW / 4)) + px4;
        const float4 v = reinterpret_cast<const float4*>(g_bconv)[idx];
        const float cA = scA[g];
        const float cB = scB[g];
        y0 += (fmaf(v.x, cA, cB) >= 0.0f) ? 1 : -1;
        y1 += (fmaf(v.y, cA, cB) >= 0.0f) ? 1 : -1;
        y2 += (fmaf(v.z, cA, cB) >= 0.0f) ? 1 : -1;
        y3 += (fmaf(v.w, cA, cB) >= 0.0f) ? 1 : -1;
    }
    const float QMID = (8.0f / 15.0f) * 4.0f;
    float4 o;
    o.x = (y0 >= 4) ? 4.0f : ((y0 >= 2) ? QMID : 0.0f);
    o.y = (y1 >= 4) ? 4.0f : ((y1 >= 2) ? QMID : 0.0f);
    o.z = (y2 >= 4) ? 4.0f : ((y2 >= 2) ? QMID : 0.0f);
    o.w = (y3 >= 4) ? 4.0f : ((y3 >= 2) ? QMID : 0.0f);
    reinterpret_cast<float4*>(out)[(size_t)bc * 256 + px4] = o;
}

// ---------------------------------------------------------------------------
extern "C" void kernel_launch(void* const* d_in, const int* in_sizes, int n_in,
                              void* d_out, int out_size) {
    (void)in_sizes; (void)n_in; (void)out_size;
    const float* x     = (const float*)d_in[0];
    const float* w     = (const float*)d_in[1];
    const float* gamma = (const float*)d_in[2];
    const float* beta  = (const float*)d_in[3];
    float* out = (float*)d_out;

    // Host-side attribute set (idempotent, capture-safe, no device work)
    cudaFuncSetAttribute(conv_mma_kernel,
                         cudaFuncAttributeMaxDynamicSharedMemorySize, SM_TOT);

    prep_w_kernel<<<256, 256>>>(w);
    prep_x_kernel<<<dim3(HPAD, NIMG), 256>>>(x);
    conv_mma_kernel<<<dim3(16, NG, NB), 256, SM_TOT>>>();
    merge_kernel<<<NB * NCOUT, 256>>>(gamma, beta, out);
}

// round 13
// speedup vs baseline: 7.0112x; 1.3021x over previous
#include <cuda_runtime.h>
#include <cuda_fp16.h>
#include <cstdint>

// Problem constants
#define NB    32
#define NG    4
#define NCOUT 256     // output channels per group
#define CING  64      // input channels per group
#define NCH   1024
#define HW    1024
#define SROW  72      // A smem row stride in halves (64 + 8 pad)
#define CHS   72      // B smem per-pixel stride in halves (64 + 8 pad)
#define BROW  (34 * CHS)      // 2448 halves per image row in smem
#define BSPL  (6 * BROW)      // 14688 halves per split (6 halo rows)

// Dynamic smem layout (bytes)
#define SM_B    0                     // bigB: 2 * 14688 halves = 58752 B
#define SM_A    58752                 // 9 A tiles, 18432 B each = 165888 B
#define A_TILE  18432
#define SM_TOT  224640                // 219.4 KB <= 227 KB cap

// Device scratch (no allocations allowed)
__device__ float  g_alpha[NCOUT];
__device__ __align__(16) __half g_A[NG * 9 * NCOUT * CING];   // [g][tap][co][ch], +-1
__device__ float  g_bconv[(size_t)NB * NCH * HW];             // 134 MB
__device__ double g_sum[NCH];
__device__ double g_sumsq[NCH];

__device__ __forceinline__ uint32_t smem_u32(const void* p) {
    uint32_t a;
    asm("{ .reg .u64 t; cvta.to.shared.u64 t, %1; cvt.u32.u64 %0, t; }" : "=r"(a) : "l"(p));
    return a;
}
__device__ __forceinline__ void ldsm_x4(uint32_t& r0, uint32_t& r1, uint32_t& r2, uint32_t& r3,
                                        uint32_t addr) {
    asm volatile("ldmatrix.sync.aligned.m8n8.x4.shared.b16 {%0,%1,%2,%3}, [%4];"
                 : "=r"(r0), "=r"(r1), "=r"(r2), "=r"(r3) : "r"(addr));
}
// accumulate: D = A*B + D
__device__ __forceinline__ void mma16816(float& c0, float& c1, float& c2, float& c3,
                                         uint32_t a0, uint32_t a1, uint32_t a2, uint32_t a3,
                                         uint32_t b0, uint32_t b1) {
    asm volatile(
        "mma.sync.aligned.m16n8k16.row.col.f32.f16.f16.f32 "
        "{%0,%1,%2,%3}, {%4,%5,%6,%7}, {%8,%9}, {%0,%1,%2,%3};"
        : "+f"(c0), "+f"(c1), "+f"(c2), "+f"(c3)
        : "r"(a0), "r"(a1), "r"(a2), "r"(a3), "r"(b0), "r"(b1));
}
// overwrite: D = A*B + 0
__device__ __forceinline__ void mma16816_z(float& c0, float& c1, float& c2, float& c3,
                                           uint32_t a0, uint32_t a1, uint32_t a2, uint32_t a3,
                                           uint32_t b0, uint32_t b1) {
    asm volatile(
        "mma.sync.aligned.m16n8k16.row.col.f32.f16.f16.f32 "
        "{%0,%1,%2,%3}, {%4,%5,%6,%7}, {%8,%9}, {%10,%10,%10,%10};"
        : "=f"(c0), "=f"(c1), "=f"(c2), "=f"(c3)
        : "r"(a0), "r"(a1), "r"(a2), "r"(a3), "r"(b0), "r"(b1), "f"(0.0f));
}

// ---------------------------------------------------------------------------
// Kernel 0: alpha = mean|w|; sign tiles A[g][tap][co][ch] fp16; zero stats.
// ---------------------------------------------------------------------------
__global__ void prep_w_kernel(const float* __restrict__ w) {
    const int co = blockIdx.x;
    const int t  = threadIdx.x;
    const float* wc = w + (size_t)co * 256 * 9;

    if (t < 4) {
        g_sum[co * 4 + t]   = 0.0;
        g_sumsq[co * 4 + t] = 0.0;
    }

    float s = 0.0f;
    for (int i = t; i < 256 * 9; i += 256) s += fabsf(wc[i]);
    __shared__ float red[256];
    red[t] = s;
    __syncthreads();
    for (int o = 128; o > 0; o >>= 1) {
        if (t < o) red[t] += red[t + o];
        __syncthreads();
    }
    if (t == 0) g_alpha[co] = red[0] / 2304.0f;

    for (int i = t; i < 256 * 9; i += 256) {
        int ci = i / 9, tap = i - ci * 9;
        int g = ci >> 6, ch = ci & 63;
        __half v = (wc[i] >= 0.0f) ? __float2half_rn(1.0f) : __float2half_rn(-1.0f);
        g_A[((size_t)(g * 9 + tap) * NCOUT + co) * CING + ch] = v;
    }
}

// ---------------------------------------------------------------------------
// Kernel 1: HMMA implicit GEMM. B halo staged DIRECTLY from x (fp32 ->
// hi/lo fp16 split computed in staging, identical formulas to the old
// prep_x kernel -> bit-identical bconv). All 9 A tiles resident, zero
// mainloop syncs, per-tap sub-accumulator flush, fused BN stats.
// CTA = (cohalf | ptile) x g x b. M=128 co, N=128 px (4 image rows).
// ---------------------------------------------------------------------------
__global__ void __launch_bounds__(256) conv_mma_kernel(const float* __restrict__ x) {
    extern __shared__ char smem[];
    __half* bigB = reinterpret_cast<__half*>(smem + SM_B);

    const int t      = threadIdx.x;
    const int wid    = t >> 5;
    const int lane   = t & 31;
    const int cohalf = blockIdx.x & 1;
    const int ptile  = blockIdx.x >> 1;    // 0..7 (4 image rows each)
    const int g      = blockIdx.y;
    const int b      = blockIdx.z;
    const int img    = b * 4 + g;
    const int px0    = ptile * 128;

    const int wm = (wid >> 1) * 32;        // warp M offset (co)
    const int wn = (wid & 1) * 64;         // warp N offset (px)

    const uint32_t sB  = smem_u32(bigB);
    const uint32_t sA  = smem_u32(smem + SM_A);

    const int aRow = lane & 15;
    const int aCol = (lane >> 4) * 8;
    const int bRow = (lane & 7) + ((lane >> 4) & 1) * 8;
    const int bCol = ((lane >> 3) & 1) * 8;

    // --- Stage bigB directly from x ---
    // Border columns wp=0 and wp=33: zeros (both splits, 6 rows).
    {
        const __half2 z2 = __halves2half2(__float2half_rn(0.f), __float2half_rn(0.f));
        for (int i = t; i < 768; i += 256) {        // 2 splits*6 rows*2 wp*32 chp
            int split = (i >= 384) ? 1 : 0;
            int r   = i - split * 384;
            int row = r >> 6;                        // 0..5
            int q   = r & 63;
            int wp  = (q >> 5) ? 33 : 0;
            int chp = q & 31;
            *reinterpret_cast<__half2*>(
                bigB + split * BSPL + row * BROW + wp * CHS + chp * 2) = z2;
        }
    }
    // Interior: 6 rows x 32 ch-pairs x 8 w-quads; hi split at BSPL*0, lo at BSPL*1.
    {
        const float* xb = x + ((size_t)b * 256 + (size_t)g * 64) * HW;
        for (int i = t; i < 1536; i += 256) {       // 6 iters/thread
            int row = i >> 8;                        // 0..5
            int r   = i & 255;
            int chp = r >> 3;                        // 0..31 (ch pair)
            int wq  = r & 7;                         // 0..7 (float4 within row)
            int xh  = ptile * 4 + row - 1;
            float4 va, vb;
            if (xh >= 0 && xh < 32) {
                const float4* src = reinterpret_cast<const float4*>(
                    xb + (size_t)(chp * 2) * HW + (size_t)xh * 32) + wq;
                va = src[0];
                vb = src[256];                       // ch+1: +1024 floats = +256 float4
            } else {
                va = make_float4(0.f, 0.f, 0.f, 0.f);
                vb = va;
            }
            const float av[4] = { va.x, va.y, va.z, va.w };
            const float bv[4] = { vb.x, vb.y, vb.z, vb.w };
#pragma unroll
            for (int j = 0; j < 4; j++) {
                const int wp = wq * 4 + j + 1;       // 1..32
                const __half h0 = __float2half_rn(av[j]);
                const __half h1 = __float2half_rn(bv[j]);
                const __half l0 = __float2half_rn(av[j] - __half2float(h0));
                const __half l1 = __float2half_rn(bv[j] - __half2float(h1));
                *reinterpret_cast<__half2*>(
                    bigB + row * BROW + wp * CHS + chp * 2) = __halves2half2(h0, h1);
                *reinterpret_cast<__half2*>(
                    bigB + BSPL + row * BROW + wp * CHS + chp * 2) = __halves2half2(l0, l1);
            }
        }
    }
    // Stage ALL 9 A tiles once: tile tap at SM_A + tap*A_TILE, row stride 72
    {
        __half* dstA = reinterpret_cast<__half*>(smem + SM_A);
        const float4* srcA = reinterpret_cast<const float4*>(
            g_A + ((size_t)(g * 9) * NCOUT + cohalf * 128) * CING);
        for (int i = t; i < 9216; i += 256) {
            int tap = i >> 10;
            int rem = i & 1023;
            int row = rem >> 3, j = rem & 7;
            float4 v = srcA[(size_t)tap * (NCOUT * CING / 8) + rem];
            *reinterpret_cast<float4*>(
                dstA + tap * (A_TILE / 2) + row * SROW + j * 8) = v;
        }
    }
    __syncthreads();   // the ONLY pre-epilogue sync

    float acc[16][4];    // per-tap sub-accumulator
    float acc2[16][4];   // cross-tap accumulator
#pragma unroll
    for (int i = 0; i < 16; i++)
#pragma unroll
        for (int j = 0; j < 4; j++) acc2[i][j] = 0.0f;

    const int pxb = wn + bRow;
    const uint32_t aAddrBase0 = sA + ((wm + 0  + aRow) * SROW + aCol) * 2;
    const uint32_t aAddrBase1 = sA + ((wm + 16 + aRow) * SROW + aCol) * 2;
    uint32_t bBase[4];
#pragma unroll
    for (int nb = 0; nb < 4; nb++) {
        const int px = pxb + nb * 16;
        bBase[nb] = sB + (((px >> 5) * BROW) + (px & 31) * CHS + bCol) * 2;
    }

#pragma unroll
    for (int tap = 0; tap < 9; tap++) {
        const int di = tap / 3, dj = tap - di * 3;
        const uint32_t aOff = tap * A_TILE;
        const uint32_t bOff = (di * BROW + dj * CHS) * 2;

        // A fragments for all 4 k-steps (shared by both splits)
        uint32_t a0[4][4], a1[4][4];
#pragma unroll
        for (int k = 0; k < 4; k++) {
            ldsm_x4(a0[k][0], a0[k][1], a0[k][2], a0[k][3],
                    aAddrBase0 + aOff + k * 32);
            ldsm_x4(a1[k][0], a1[k][1], a1[k][2], a1[k][3],
                    aAddrBase1 + aOff + k * 32);
        }

#pragma unroll
        for (int split = 0; split < 2; split++) {
            const uint32_t bSplitOff = bOff + split * (BSPL * 2);
#pragma unroll
            for (int k = 0; k < 4; k++) {
#pragma unroll
                for (int nb = 0; nb < 4; nb++) {
                    uint32_t r0, r1, r2, r3;
                    ldsm_x4(r0, r1, r2, r3, bBase[nb] + bSplitOff + k * 32);
                    if (split == 0 && k == 0) {
                        mma16816_z(acc[nb * 2][0], acc[nb * 2][1],
                                   acc[nb * 2][2], acc[nb * 2][3],
                                   a0[k][0], a0[k][1], a0[k][2], a0[k][3], r0, r1);
                        mma16816_z(acc[nb * 2 + 1][0], acc[nb * 2 + 1][1],
                                   acc[nb * 2 + 1][2], acc[nb * 2 + 1][3],
                                   a0[k][0], a0[k][1], a0[k][2], a0[k][3], r2, r3);
                        mma16816_z(acc[8 + nb * 2][0], acc[8 + nb * 2][1],
                                   acc[8 + nb * 2][2], acc[8 + nb * 2][3],
                                   a1[k][0], a1[k][1], a1[k][2], a1[k][3], r0, r1);
                        mma16816_z(acc[8 + nb * 2 + 1][0], acc[8 + nb * 2 + 1][1],
                                   acc[8 + nb * 2 + 1][2], acc[8 + nb * 2 + 1][3],
                                   a1[k][0], a1[k][1], a1[k][2], a1[k][3], r2, r3);
                    } else {
                        mma16816(acc[nb * 2][0], acc[nb * 2][1],
                                 acc[nb * 2][2], acc[nb * 2][3],
                                 a0[k][0], a0[k][1], a0[k][2], a0[k][3], r0, r1);
                        mma16816(acc[nb * 2 + 1][0], acc[nb * 2 + 1][1],
                                 acc[nb * 2 + 1][2], acc[nb * 2 + 1][3],
                                 a0[k][0], a0[k][1], a0[k][2], a0[k][3], r2, r3);
                        mma16816(acc[8 + nb * 2][0], acc[8 + nb * 2][1],
                                 acc[8 + nb * 2][2], acc[8 + nb * 2][3],
                                 a1[k][0], a1[k][1], a1[k][2], a1[k][3], r0, r1);
                        mma16816(acc[8 + nb * 2 + 1][0], acc[8 + nb * 2 + 1][1],
                                 acc[8 + nb * 2 + 1][2], acc[8 + nb * 2 + 1][3],
                                 a1[k][0], a1[k][1], a1[k][2], a1[k][3], r2, r3);
                    }
                }
            }
        }
        // flush tap sub-accumulator into cross-tap bank
#pragma unroll
        for (int i = 0; i < 16; i++)
#pragma unroll
            for (int j = 0; j < 4; j++) acc2[i][j] += acc[i][j];
    }

    // --- Epilogue 1: bconv stores (full 32B sectors) ---
    const int coBase = cohalf * 128 + wm;
#pragma unroll
    for (int mi = 0; mi < 2; mi++) {
#pragma unroll
        for (int ni = 0; ni < 8; ni++) {
            const int co_r = coBase + mi * 16 + (lane >> 2);
            const int px_c = px0 + wn + ni * 8 + (lane & 3) * 2;
            float* p0 = &g_bconv[((size_t)img * NCOUT + co_r) * HW + px_c];
            *reinterpret_cast<float2*>(p0) =
                make_float2(acc2[mi * 8 + ni][0], acc2[mi * 8 + ni][1]);
            *reinterpret_cast<float2*>(p0 + 8 * HW) =
                make_float2(acc2[mi * 8 + ni][2], acc2[mi * 8 + ni][3]);
        }
    }

    // --- Epilogue 2: fused BN stats ---
    float st1[4], st2[4];
#pragma unroll
    for (int mi = 0; mi < 2; mi++) {
#pragma unroll
        for (int half = 0; half < 2; half++) {
            float s1 = 0.f, s2 = 0.f;
#pragma unroll
            for (int ni = 0; ni < 8; ni++) {
                const float a = acc2[mi * 8 + ni][half * 2 + 0];
                const float c = acc2[mi * 8 + ni][half * 2 + 1];
                s1 += a + c;
                s2 += a * a + c * c;
            }
            st1[mi * 2 + half] = s1;
            st2[mi * 2 + half] = s2;
        }
    }
#pragma unroll
    for (int q = 0; q < 4; q++) {
#pragma unroll
        for (int o = 1; o <= 2; o <<= 1) {
            st1[q] += __shfl_xor_sync(0xFFFFFFFFu, st1[q], o);
            st2[q] += __shfl_xor_sync(0xFFFFFFFFu, st2[q], o);
        }
    }
    __syncthreads();   // ldsm reads done; safe to reuse smem
    float* sbuf = reinterpret_cast<float*>(smem);   // [128 co][2 nwarp][2]
    if ((lane & 3) == 0) {
#pragma unroll
        for (int q = 0; q < 4; q++) {
            const int mi = q >> 1, half = q & 1;
            const int co_l = wm + mi * 16 + half * 8 + (lane >> 2);
            sbuf[(co_l * 2 + (wid & 1)) * 2 + 0] = st1[q];
            sbuf[(co_l * 2 + (wid & 1)) * 2 + 1] = st2[q];
        }
    }
    __syncthreads();
    if (t < 128) {
        const float s1 = sbuf[(t * 2 + 0) * 2 + 0] + sbuf[(t * 2 + 1) * 2 + 0];
        const float s2 = sbuf[(t * 2 + 0) * 2 + 1] + sbuf[(t * 2 + 1) * 2 + 1];
        const int ch = g * NCOUT + cohalf * 128 + t;
        atomicAdd(&g_sum[ch],   (double)s1);
        atomicAdd(&g_sumsq[ch], (double)s2);
    }
}

// ---------------------------------------------------------------------------
// Kernel 2: sign + group merge + qrelu with in-block BN finalize.
// g_bconv loads are issued BEFORE the fp64 constant computation + sync so
// DRAM latency hides the rsqrt. Arithmetic identical to round 12.
// ---------------------------------------------------------------------------
__global__ void merge_kernel(const float* __restrict__ gamma,
                             const float* __restrict__ beta,
                             float* __restrict__ out) {
    const int t  = threadIdx.x;
    const int bc = blockIdx.x;           // = b*256 + co
    const int co = bc & (NCOUT - 1);
    const int b  = bc >> 8;

    // issue all 4 loads first (independent of scA/scB)
    float4 v[NG];
#pragma unroll
    for (int g = 0; g < NG; g++) {
        const size_t idx = ((((size_t)b * NG + g) * NCOUT + co) * (HW / 4)) + t;
        v[g] = reinterpret_cast<const float4*>(g_bconv)[idx];
    }

    __shared__ float scA[4], scB[4];
    if (t < 4) {
        const int ch = t * NCOUT + co;   // g = t
        const double N = (double)NB * (double)HW;
        const double mean_b = g_sum[ch] / N;
        const double var_b  = g_sumsq[ch] / N - mean_b * mean_b;
        const double a      = (double)g_alpha[co];
        const double inv    = rsqrt(a * a * var_b + 1e-5) * (double)gamma[ch];
        scA[t] = (float)(a * inv);
        scB[t] = (float)((double)beta[ch] - a * mean_b * inv);
    }
    __syncthreads();

    int y0 = 0, y1 = 0, y2 = 0, y3 = 0;
#pragma unroll
    for (int g = 0; g < NG; g++) {
        const float cA = scA[g];
        const float cB = scB[g];
        y0 += (fmaf(v[g].x, cA, cB) >= 0.0f) ? 1 : -1;
        y1 += (fmaf(v[g].y, cA, cB) >= 0.0f) ? 1 : -1;
        y2 += (fmaf(v[g].z, cA, cB) >= 0.0f) ? 1 : -1;
        y3 += (fmaf(v[g].w, cA, cB) >= 0.0f) ? 1 : -1;
    }
    const float QMID = (8.0f / 15.0f) * 4.0f;
    float4 o;
    o.x = (y0 >= 4) ? 4.0f : ((y0 >= 2) ? QMID : 0.0f);
    o.y = (y1 >= 4) ? 4.0f : ((y1 >= 2) ? QMID : 0.0f);
    o.z = (y2 >= 4) ? 4.0f : ((y2 >= 2) ? QMID : 0.0f);
    o.w = (y3 >= 4) ? 4.0f : ((y3 >= 2) ? QMID : 0.0f);
    reinterpret_cast<float4*>(out)[(size_t)bc * 256 + t] = o;
}

// ---------------------------------------------------------------------------
extern "C" void kernel_launch(void* const* d_in, const int* in_sizes, int n_in,
                              void* d_out, int out_size) {
    (void)in_sizes; (void)n_in; (void)out_size;
    const float* x     = (const float*)d_in[0];
    const float* w     = (const float*)d_in[1];
    const float* gamma = (const float*)d_in[2];
    const float* beta  = (const float*)d_in[3];
    float* out = (float*)d_out;

    // Host-side attribute set (idempotent, capture-safe, no device work)
    cudaFuncSetAttribute(conv_mma_kernel,
                         cudaFuncAttributeMaxDynamicSharedMemorySize, SM_TOT);

    prep_w_kernel<<<256, 256>>>(w);
    conv_mma_kernel<<<dim3(16, NG, NB), 256, SM_TOT>>>(x);
    merge_kernel<<<NB * NCOUT, 256>>>(gamma, beta, out);
}

// round 14
// speedup vs baseline: 7.1664x; 1.0221x over previous
#include <cuda_runtime.h>
#include <cuda_fp16.h>
#include <cstdint>

// Problem constants
#define NB    32
#define NG    4
#define NCOUT 256     // output channels per group
#define CING  64      // input channels per group
#define NCH   1024
#define HW    1024
#define SROW  72      // A smem row stride in halves (64 + 8 pad)
#define CHS   72      // B smem per-pixel stride in halves (64 + 8 pad)
#define BROW  (34 * CHS)      // 2448 halves per image row in smem
#define BSPL  (6 * BROW)      // 14688 halves per split (6 halo rows)

// Dynamic smem layout (bytes): bigB + 2 A buffers (64 co each)
#define SM_B    0                     // bigB: 2 * 14688 halves = 58752 B
#define SM_A0   58752                 // A buf 0: 64*72*2 = 9216 B
#define SM_A1   67968                 // A buf 1
#define SM_TOT  77184                 // 75.4 KB -> 2 CTAs/SM

// Device scratch (no allocations allowed)
__device__ float  g_alpha[NCOUT];
__device__ __align__(16) __half g_A[NG * 9 * NCOUT * CING];   // [g][tap][co][ch], +-1
__device__ float  g_bconv[(size_t)NB * NCH * HW];             // 134 MB
__device__ double g_sum[NCH];
__device__ double g_sumsq[NCH];

__device__ __forceinline__ uint32_t smem_u32(const void* p) {
    uint32_t a;
    asm("{ .reg .u64 t; cvta.to.shared.u64 t, %1; cvt.u32.u64 %0, t; }" : "=r"(a) : "l"(p));
    return a;
}
__device__ __forceinline__ void ldsm_x4(uint32_t& r0, uint32_t& r1, uint32_t& r2, uint32_t& r3,
                                        uint32_t addr) {
    asm volatile("ldmatrix.sync.aligned.m8n8.x4.shared.b16 {%0,%1,%2,%3}, [%4];"
                 : "=r"(r0), "=r"(r1), "=r"(r2), "=r"(r3) : "r"(addr));
}
// accumulate: D = A*B + D
__device__ __forceinline__ void mma16816(float& c0, float& c1, float& c2, float& c3,
                                         uint32_t a0, uint32_t a1, uint32_t a2, uint32_t a3,
                                         uint32_t b0, uint32_t b1) {
    asm volatile(
        "mma.sync.aligned.m16n8k16.row.col.f32.f16.f16.f32 "
        "{%0,%1,%2,%3}, {%4,%5,%6,%7}, {%8,%9}, {%0,%1,%2,%3};"
        : "+f"(c0), "+f"(c1), "+f"(c2), "+f"(c3)
        : "r"(a0), "r"(a1), "r"(a2), "r"(a3), "r"(b0), "r"(b1));
}
// overwrite: D = A*B + 0
__device__ __forceinline__ void mma16816_z(float& c0, float& c1, float& c2, float& c3,
                                           uint32_t a0, uint32_t a1, uint32_t a2, uint32_t a3,
                                           uint32_t b0, uint32_t b1) {
    asm volatile(
        "mma.sync.aligned.m16n8k16.row.col.f32.f16.f16.f32 "
        "{%0,%1,%2,%3}, {%4,%5,%6,%7}, {%8,%9}, {%10,%10,%10,%10};"
        : "=f"(c0), "=f"(c1), "=f"(c2), "=f"(c3)
        : "r"(a0), "r"(a1), "r"(a2), "r"(a3), "r"(b0), "r"(b1), "f"(0.0f));
}

// ---------------------------------------------------------------------------
// Kernel 0: alpha = mean|w|; sign tiles A[g][tap][co][ch] fp16; zero stats.
// ---------------------------------------------------------------------------
__global__ void prep_w_kernel(const float* __restrict__ w) {
    const int co = blockIdx.x;
    const int t  = threadIdx.x;
    const float* wc = w + (size_t)co * 256 * 9;

    if (t < 4) {
        g_sum[co * 4 + t]   = 0.0;
        g_sumsq[co * 4 + t] = 0.0;
    }

    float s = 0.0f;
    for (int i = t; i < 256 * 9; i += 256) s += fabsf(wc[i]);
    __shared__ float red[256];
    red[t] = s;
    __syncthreads();
    for (int o = 128; o > 0; o >>= 1) {
        if (t < o) red[t] += red[t + o];
        __syncthreads();
    }
    if (t == 0) g_alpha[co] = red[0] / 2304.0f;

    for (int i = t; i < 256 * 9; i += 256) {
        int ci = i / 9, tap = i - ci * 9;
        int g = ci >> 6, ch = ci & 63;
        __half v = (wc[i] >= 0.0f) ? __float2half_rn(1.0f) : __float2half_rn(-1.0f);
        g_A[((size_t)(g * 9 + tap) * NCOUT + co) * CING + ch] = v;
    }
}

// ---------------------------------------------------------------------------
// Kernel 1: HMMA implicit GEMM, M=64 tiles for 2 CTAs/SM.
// B halo staged directly from x (hi/lo fp16 split, identical formulas ->
// bit-identical bconv). A staged per-tap, double-buffered. Per-tap
// sub-accumulator flush; fused BN stats.
// CTA = (coq | ptile) x g x b. M=64 co, N=128 px (4 image rows).
// 8 warps: 2 M x 4 N, warp tile 32co x 32px.
// ---------------------------------------------------------------------------
__global__ void __launch_bounds__(256, 2) conv_mma_kernel(const float* __restrict__ x) {
    extern __shared__ char smem[];
    __half* bigB = reinterpret_cast<__half*>(smem + SM_B);

    const int t     = threadIdx.x;
    const int wid   = t >> 5;
    const int lane  = t & 31;
    const int coq   = blockIdx.x & 3;      // co quarter (64 couts)
    const int ptile = blockIdx.x >> 2;     // 0..7 (4 image rows each)
    const int g     = blockIdx.y;
    const int b     = blockIdx.z;
    const int img   = b * 4 + g;
    const int px0   = ptile * 128;

    const int wm = (wid >> 2) * 32;        // warp M offset (co): 0 or 32
    const int wn = (wid & 3) * 32;         // warp N offset (px): 0,32,64,96

    const uint32_t sB  = smem_u32(bigB);
    const uint32_t sA0 = smem_u32(smem + SM_A0);
    const uint32_t sA1 = smem_u32(smem + SM_A1);

    const int aRow = lane & 15;
    const int aCol = (lane >> 4) * 8;
    const int bRow = (lane & 7) + ((lane >> 4) & 1) * 8;
    const int bCol = ((lane >> 3) & 1) * 8;

    // --- Stage bigB directly from x (identical to round 13) ---
    {
        const __half2 z2 = __halves2half2(__float2half_rn(0.f), __float2half_rn(0.f));
        for (int i = t; i < 768; i += 256) {        // borders wp 0/33
            int split = (i >= 384) ? 1 : 0;
            int r   = i - split * 384;
            int row = r >> 6;
            int q   = r & 63;
            int wp  = (q >> 5) ? 33 : 0;
            int chp = q & 31;
            *reinterpret_cast<__half2*>(
                bigB + split * BSPL + row * BROW + wp * CHS + chp * 2) = z2;
        }
        const float* xb = x + ((size_t)b * 256 + (size_t)g * 64) * HW;
        for (int i = t; i < 1536; i += 256) {       // interior
            int row = i >> 8;
            int r   = i & 255;
            int chp = r >> 3;
            int wq  = r & 7;
            int xh  = ptile * 4 + row - 1;
            float4 va, vb;
            if (xh >= 0 && xh < 32) {
                const float4* src = reinterpret_cast<const float4*>(
                    xb + (size_t)(chp * 2) * HW + (size_t)xh * 32) + wq;
                va = src[0];
                vb = src[256];
            } else {
                va = make_float4(0.f, 0.f, 0.f, 0.f);
                vb = va;
            }
            const float av[4] = { va.x, va.y, va.z, va.w };
            const float bv[4] = { vb.x, vb.y, vb.z, vb.w };
#pragma unroll
            for (int j = 0; j < 4; j++) {
                const int wp = wq * 4 + j + 1;
                const __half h0 = __float2half_rn(av[j]);
                const __half h1 = __float2half_rn(bv[j]);
                const __half l0 = __float2half_rn(av[j] - __half2float(h0));
                const __half l1 = __float2half_rn(bv[j] - __half2float(h1));
                *reinterpret_cast<__half2*>(
                    bigB + row * BROW + wp * CHS + chp * 2) = __halves2half2(h0, h1);
                *reinterpret_cast<__half2*>(
                    bigB + BSPL + row * BROW + wp * CHS + chp * 2) = __halves2half2(l0, l1);
            }
        }
    }
    // Stage A(tap=0) into buf0: 64 rows x 64 ch = 512 float4
    {
        const float4* srcA = reinterpret_cast<const float4*>(
            g_A + ((size_t)(g * 9) * NCOUT + coq * 64) * CING);
        __half* dst = reinterpret_cast<__half*>(smem + SM_A0);
        for (int i = t; i < 512; i += 256) {
            int row = i >> 3, j = i & 7;
            *reinterpret_cast<float4*>(dst + row * SROW + j * 8) = srcA[i];
        }
    }
    __syncthreads();

    float acc[8][4];     // per-tap sub-accumulator: [mi*4 + ni][quad]
    float acc2[8][4];    // cross-tap accumulator
#pragma unroll
    for (int i = 0; i < 8; i++)
#pragma unroll
        for (int j = 0; j < 4; j++) acc2[i][j] = 0.0f;

    const int pxb = wn + bRow;
    uint32_t bBase[2];
#pragma unroll
    for (int nb = 0; nb < 2; nb++) {
        const int px = pxb + nb * 16;
        bBase[nb] = sB + (((px >> 5) * BROW) + (px & 31) * CHS + bCol) * 2;
    }

    for (int tap = 0; tap < 9; tap++) {
        const int di = tap / 3, dj = tap - di * 3;
        const uint32_t sAcur = (tap & 1) ? sA1 : sA0;
        const uint32_t bOff = (di * BROW + dj * CHS) * 2;
        const uint32_t aAddr0 = sAcur + ((wm + 0  + aRow) * SROW + aCol) * 2;
        const uint32_t aAddr1 = sAcur + ((wm + 16 + aRow) * SROW + aCol) * 2;

        // prefetch A(tap+1) into the other buffer (overlaps mma)
        if (tap < 8) {
            const float4* srcA = reinterpret_cast<const float4*>(
                g_A + ((size_t)(g * 9 + tap + 1) * NCOUT + coq * 64) * CING);
            __half* dst = reinterpret_cast<__half*>(smem + ((tap & 1) ? SM_A0 : SM_A1));
            for (int i = t; i < 512; i += 256) {
                int row = i >> 3, j = i & 7;
                *reinterpret_cast<float4*>(dst + row * SROW + j * 8) = srcA[i];
            }
        }

#pragma unroll
        for (int split = 0; split < 2; split++) {
            const uint32_t bSplitOff = bOff + split * (BSPL * 2);
#pragma unroll
            for (int k = 0; k < 4; k++) {
                uint32_t a0[4], a1[4];
                ldsm_x4(a0[0], a0[1], a0[2], a0[3], aAddr0 + k * 32);
                ldsm_x4(a1[0], a1[1], a1[2], a1[3], aAddr1 + k * 32);
#pragma unroll
                for (int nb = 0; nb < 2; nb++) {
                    uint32_t r0, r1, r2, r3;
                    ldsm_x4(r0, r1, r2, r3, bBase[nb] + bSplitOff + k * 32);
                    if (split == 0 && k == 0) {
                        mma16816_z(acc[nb * 2][0], acc[nb * 2][1],
                                   acc[nb * 2][2], acc[nb * 2][3],
                                   a0[0], a0[1], a0[2], a0[3], r0, r1);
                        mma16816_z(acc[nb * 2 + 1][0], acc[nb * 2 + 1][1],
                                   acc[nb * 2 + 1][2], acc[nb * 2 + 1][3],
                                   a0[0], a0[1], a0[2], a0[3], r2, r3);
                        mma16816_z(acc[4 + nb * 2][0], acc[4 + nb * 2][1],
                                   acc[4 + nb * 2][2], acc[4 + nb * 2][3],
                                   a1[0], a1[1], a1[2], a1[3], r0, r1);
                        mma16816_z(acc[4 + nb * 2 + 1][0], acc[4 + nb * 2 + 1][1],
                                   acc[4 + nb * 2 + 1][2], acc[4 + nb * 2 + 1][3],
                                   a1[0], a1[1], a1[2], a1[3], r2, r3);
                    } else {
                        mma16816(acc[nb * 2][0], acc[nb * 2][1],
                                 acc[nb * 2][2], acc[nb * 2][3],
                                 a0[0], a0[1], a0[2], a0[3], r0, r1);
                        mma16816(acc[nb * 2 + 1][0], acc[nb * 2 + 1][1],
                                 acc[nb * 2 + 1][2], acc[nb * 2 + 1][3],
                                 a0[0], a0[1], a0[2], a0[3], r2, r3);
                        mma16816(acc[4 + nb * 2][0], acc[4 + nb * 2][1],
                                 acc[4 + nb * 2][2], acc[4 + nb * 2][3],
                                 a1[0], a1[1], a1[2], a1[3], r0, r1);
                        mma16816(acc[4 + nb * 2 + 1][0], acc[4 + nb * 2 + 1][1],
                                 acc[4 + nb * 2 + 1][2], acc[4 + nb * 2 + 1][3],
                                 a1[0], a1[1], a1[2], a1[3], r2, r3);
                    }
                }
            }
        }
        __syncthreads();   // A prefetch visible; this tap's A reads done

        // flush tap sub-accumulator into cross-tap bank
#pragma unroll
        for (int i = 0; i < 8; i++)
#pragma unroll
            for (int j = 0; j < 4; j++) acc2[i][j] += acc[i][j];
    }

    // --- Epilogue 1: bconv stores (full 32B sectors) ---
    const int coBase = coq * 64 + wm;
#pragma unroll
    for (int mi = 0; mi < 2; mi++) {
#pragma unroll
        for (int ni = 0; ni < 4; ni++) {
            const int co_r = coBase + mi * 16 + (lane >> 2);
            const int px_c = px0 + wn + ni * 8 + (lane & 3) * 2;
            float* p0 = &g_bconv[((size_t)img * NCOUT + co_r) * HW + px_c];
            *reinterpret_cast<float2*>(p0) =
                make_float2(acc2[mi * 4 + ni][0], acc2[mi * 4 + ni][1]);
            *reinterpret_cast<float2*>(p0 + 8 * HW) =
                make_float2(acc2[mi * 4 + ni][2], acc2[mi * 4 + ni][3]);
        }
    }

    // --- Epilogue 2: fused BN stats ---
    float st1[4], st2[4];
#pragma unroll
    for (int mi = 0; mi < 2; mi++) {
#pragma unroll
        for (int half = 0; half < 2; half++) {
            float s1 = 0.f, s2 = 0.f;
#pragma unroll
            for (int ni = 0; ni < 4; ni++) {
                const float a = acc2[mi * 4 + ni][half * 2 + 0];
                const float c = acc2[mi * 4 + ni][half * 2 + 1];
                s1 += a + c;
                s2 += a * a + c * c;
            }
            st1[mi * 2 + half] = s1;
            st2[mi * 2 + half] = s2;
        }
    }
#pragma unroll
    for (int q = 0; q < 4; q++) {
#pragma unroll
        for (int o = 1; o <= 2; o <<= 1) {
            st1[q] += __shfl_xor_sync(0xFFFFFFFFu, st1[q], o);
            st2[q] += __shfl_xor_sync(0xFFFFFFFFu, st2[q], o);
        }
    }
    __syncthreads();   // ldsm reads done; safe to reuse smem
    float* sbuf = reinterpret_cast<float*>(smem);   // [64 co][4 nwarp][2]
    if ((lane & 3) == 0) {
#pragma unroll
        for (int q = 0; q < 4; q++) {
            const int mi = q >> 1, half = q & 1;
            const int co_l = wm + mi * 16 + half * 8 + (lane >> 2);
            sbuf[(co_l * 4 + (wid & 3)) * 2 + 0] = st1[q];
            sbuf[(co_l * 4 + (wid & 3)) * 2 + 1] = st2[q];
        }
    }
    __syncthreads();
    if (t < 64) {
        float s1 = 0.f, s2 = 0.f;
#pragma unroll
        for (int nw = 0; nw < 4; nw++) {
            s1 += sbuf[(t * 4 + nw) * 2 + 0];
            s2 += sbuf[(t * 4 + nw) * 2 + 1];
        }
        const int ch = g * NCOUT + coq * 64 + t;
        atomicAdd(&g_sum[ch],   (double)s1);
        atomicAdd(&g_sumsq[ch], (double)s2);
    }
}

// ---------------------------------------------------------------------------
// Kernel 2: sign + group merge + qrelu with in-block BN finalize.
// Loads issued before the fp64 constants so DRAM latency hides the rsqrt.
// ---------------------------------------------------------------------------
__global__ void merge_kernel(const float* __restrict__ gamma,
                             const float* __restrict__ beta,
                             float* __restrict__ out) {
    const int t  = threadIdx.x;
    const int bc = blockIdx.x;           // = b*256 + co
    const int co = bc & (NCOUT - 1);
    const int b  = bc >> 8;

    float4 v[NG];
#pragma unroll
    for (int g = 0; g < NG; g++) {
        const size_t idx = ((((size_t)b * NG + g) * NCOUT + co) * (HW / 4)) + t;
        v[g] = reinterpret_cast<const float4*>(g_bconv)[idx];
    }

    __shared__ float scA[4], scB[4];
    if (t < 4) {
        const int ch = t * NCOUT + co;   // g = t
        const double N = (double)NB * (double)HW;
        const double mean_b = g_sum[ch] / N;
        const double var_b  = g_sumsq[ch] / N - mean_b * mean_b;
        const double a      = (double)g_alpha[co];
        const double inv    = rsqrt(a * a * var_b + 1e-5) * (double)gamma[ch];
        scA[t] = (float)(a * inv);
        scB[t] = (float)((double)beta[ch] - a * mean_b * inv);
    }
    __syncthreads();

    int y0 = 0, y1 = 0, y2 = 0, y3 = 0;
#pragma unroll
    for (int g = 0; g < NG; g++) {
        const float cA = scA[g];
        const float cB = scB[g];
        y0 += (fmaf(v[g].x, cA, cB) >= 0.0f) ? 1 : -1;
        y1 += (fmaf(v[g].y, cA, cB) >= 0.0f) ? 1 : -1;
        y2 += (fmaf(v[g].z, cA, cB) >= 0.0f) ? 1 : -1;
        y3 += (fmaf(v[g].w, cA, cB) >= 0.0f) ? 1 : -1;
    }
    const float QMID = (8.0f / 15.0f) * 4.0f;
    float4 o;
    o.x = (y0 >= 4) ? 4.0f : ((y0 >= 2) ? QMID : 0.0f);
    o.y = (y1 >= 4) ? 4.0f : ((y1 >= 2) ? QMID : 0.0f);
    o.z = (y2 >= 4) ? 4.0f : ((y2 >= 2) ? QMID : 0.0f);
    o.w = (y3 >= 4) ? 4.0f : ((y3 >= 2) ? QMID : 0.0f);
    reinterpret_cast<float4*>(out)[(size_t)bc * 256 + t] = o;
}

// ---------------------------------------------------------------------------
extern "C" void kernel_launch(void* const* d_in, const int* in_sizes, int n_in,
                              void* d_out, int out_size) {
    (void)in_sizes; (void)n_in; (void)out_size;
    const float* x     = (const float*)d_in[0];
    const float* w     = (const float*)d_in[1];
    const float* gamma = (const float*)d_in[2];
    const float* beta  = (const float*)d_in[3];
    float* out = (float*)d_out;

    // Host-side attribute set (idempotent, capture-safe, no device work)
    cudaFuncSetAttribute(conv_mma_kernel,
                         cudaFuncAttributeMaxDynamicSharedMemorySize, SM_TOT);

    prep_w_kernel<<<256, 256>>>(w);
    conv_mma_kernel<<<dim3(32, NG, NB), 256, SM_TOT>>>(x);
    merge_kernel<<<NB * NCOUT, 256>>>(gamma, beta, out);
}

// round 15
// speedup vs baseline: 7.2191x; 1.0074x over previous
#include <cuda_runtime.h>
#include <cuda_fp16.h>
#include <cstdint>

// Problem constants
#define NB    32
#define NG    4
#define NCOUT 256     // output channels per group
#define CING  64      // input channels per group
#define NCH   1024
#define HW    1024
#define SROW  72      // A smem row stride in halves (64 + 8 pad)
#define CHS   72      // B smem per-pixel stride in halves (64 + 8 pad)
#define BROW  (34 * CHS)      // 2448 halves per image row in smem
#define BSPL  (6 * BROW)      // 14688 halves per split (6 halo rows)

// Dynamic smem layout (bytes): bigB + 2 A buffers (64 co each)
#define SM_B    0                     // bigB: 2 * 14688 halves = 58752 B
#define SM_A0   58752                 // A buf 0: 64*72*2 = 9216 B
#define SM_A1   67968                 // A buf 1
#define SM_TOT  77184                 // 75.4 KB -> 2 CTAs/SM

// Device scratch (no allocations allowed)
__device__ float  g_apart[NCOUT * 4];                         // per-(co,slice) |w| partials
__device__ __align__(16) __half g_A[NG * 9 * NCOUT * CING];   // [g][tap][co][ch], +-1
__device__ float  g_bconv[(size_t)NB * NCH * HW];             // 134 MB
__device__ double g_sum[NCH];
__device__ double g_sumsq[NCH];

__device__ __forceinline__ uint32_t smem_u32(const void* p) {
    uint32_t a;
    asm("{ .reg .u64 t; cvta.to.shared.u64 t, %1; cvt.u32.u64 %0, t; }" : "=r"(a) : "l"(p));
    return a;
}
__device__ __forceinline__ void ldsm_x4(uint32_t& r0, uint32_t& r1, uint32_t& r2, uint32_t& r3,
                                        uint32_t addr) {
    asm volatile("ldmatrix.sync.aligned.m8n8.x4.shared.b16 {%0,%1,%2,%3}, [%4];"
                 : "=r"(r0), "=r"(r1), "=r"(r2), "=r"(r3) : "r"(addr));
}
// accumulate: D = A*B + D
__device__ __forceinline__ void mma16816(float& c0, float& c1, float& c2, float& c3,
                                         uint32_t a0, uint32_t a1, uint32_t a2, uint32_t a3,
                                         uint32_t b0, uint32_t b1) {
    asm volatile(
        "mma.sync.aligned.m16n8k16.row.col.f32.f16.f16.f32 "
        "{%0,%1,%2,%3}, {%4,%5,%6,%7}, {%8,%9}, {%0,%1,%2,%3};"
        : "+f"(c0), "+f"(c1), "+f"(c2), "+f"(c3)
        : "r"(a0), "r"(a1), "r"(a2), "r"(a3), "r"(b0), "r"(b1));
}
// overwrite: D = A*B + 0
__device__ __forceinline__ void mma16816_z(float& c0, float& c1, float& c2, float& c3,
                                           uint32_t a0, uint32_t a1, uint32_t a2, uint32_t a3,
                                           uint32_t b0, uint32_t b1) {
    asm volatile(
        "mma.sync.aligned.m16n8k16.row.col.f32.f16.f16.f32 "
        "{%0,%1,%2,%3}, {%4,%5,%6,%7}, {%8,%9}, {%10,%10,%10,%10};"
        : "=f"(c0), "=f"(c1), "=f"(c2), "=f"(c3)
        : "r"(a0), "r"(a1), "r"(a2), "r"(a3), "r"(b0), "r"(b1), "f"(0.0f));
}

// ---------------------------------------------------------------------------
// Kernel 0: per-(co, ci-slice of 64) |w| partial + sign tiles; zero stats.
// grid 1024 (= co*4 + slice), 256 threads. 4x the parallelism of the old
// one-block-per-co version (was latency-bound at occ 21%).
// ---------------------------------------------------------------------------
__global__ void prep_w_kernel(const float* __restrict__ w) {
    const int bid   = blockIdx.x;        // 0..1023
    const int co    = bid >> 2;
    const int slice = bid & 3;           // ci slice: slice*64 .. slice*64+63
    const int t     = threadIdx.x;

    if (t == 0) {
        g_sum[bid]   = 0.0;
        g_sumsq[bid] = 0.0;
    }

    // this slice's weights: w[co][slice*64 + 0..63][9] = 576 contiguous floats
    const float* wc = w + ((size_t)co * 256 + slice * 64) * 9;

    float s = 0.0f;
    float wv[3];
    const int n0 = t * 2;                 // elements 2t, 2t+1 (+ tail for t<64)
    wv[0] = wc[n0];
    wv[1] = wc[n0 + 1];
    wv[2] = (t < 64) ? wc[512 + t] : 0.0f;
    s = fabsf(wv[0]) + fabsf(wv[1]) + ((t < 64) ? fabsf(wv[2]) : 0.0f);

    __shared__ float red[256];
    red[t] = s;
    __syncthreads();
    for (int o = 128; o > 0; o >>= 1) {
        if (t < o) red[t] += red[t + o];
        __syncthreads();
    }
    if (t == 0) g_apart[bid] = red[0];

    // signs: element index e in [0,576) -> ci_local = e/9, tap = e%9
    // g_A[((g*9+tap)*256+co)*64 + ch], g = slice, ch = ci_local
#pragma unroll
    for (int u = 0; u < 3; u++) {
        const int e = (u < 2) ? (n0 + u) : (512 + t);
        if (u == 2 && t >= 64) break;
        const int cil = e / 9;
        const int tap = e - cil * 9;
        const __half v = (wv[u] >= 0.0f) ? __float2half_rn(1.0f) : __float2half_rn(-1.0f);
        g_A[((size_t)(slice * 9 + tap) * NCOUT + co) * CING + cil] = v;
    }
}

// ---------------------------------------------------------------------------
// Kernel 1: HMMA implicit GEMM, M=64 tiles for 2 CTAs/SM (unchanged R14).
// ---------------------------------------------------------------------------
__global__ void __launch_bounds__(256, 2) conv_mma_kernel(const float* __restrict__ x) {
    extern __shared__ char smem[];
    __half* bigB = reinterpret_cast<__half*>(smem + SM_B);

    const int t     = threadIdx.x;
    const int wid   = t >> 5;
    const int lane  = t & 31;
    const int coq   = blockIdx.x & 3;      // co quarter (64 couts)
    const int ptile = blockIdx.x >> 2;     // 0..7 (4 image rows each)
    const int g     = blockIdx.y;
    const int b     = blockIdx.z;
    const int img   = b * 4 + g;
    const int px0   = ptile * 128;

    const int wm = (wid >> 2) * 32;        // warp M offset (co): 0 or 32
    const int wn = (wid & 3) * 32;         // warp N offset (px): 0,32,64,96

    const uint32_t sB  = smem_u32(bigB);
    const uint32_t sA0 = smem_u32(smem + SM_A0);
    const uint32_t sA1 = smem_u32(smem + SM_A1);

    const int aRow = lane & 15;
    const int aCol = (lane >> 4) * 8;
    const int bRow = (lane & 7) + ((lane >> 4) & 1) * 8;
    const int bCol = ((lane >> 3) & 1) * 8;

    // --- Stage bigB directly from x ---
    {
        const __half2 z2 = __halves2half2(__float2half_rn(0.f), __float2half_rn(0.f));
        for (int i = t; i < 768; i += 256) {        // borders wp 0/33
            int split = (i >= 384) ? 1 : 0;
            int r   = i - split * 384;
            int row = r >> 6;
            int q   = r & 63;
            int wp  = (q >> 5) ? 33 : 0;
            int chp = q & 31;
            *reinterpret_cast<__half2*>(
                bigB + split * BSPL + row * BROW + wp * CHS + chp * 2) = z2;
        }
        const float* xb = x + ((size_t)b * 256 + (size_t)g * 64) * HW;
        for (int i = t; i < 1536; i += 256) {       // interior
            int row = i >> 8;
            int r   = i & 255;
            int chp = r >> 3;
            int wq  = r & 7;
            int xh  = ptile * 4 + row - 1;
            float4 va, vb;
            if (xh >= 0 && xh < 32) {
                const float4* src = reinterpret_cast<const float4*>(
                    xb + (size_t)(chp * 2) * HW + (size_t)xh * 32) + wq;
                va = src[0];
                vb = src[256];
            } else {
                va = make_float4(0.f, 0.f, 0.f, 0.f);
                vb = va;
            }
            const float av[4] = { va.x, va.y, va.z, va.w };
            const float bv[4] = { vb.x, vb.y, vb.z, vb.w };
#pragma unroll
            for (int j = 0; j < 4; j++) {
                const int wp = wq * 4 + j + 1;
                const __half h0 = __float2half_rn(av[j]);
                const __half h1 = __float2half_rn(bv[j]);
                const __half l0 = __float2half_rn(av[j] - __half2float(h0));
                const __half l1 = __float2half_rn(bv[j] - __half2float(h1));
                *reinterpret_cast<__half2*>(
                    bigB + row * BROW + wp * CHS + chp * 2) = __halves2half2(h0, h1);
                *reinterpret_cast<__half2*>(
                    bigB + BSPL + row * BROW + wp * CHS + chp * 2) = __halves2half2(l0, l1);
            }
        }
    }
    // Stage A(tap=0) into buf0: 64 rows x 64 ch = 512 float4
    {
        const float4* srcA = reinterpret_cast<const float4*>(
            g_A + ((size_t)(g * 9) * NCOUT + coq * 64) * CING);
        __half* dst = reinterpret_cast<__half*>(smem + SM_A0);
        for (int i = t; i < 512; i += 256) {
            int row = i >> 3, j = i & 7;
            *reinterpret_cast<float4*>(dst + row * SROW + j * 8) = srcA[i];
        }
    }
    __syncthreads();

    float acc[8][4];     // per-tap sub-accumulator
    float acc2[8][4];    // cross-tap accumulator
#pragma unroll
    for (int i = 0; i < 8; i++)
#pragma unroll
        for (int j = 0; j < 4; j++) acc2[i][j] = 0.0f;

    const int pxb = wn + bRow;
    uint32_t bBase[2];
#pragma unroll
    for (int nb = 0; nb < 2; nb++) {
        const int px = pxb + nb * 16;
        bBase[nb] = sB + (((px >> 5) * BROW) + (px & 31) * CHS + bCol) * 2;
    }

    for (int tap = 0; tap < 9; tap++) {
        const int di = tap / 3, dj = tap - di * 3;
        const uint32_t sAcur = (tap & 1) ? sA1 : sA0;
        const uint32_t bOff = (di * BROW + dj * CHS) * 2;
        const uint32_t aAddr0 = sAcur + ((wm + 0  + aRow) * SROW + aCol) * 2;
        const uint32_t aAddr1 = sAcur + ((wm + 16 + aRow) * SROW + aCol) * 2;

        // prefetch A(tap+1) into the other buffer (overlaps mma)
        if (tap < 8) {
            const float4* srcA = reinterpret_cast<const float4*>(
                g_A + ((size_t)(g * 9 + tap + 1) * NCOUT + coq * 64) * CING);
            __half* dst = reinterpret_cast<__half*>(smem + ((tap & 1) ? SM_A0 : SM_A1));
            for (int i = t; i < 512; i += 256) {
                int row = i >> 3, j = i & 7;
                *reinterpret_cast<float4*>(dst + row * SROW + j * 8) = srcA[i];
            }
        }

#pragma unroll
        for (int split = 0; split < 2; split++) {
            const uint32_t bSplitOff = bOff + split * (BSPL * 2);
#pragma unroll
            for (int k = 0; k < 4; k++) {
                uint32_t a0[4], a1[4];
                ldsm_x4(a0[0], a0[1], a0[2], a0[3], aAddr0 + k * 32);
                ldsm_x4(a1[0], a1[1], a1[2], a1[3], aAddr1 + k * 32);
#pragma unroll
                for (int nb = 0; nb < 2; nb++) {
                    uint32_t r0, r1, r2, r3;
                    ldsm_x4(r0, r1, r2, r3, bBase[nb] + bSplitOff + k * 32);
                    if (split == 0 && k == 0) {
                        mma16816_z(acc[nb * 2][0], acc[nb * 2][1],
                                   acc[nb * 2][2], acc[nb * 2][3],
                                   a0[0], a0[1], a0[2], a0[3], r0, r1);
                        mma16816_z(acc[nb * 2 + 1][0], acc[nb * 2 + 1][1],
                                   acc[nb * 2 + 1][2], acc[nb * 2 + 1][3],
                                   a0[0], a0[1], a0[2], a0[3], r2, r3);
                        mma16816_z(acc[4 + nb * 2][0], acc[4 + nb * 2][1],
                                   acc[4 + nb * 2][2], acc[4 + nb * 2][3],
                                   a1[0], a1[1], a1[2], a1[3], r0, r1);
                        mma16816_z(acc[4 + nb * 2 + 1][0], acc[4 + nb * 2 + 1][1],
                                   acc[4 + nb * 2 + 1][2], acc[4 + nb * 2 + 1][3],
                                   a1[0], a1[1], a1[2], a1[3], r2, r3);
                    } else {
                        mma16816(acc[nb * 2][0], acc[nb * 2][1],
                                 acc[nb * 2][2], acc[nb * 2][3],
                                 a0[0], a0[1], a0[2], a0[3], r0, r1);
                        mma16816(acc[nb * 2 + 1][0], acc[nb * 2 + 1][1],
                                 acc[nb * 2 + 1][2], acc[nb * 2 + 1][3],
                                 a0[0], a0[1], a0[2], a0[3], r2, r3);
                        mma16816(acc[4 + nb * 2][0], acc[4 + nb * 2][1],
                                 acc[4 + nb * 2][2], acc[4 + nb * 2][3],
                                 a1[0], a1[1], a1[2], a1[3], r0, r1);
                        mma16816(acc[4 + nb * 2 + 1][0], acc[4 + nb * 2 + 1][1],
                                 acc[4 + nb * 2 + 1][2], acc[4 + nb * 2 + 1][3],
                                 a1[0], a1[1], a1[2], a1[3], r2, r3);
                    }
                }
            }
        }
        __syncthreads();   // A prefetch visible; this tap's A reads done

#pragma unroll
        for (int i = 0; i < 8; i++)
#pragma unroll
            for (int j = 0; j < 4; j++) acc2[i][j] += acc[i][j];
    }

    // --- Epilogue 1: bconv stores ---
    const int coBase = coq * 64 + wm;
#pragma unroll
    for (int mi = 0; mi < 2; mi++) {
#pragma unroll
        for (int ni = 0; ni < 4; ni++) {
            const int co_r = coBase + mi * 16 + (lane >> 2);
            const int px_c = px0 + wn + ni * 8 + (lane & 3) * 2;
            float* p0 = &g_bconv[((size_t)img * NCOUT + co_r) * HW + px_c];
            *reinterpret_cast<float2*>(p0) =
                make_float2(acc2[mi * 4 + ni][0], acc2[mi * 4 + ni][1]);
            *reinterpret_cast<float2*>(p0 + 8 * HW) =
                make_float2(acc2[mi * 4 + ni][2], acc2[mi * 4 + ni][3]);
        }
    }

    // --- Epilogue 2: fused BN stats ---
    float st1[4], st2[4];
#pragma unroll
    for (int mi = 0; mi < 2; mi++) {
#pragma unroll
        for (int half = 0; half < 2; half++) {
            float s1 = 0.f, s2 = 0.f;
#pragma unroll
            for (int ni = 0; ni < 4; ni++) {
                const float a = acc2[mi * 4 + ni][half * 2 + 0];
                const float c = acc2[mi * 4 + ni][half * 2 + 1];
                s1 += a + c;
                s2 += a * a + c * c;
            }
            st1[mi * 2 + half] = s1;
            st2[mi * 2 + half] = s2;
        }
    }
#pragma unroll
    for (int q = 0; q < 4; q++) {
#pragma unroll
        for (int o = 1; o <= 2; o <<= 1) {
            st1[q] += __shfl_xor_sync(0xFFFFFFFFu, st1[q], o);
            st2[q] += __shfl_xor_sync(0xFFFFFFFFu, st2[q], o);
        }
    }
    __syncthreads();   // ldsm reads done; safe to reuse smem
    float* sbuf = reinterpret_cast<float*>(smem);   // [64 co][4 nwarp][2]
    if ((lane & 3) == 0) {
#pragma unroll
        for (int q = 0; q < 4; q++) {
            const int mi = q >> 1, half = q & 1;
            const int co_l = wm + mi * 16 + half * 8 + (lane >> 2);
            sbuf[(co_l * 4 + (wid & 3)) * 2 + 0] = st1[q];
            sbuf[(co_l * 4 + (wid & 3)) * 2 + 1] = st2[q];
        }
    }
    __syncthreads();
    if (t < 64) {
        float s1 = 0.f, s2 = 0.f;
#pragma unroll
        for (int nw = 0; nw < 4; nw++) {
            s1 += sbuf[(t * 4 + nw) * 2 + 0];
            s2 += sbuf[(t * 4 + nw) * 2 + 1];
        }
        const int ch = g * NCOUT + coq * 64 + t;
        atomicAdd(&g_sum[ch],   (double)s1);
        atomicAdd(&g_sumsq[ch], (double)s2);
    }
}

// ---------------------------------------------------------------------------
// Kernel 2: sign + group merge + qrelu with in-block BN finalize
// (alpha assembled from the 4 prep_w partials, fixed order, fp64).
// ---------------------------------------------------------------------------
__global__ void merge_kernel(const float* __restrict__ gamma,
                             const float* __restrict__ beta,
                             float* __restrict__ out) {
    const int t  = threadIdx.x;
    const int bc = blockIdx.x;           // = b*256 + co
    const int co = bc & (NCOUT - 1);
    const int b  = bc >> 8;

    // issue all 4 loads first (independent of scA/scB)
    float4 v[NG];
#pragma unroll
    for (int g = 0; g < NG; g++) {
        const size_t idx = ((((size_t)b * NG + g) * NCOUT + co) * (HW / 4)) + t;
        v[g] = reinterpret_cast<const float4*>(g_bconv)[idx];
    }

    __shared__ float scA[4], scB[4];
    if (t < 4) {
        const int ch = t * NCOUT + co;   // g = t
        const double N = (double)NB * (double)HW;
        const double a = (((double)g_apart[co * 4 + 0] + (double)g_apart[co * 4 + 1])
                        + ((double)g_apart[co * 4 + 2] + (double)g_apart[co * 4 + 3]))
                       / 2304.0;
        const double mean_b = g_sum[ch] / N;
        const double var_b  = g_sumsq[ch] / N - mean_b * mean_b;
        const double inv    = rsqrt(a * a * var_b + 1e-5) * (double)gamma[ch];
        scA[t] = (float)(a * inv);
        scB[t] = (float)((double)beta[ch] - a * mean_b * inv);
    }
    __syncthreads();

    int y0 = 0, y1 = 0, y2 = 0, y3 = 0;
#pragma unroll
    for (int g = 0; g < NG; g++) {
        const float cA = scA[g];
        const float cB = scB[g];
        y0 += (fmaf(v[g].x, cA, cB) >= 0.0f) ? 1 : -1;
        y1 += (fmaf(v[g].y, cA, cB) >= 0.0f) ? 1 : -1;
        y2 += (fmaf(v[g].z, cA, cB) >= 0.0f) ? 1 : -1;
        y3 += (fmaf(v[g].w, cA, cB) >= 0.0f) ? 1 : -1;
    }
    const float QMID = (8.0f / 15.0f) * 4.0f;
    float4 o;
    o.x = (y0 >= 4) ? 4.0f : ((y0 >= 2) ? QMID : 0.0f);
    o.y = (y1 >= 4) ? 4.0f : ((y1 >= 2) ? QMID : 0.0f);
    o.z = (y2 >= 4) ? 4.0f : ((y2 >= 2) ? QMID : 0.0f);
    o.w = (y3 >= 4) ? 4.0f : ((y3 >= 2) ? QMID : 0.0f);
    reinterpret_cast<float4*>(out)[(size_t)bc * 256 + t] = o;
}

// ---------------------------------------------------------------------------
extern "C" void kernel_launch(void* const* d_in, const int* in_sizes, int n_in,
                              void* d_out, int out_size) {
    (void)in_sizes; (void)n_in; (void)out_size;
    const float* x     = (const float*)d_in[0];
    const float* w     = (const float*)d_in[1];
    const float* gamma = (const float*)d_in[2];
    const float* beta  = (const float*)d_in[3];
    float* out = (float*)d_out;

    // Host-side attribute set (idempotent, capture-safe, no device work)
    cudaFuncSetAttribute(conv_mma_kernel,
                         cudaFuncAttributeMaxDynamicSharedMemorySize, SM_TOT);

    prep_w_kernel<<<NCOUT * 4, 256>>>(w);
    conv_mma_kernel<<<dim3(32, NG, NB), 256, SM_TOT>>>(x);
    merge_kernel<<<NB * NCOUT, 256>>>(gamma, beta, out);
}

// round 16
// speedup vs baseline: 7.3744x; 1.0215x over previous
#include <cuda_runtime.h>
#include <cuda_fp16.h>
#include <cstdint>

// Problem constants
#define NB    32
#define NG    4
#define NCOUT 256     // output channels per group
#define CING  64      // input channels per group
#define NCH   1024
#define HW    1024
#define SROW  72      // A smem row stride in halves (64 + 8 pad)
#define CHS   72      // B smem per-pixel stride in halves (64 + 8 pad)
#define BROW  (34 * CHS)      // 2448 halves per image row in smem
#define BSPL  (6 * BROW)      // 14688 halves per split (6 halo rows)

// Dynamic smem layout (bytes): bigB + 2 A buffers (64 co each)
#define SM_B    0                     // bigB: 2 * 14688 halves = 58752 B
#define SM_A0   58752                 // A buf 0: 64*72*2 = 9216 B
#define SM_A1   67968                 // A buf 1
#define SM_TOT  77184                 // 75.4 KB -> 2 CTAs/SM

// Device scratch (no allocations allowed)
__device__ float  g_apart[NCOUT * 4];                         // per-(co,slice) |w| partials
__device__ __align__(16) __half g_A[NG * 9 * NCOUT * CING];   // [g][tap][co][ch], +-1
__device__ float  g_bconv[(size_t)NB * NCH * HW];             // 134 MB
__device__ double g_sum[NCH];
__device__ double g_sumsq[NCH];

__device__ __forceinline__ uint32_t smem_u32(const void* p) {
    uint32_t a;
    asm("{ .reg .u64 t; cvta.to.shared.u64 t, %1; cvt.u32.u64 %0, t; }" : "=r"(a) : "l"(p));
    return a;
}
__device__ __forceinline__ void ldsm_x4(uint32_t& r0, uint32_t& r1, uint32_t& r2, uint32_t& r3,
                                        uint32_t addr) {
    asm volatile("ldmatrix.sync.aligned.m8n8.x4.shared.b16 {%0,%1,%2,%3}, [%4];"
                 : "=r"(r0), "=r"(r1), "=r"(r2), "=r"(r3) : "r"(addr));
}
// accumulate: D = A*B + D
__device__ __forceinline__ void mma16816(float& c0, float& c1, float& c2, float& c3,
                                         uint32_t a0, uint32_t a1, uint32_t a2, uint32_t a3,
                                         uint32_t b0, uint32_t b1) {
    asm volatile(
        "mma.sync.aligned.m16n8k16.row.col.f32.f16.f16.f32 "
        "{%0,%1,%2,%3}, {%4,%5,%6,%7}, {%8,%9}, {%0,%1,%2,%3};"
        : "+f"(c0), "+f"(c1), "+f"(c2), "+f"(c3)
        : "r"(a0), "r"(a1), "r"(a2), "r"(a3), "r"(b0), "r"(b1));
}
// overwrite: D = A*B + 0
__device__ __forceinline__ void mma16816_z(float& c0, float& c1, float& c2, float& c3,
                                           uint32_t a0, uint32_t a1, uint32_t a2, uint32_t a3,
                                           uint32_t b0, uint32_t b1) {
    asm volatile(
        "mma.sync.aligned.m16n8k16.row.col.f32.f16.f16.f32 "
        "{%0,%1,%2,%3}, {%4,%5,%6,%7}, {%8,%9}, {%10,%10,%10,%10};"
        : "=f"(c0), "=f"(c1), "=f"(c2), "=f"(c3)
        : "r"(a0), "r"(a1), "r"(a2), "r"(a3), "r"(b0), "r"(b1), "f"(0.0f));
}

// ---------------------------------------------------------------------------
// Kernel 0: per-(co, ci-slice of 64) |w| partial + sign tiles; zero stats.
// grid 1024, 256 threads.
// ---------------------------------------------------------------------------
__global__ void prep_w_kernel(const float* __restrict__ w) {
    const int bid   = blockIdx.x;        // 0..1023
    const int co    = bid >> 2;
    const int slice = bid & 3;           // ci slice: slice*64 .. slice*64+63
    const int t     = threadIdx.x;

    if (t == 0) {
        g_sum[bid]   = 0.0;
        g_sumsq[bid] = 0.0;
    }

    const float* wc = w + ((size_t)co * 256 + slice * 64) * 9;

    float s = 0.0f;
    float wv[3];
    const int n0 = t * 2;
    wv[0] = wc[n0];
    wv[1] = wc[n0 + 1];
    wv[2] = (t < 64) ? wc[512 + t] : 0.0f;
    s = fabsf(wv[0]) + fabsf(wv[1]) + ((t < 64) ? fabsf(wv[2]) : 0.0f);

    __shared__ float red[256];
    red[t] = s;
    __syncthreads();
    for (int o = 128; o > 0; o >>= 1) {
        if (t < o) red[t] += red[t + o];
        __syncthreads();
    }
    if (t == 0) g_apart[bid] = red[0];

#pragma unroll
    for (int u = 0; u < 3; u++) {
        const int e = (u < 2) ? (n0 + u) : (512 + t);
        if (u == 2 && t >= 64) break;
        const int cil = e / 9;
        const int tap = e - cil * 9;
        const __half v = (wv[u] >= 0.0f) ? __float2half_rn(1.0f) : __float2half_rn(-1.0f);
        g_A[((size_t)(slice * 9 + tap) * NCOUT + co) * CING + cil] = v;
    }
}

// ---------------------------------------------------------------------------
// Kernel 1: HMMA implicit GEMM, M=64 tiles for 2 CTAs/SM (R14/15 mainloop,
// byte-identical math). bconv stores use streaming hint (__stcs): write-once
// data streams through L2 evict-first, protecting the x halo regions.
// ---------------------------------------------------------------------------
__global__ void __launch_bounds__(256, 2) conv_mma_kernel(const float* __restrict__ x) {
    extern __shared__ char smem[];
    __half* bigB = reinterpret_cast<__half*>(smem + SM_B);

    const int t     = threadIdx.x;
    const int wid   = t >> 5;
    const int lane  = t & 31;
    const int coq   = blockIdx.x & 3;      // co quarter (64 couts)
    const int ptile = blockIdx.x >> 2;     // 0..7 (4 image rows each)
    const int g     = blockIdx.y;
    const int b     = blockIdx.z;
    const int img   = b * 4 + g;
    const int px0   = ptile * 128;

    const int wm = (wid >> 2) * 32;        // warp M offset (co): 0 or 32
    const int wn = (wid & 3) * 32;         // warp N offset (px): 0,32,64,96

    const uint32_t sB  = smem_u32(bigB);
    const uint32_t sA0 = smem_u32(smem + SM_A0);
    const uint32_t sA1 = smem_u32(smem + SM_A1);

    const int aRow = lane & 15;
    const int aCol = (lane >> 4) * 8;
    const int bRow = (lane & 7) + ((lane >> 4) & 1) * 8;
    const int bCol = ((lane >> 3) & 1) * 8;

    // --- Stage bigB directly from x ---
    {
        const __half2 z2 = __halves2half2(__float2half_rn(0.f), __float2half_rn(0.f));
        for (int i = t; i < 768; i += 256) {        // borders wp 0/33
            int split = (i >= 384) ? 1 : 0;
            int r   = i - split * 384;
            int row = r >> 6;
            int q   = r & 63;
            int wp  = (q >> 5) ? 33 : 0;
            int chp = q & 31;
            *reinterpret_cast<__half2*>(
                bigB + split * BSPL + row * BROW + wp * CHS + chp * 2) = z2;
        }
        const float* xb = x + ((size_t)b * 256 + (size_t)g * 64) * HW;
        for (int i = t; i < 1536; i += 256) {       // interior
            int row = i >> 8;
            int r   = i & 255;
            int chp = r >> 3;
            int wq  = r & 7;
            int xh  = ptile * 4 + row - 1;
            float4 va, vb;
            if (xh >= 0 && xh < 32) {
                const float4* src = reinterpret_cast<const float4*>(
                    xb + (size_t)(chp * 2) * HW + (size_t)xh * 32) + wq;
                va = src[0];
                vb = src[256];
            } else {
                va = make_float4(0.f, 0.f, 0.f, 0.f);
                vb = va;
            }
            const float av[4] = { va.x, va.y, va.z, va.w };
            const float bv[4] = { vb.x, vb.y, vb.z, vb.w };
#pragma unroll
            for (int j = 0; j < 4; j++) {
                const int wp = wq * 4 + j + 1;
                const __half h0 = __float2half_rn(av[j]);
                const __half h1 = __float2half_rn(bv[j]);
                const __half l0 = __float2half_rn(av[j] - __half2float(h0));
                const __half l1 = __float2half_rn(bv[j] - __half2float(h1));
                *reinterpret_cast<__half2*>(
                    bigB + row * BROW + wp * CHS + chp * 2) = __halves2half2(h0, h1);
                *reinterpret_cast<__half2*>(
                    bigB + BSPL + row * BROW + wp * CHS + chp * 2) = __halves2half2(l0, l1);
            }
        }
    }
    // Stage A(tap=0) into buf0
    {
        const float4* srcA = reinterpret_cast<const float4*>(
            g_A + ((size_t)(g * 9) * NCOUT + coq * 64) * CING);
        __half* dst = reinterpret_cast<__half*>(smem + SM_A0);
        for (int i = t; i < 512; i += 256) {
            int row = i >> 3, j = i & 7;
            *reinterpret_cast<float4*>(dst + row * SROW + j * 8) = srcA[i];
        }
    }
    __syncthreads();

    float acc[8][4];     // per-tap sub-accumulator
    float acc2[8][4];    // cross-tap accumulator
#pragma unroll
    for (int i = 0; i < 8; i++)
#pragma unroll
        for (int j = 0; j < 4; j++) acc2[i][j] = 0.0f;

    const int pxb = wn + bRow;
    uint32_t bBase[2];
#pragma unroll
    for (int nb = 0; nb < 2; nb++) {
        const int px = pxb + nb * 16;
        bBase[nb] = sB + (((px >> 5) * BROW) + (px & 31) * CHS + bCol) * 2;
    }

    for (int tap = 0; tap < 9; tap++) {
        const int di = tap / 3, dj = tap - di * 3;
        const uint32_t sAcur = (tap & 1) ? sA1 : sA0;
        const uint32_t bOff = (di * BROW + dj * CHS) * 2;
        const uint32_t aAddr0 = sAcur + ((wm + 0  + aRow) * SROW + aCol) * 2;
        const uint32_t aAddr1 = sAcur + ((wm + 16 + aRow) * SROW + aCol) * 2;

        // prefetch A(tap+1) into the other buffer (overlaps mma)
        if (tap < 8) {
            const float4* srcA = reinterpret_cast<const float4*>(
                g_A + ((size_t)(g * 9 + tap + 1) * NCOUT + coq * 64) * CING);
            __half* dst = reinterpret_cast<__half*>(smem + ((tap & 1) ? SM_A0 : SM_A1));
            for (int i = t; i < 512; i += 256) {
                int row = i >> 3, j = i & 7;
                *reinterpret_cast<float4*>(dst + row * SROW + j * 8) = srcA[i];
            }
        }

#pragma unroll
        for (int split = 0; split < 2; split++) {
            const uint32_t bSplitOff = bOff + split * (BSPL * 2);
#pragma unroll
            for (int k = 0; k < 4; k++) {
                uint32_t a0[4], a1[4];
                ldsm_x4(a0[0], a0[1], a0[2], a0[3], aAddr0 + k * 32);
                ldsm_x4(a1[0], a1[1], a1[2], a1[3], aAddr1 + k * 32);
#pragma unroll
                for (int nb = 0; nb < 2; nb++) {
                    uint32_t r0, r1, r2, r3;
                    ldsm_x4(r0, r1, r2, r3, bBase[nb] + bSplitOff + k * 32);
                    if (split == 0 && k == 0) {
                        mma16816_z(acc[nb * 2][0], acc[nb * 2][1],
                                   acc[nb * 2][2], acc[nb * 2][3],
                                   a0[0], a0[1], a0[2], a0[3], r0, r1);
                        mma16816_z(acc[nb * 2 + 1][0], acc[nb * 2 + 1][1],
                                   acc[nb * 2 + 1][2], acc[nb * 2 + 1][3],
                                   a0[0], a0[1], a0[2], a0[3], r2, r3);
                        mma16816_z(acc[4 + nb * 2][0], acc[4 + nb * 2][1],
                                   acc[4 + nb * 2][2], acc[4 + nb * 2][3],
                                   a1[0], a1[1], a1[2], a1[3], r0, r1);
                        mma16816_z(acc[4 + nb * 2 + 1][0], acc[4 + nb * 2 + 1][1],
                                   acc[4 + nb * 2 + 1][2], acc[4 + nb * 2 + 1][3],
                                   a1[0], a1[1], a1[2], a1[3], r2, r3);
                    } else {
                        mma16816(acc[nb * 2][0], acc[nb * 2][1],
                                 acc[nb * 2][2], acc[nb * 2][3],
                                 a0[0], a0[1], a0[2], a0[3], r0, r1);
                        mma16816(acc[nb * 2 + 1][0], acc[nb * 2 + 1][1],
                                 acc[nb * 2 + 1][2], acc[nb * 2 + 1][3],
                                 a0[0], a0[1], a0[2], a0[3], r2, r3);
                        mma16816(acc[4 + nb * 2][0], acc[4 + nb * 2][1],
                                 acc[4 + nb * 2][2], acc[4 + nb * 2][3],
                                 a1[0], a1[1], a1[2], a1[3], r0, r1);
                        mma16816(acc[4 + nb * 2 + 1][0], acc[4 + nb * 2 + 1][1],
                                 acc[4 + nb * 2 + 1][2], acc[4 + nb * 2 + 1][3],
                                 a1[0], a1[1], a1[2], a1[3], r2, r3);
                    }
                }
            }
        }
        __syncthreads();   // A prefetch visible; this tap's A reads done

#pragma unroll
        for (int i = 0; i < 8; i++)
#pragma unroll
            for (int j = 0; j < 4; j++) acc2[i][j] += acc[i][j];
    }

    // --- Epilogue 1: bconv stores (streaming, evict-first) ---
    const int coBase = coq * 64 + wm;
#pragma unroll
    for (int mi = 0; mi < 2; mi++) {
#pragma unroll
        for (int ni = 0; ni < 4; ni++) {
            const int co_r = coBase + mi * 16 + (lane >> 2);
            const int px_c = px0 + wn + ni * 8 + (lane & 3) * 2;
            float* p0 = &g_bconv[((size_t)img * NCOUT + co_r) * HW + px_c];
            __stcs(reinterpret_cast<float2*>(p0),
                   make_float2(acc2[mi * 4 + ni][0], acc2[mi * 4 + ni][1]));
            __stcs(reinterpret_cast<float2*>(p0 + 8 * HW),
                   make_float2(acc2[mi * 4 + ni][2], acc2[mi * 4 + ni][3]));
        }
    }

    // --- Epilogue 2: fused BN stats ---
    float st1[4], st2[4];
#pragma unroll
    for (int mi = 0; mi < 2; mi++) {
#pragma unroll
        for (int half = 0; half < 2; half++) {
            float s1 = 0.f, s2 = 0.f;
#pragma unroll
            for (int ni = 0; ni < 4; ni++) {
                const float a = acc2[mi * 4 + ni][half * 2 + 0];
                const float c = acc2[mi * 4 + ni][half * 2 + 1];
                s1 += a + c;
                s2 += a * a + c * c;
            }
            st1[mi * 2 + half] = s1;
            st2[mi * 2 + half] = s2;
        }
    }
#pragma unroll
    for (int q = 0; q < 4; q++) {
#pragma unroll
        for (int o = 1; o <= 2; o <<= 1) {
            st1[q] += __shfl_xor_sync(0xFFFFFFFFu, st1[q], o);
            st2[q] += __shfl_xor_sync(0xFFFFFFFFu, st2[q], o);
        }
    }
    __syncthreads();   // ldsm reads done; safe to reuse smem
    float* sbuf = reinterpret_cast<float*>(smem);   // [64 co][4 nwarp][2]
    if ((lane & 3) == 0) {
#pragma unroll
        for (int q = 0; q < 4; q++) {
            const int mi = q >> 1, half = q & 1;
            const int co_l = wm + mi * 16 + half * 8 + (lane >> 2);
            sbuf[(co_l * 4 + (wid & 3)) * 2 + 0] = st1[q];
            sbuf[(co_l * 4 + (wid & 3)) * 2 + 1] = st2[q];
        }
    }
    __syncthreads();
    if (t < 64) {
        float s1 = 0.f, s2 = 0.f;
#pragma unroll
        for (int nw = 0; nw < 4; nw++) {
            s1 += sbuf[(t * 4 + nw) * 2 + 0];
            s2 += sbuf[(t * 4 + nw) * 2 + 1];
        }
        const int ch = g * NCOUT + coq * 64 + t;
        atomicAdd(&g_sum[ch],   (double)s1);
        atomicAdd(&g_sumsq[ch], (double)s2);
    }
}

// ---------------------------------------------------------------------------
// Kernel 2: sign + group merge + qrelu, BN finalize computed ONCE per block
// and reused across 8 batches (grid = co * 4 b-octets = 1024 blocks).
// bconv reads use streaming hint (read-once data).
// ---------------------------------------------------------------------------
__global__ void __launch_bounds__(256) merge_kernel(const float* __restrict__ gamma,
                                                    const float* __restrict__ beta,
                                                    float* __restrict__ out) {
    const int t   = threadIdx.x;
    const int co  = blockIdx.x & (NCOUT - 1);
    const int b0  = (blockIdx.x >> 8) * 8;      // batch octet start

    __shared__ float scA[4], scB[4];
    if (t < 4) {
        const int ch = t * NCOUT + co;   // g = t
        const double N = (double)NB * (double)HW;
        const double a = (((double)g_apart[co * 4 + 0] + (double)g_apart[co * 4 + 1])
                        + ((double)g_apart[co * 4 + 2] + (double)g_apart[co * 4 + 3]))
                       / 2304.0;
        const double mean_b = g_sum[ch] / N;
        const double var_b  = g_sumsq[ch] / N - mean_b * mean_b;
        const double inv    = rsqrt(a * a * var_b + 1e-5) * (double)gamma[ch];
        scA[t] = (float)(a * inv);
        scB[t] = (float)((double)beta[ch] - a * mean_b * inv);
    }
    __syncthreads();

    const float cA0 = scA[0], cB0 = scB[0];
    const float cA1 = scA[1], cB1 = scB[1];
    const float cA2 = scA[2], cB2 = scB[2];
    const float cA3 = scA[3], cB3 = scB[3];
    const float QMID = (8.0f / 15.0f) * 4.0f;

#pragma unroll
    for (int bb = 0; bb < 8; bb++) {
        const int b = b0 + bb;
        float4 v[NG];
#pragma unroll
        for (int g = 0; g < NG; g++) {
            const size_t idx = ((((size_t)b * NG + g) * NCOUT + co) * (HW / 4)) + t;
            v[g] = __ldcs(reinterpret_cast<const float4*>(g_bconv) + idx);
        }
        int y0, y1, y2, y3;
        y0  = (fmaf(v[0].x, cA0, cB0) >= 0.0f) ? 1 : -1;
        y1  = (fmaf(v[0].y, cA0, cB0) >= 0.0f) ? 1 : -1;
        y2  = (fmaf(v[0].z, cA0, cB0) >= 0.0f) ? 1 : -1;
        y3  = (fmaf(v[0].w, cA0, cB0) >= 0.0f) ? 1 : -1;
        y0 += (fmaf(v[1].x, cA1, cB1) >= 0.0f) ? 1 : -1;
        y1 += (fmaf(v[1].y, cA1, cB1) >= 0.0f) ? 1 : -1;
        y2 += (fmaf(v[1].z, cA1, cB1) >= 0.0f) ? 1 : -1;
        y3 += (fmaf(v[1].w, cA1, cB1) >= 0.0f) ? 1 : -1;
        y0 += (fmaf(v[2].x, cA2, cB2) >= 0.0f) ? 1 : -1;
        y1 += (fmaf(v[2].y, cA2, cB2) >= 0.0f) ? 1 : -1;
        y2 += (fmaf(v[2].z, cA2, cB2) >= 0.0f) ? 1 : -1;
        y3 += (fmaf(v[2].w, cA2, cB2) >= 0.0f) ? 1 : -1;
        y0 += (fmaf(v[3].x, cA3, cB3) >= 0.0f) ? 1 : -1;
        y1 += (fmaf(v[3].y, cA3, cB3) >= 0.0f) ? 1 : -1;
        y2 += (fmaf(v[3].z, cA3, cB3) >= 0.0f) ? 1 : -1;
        y3 += (fmaf(v[3].w, cA3, cB3) >= 0.0f) ? 1 : -1;

        float4 o;
        o.x = (y0 >= 4) ? 4.0f : ((y0 >= 2) ? QMID : 0.0f);
        o.y = (y1 >= 4) ? 4.0f : ((y1 >= 2) ? QMID : 0.0f);
        o.z = (y2 >= 4) ? 4.0f : ((y2 >= 2) ? QMID : 0.0f);
        o.w = (y3 >= 4) ? 4.0f : ((y3 >= 2) ? QMID : 0.0f);
        reinterpret_cast<float4*>(out)[((size_t)b * NCOUT + co) * 256 + t] = o;
    }
}

// ---------------------------------------------------------------------------
extern "C" void kernel_launch(void* const* d_in, const int* in_sizes, int n_in,
                              void* d_out, int out_size) {
    (void)in_sizes; (void)n_in; (void)out_size;
    const float* x     = (const float*)d_in[0];
    const float* w     = (const float*)d_in[1];
    const float* gamma = (const float*)d_in[2];
    const float* beta  = (const float*)d_in[3];
    float* out = (float*)d_out;

    // Host-side attribute set (idempotent, capture-safe, no device work)
    cudaFuncSetAttribute(conv_mma_kernel,
                         cudaFuncAttributeMaxDynamicSharedMemorySize, SM_TOT);

    prep_w_kernel<<<NCOUT * 4, 256>>>(w);
    conv_mma_kernel<<<dim3(32, NG, NB), 256, SM_TOT>>>(x);
    merge_kernel<<<NCOUT * 4, 256>>>(gamma, beta, out);
}

// round 17
// speedup vs baseline: 7.3846x; 1.0014x over previous
#include <cuda_runtime.h>
#include <cuda_fp16.h>
#include <cstdint>

// Problem constants
#define NB    32
#define NG    4
#define NCOUT 256     // output channels per group
#define CING  64      // input channels per group
#define NCH   1024
#define HW    1024
#define SROW  72      // A smem row stride in halves (64 + 8 pad)
#define CHS   72      // B smem per-pixel stride in halves (64 + 8 pad)
#define BROW  (34 * CHS)      // 2448 halves per image row in smem
#define BSPL  (6 * BROW)      // 14688 halves per split (6 halo rows)

// Dynamic smem layout (bytes): bigB + 2 A buffers (64 co each)
#define SM_B    0                     // bigB: 2 * 14688 halves = 58752 B
#define SM_A0   58752                 // A buf 0: 64*72*2 = 9216 B
#define SM_A1   67968                 // A buf 1
#define SM_TOT  77184                 // 75.4 KB -> 2 CTAs/SM

// Device scratch (no allocations allowed)
__device__ float  g_apart[NCOUT * 4];                         // per-(co,slice) |w| partials
__device__ __align__(16) __half g_A[NG * 9 * NCOUT * CING];   // [g][tap][co][ch], +-1
__device__ float  g_bconv[(size_t)NB * NCH * HW];             // 134 MB
__device__ double g_sum[NCH];
__device__ double g_sumsq[NCH];

__device__ __forceinline__ uint32_t smem_u32(const void* p) {
    uint32_t a;
    asm("{ .reg .u64 t; cvta.to.shared.u64 t, %1; cvt.u32.u64 %0, t; }" : "=r"(a) : "l"(p));
    return a;
}
__device__ __forceinline__ void ldsm_x4(uint32_t& r0, uint32_t& r1, uint32_t& r2, uint32_t& r3,
                                        uint32_t addr) {
    asm volatile("ldmatrix.sync.aligned.m8n8.x4.shared.b16 {%0,%1,%2,%3}, [%4];"
                 : "=r"(r0), "=r"(r1), "=r"(r2), "=r"(r3) : "r"(addr));
}
// accumulate: D = A*B + D
__device__ __forceinline__ void mma16816(float& c0, float& c1, float& c2, float& c3,
                                         uint32_t a0, uint32_t a1, uint32_t a2, uint32_t a3,
                                         uint32_t b0, uint32_t b1) {
    asm volatile(
        "mma.sync.aligned.m16n8k16.row.col.f32.f16.f16.f32 "
        "{%0,%1,%2,%3}, {%4,%5,%6,%7}, {%8,%9}, {%0,%1,%2,%3};"
        : "+f"(c0), "+f"(c1), "+f"(c2), "+f"(c3)
        : "r"(a0), "r"(a1), "r"(a2), "r"(a3), "r"(b0), "r"(b1));
}
// overwrite: D = A*B + 0
__device__ __forceinline__ void mma16816_z(float& c0, float& c1, float& c2, float& c3,
                                           uint32_t a0, uint32_t a1, uint32_t a2, uint32_t a3,
                                           uint32_t b0, uint32_t b1) {
    asm volatile(
        "mma.sync.aligned.m16n8k16.row.col.f32.f16.f16.f32 "
        "{%0,%1,%2,%3}, {%4,%5,%6,%7}, {%8,%9}, {%10,%10,%10,%10};"
        : "=f"(c0), "=f"(c1), "=f"(c2), "=f"(c3)
        : "r"(a0), "r"(a1), "r"(a2), "r"(a3), "r"(b0), "r"(b1), "f"(0.0f));
}

// ---------------------------------------------------------------------------
// Kernel 0: per-(co, ci-slice of 64) |w| partial + sign tiles; zero stats.
// grid 1024, 256 threads. (Implicit PDL completion trigger at kernel end.)
// ---------------------------------------------------------------------------
__global__ void prep_w_kernel(const float* __restrict__ w) {
    const int bid   = blockIdx.x;        // 0..1023
    const int co    = bid >> 2;
    const int slice = bid & 3;           // ci slice: slice*64 .. slice*64+63
    const int t     = threadIdx.x;

    if (t == 0) {
        g_sum[bid]   = 0.0;
        g_sumsq[bid] = 0.0;
    }

    const float* wc = w + ((size_t)co * 256 + slice * 64) * 9;

    float s = 0.0f;
    float wv[3];
    const int n0 = t * 2;
    wv[0] = wc[n0];
    wv[1] = wc[n0 + 1];
    wv[2] = (t < 64) ? wc[512 + t] : 0.0f;
    s = fabsf(wv[0]) + fabsf(wv[1]) + ((t < 64) ? fabsf(wv[2]) : 0.0f);

    __shared__ float red[256];
    red[t] = s;
    __syncthreads();
    for (int o = 128; o > 0; o >>= 1) {
        if (t < o) red[t] += red[t + o];
        __syncthreads();
    }
    if (t == 0) g_apart[bid] = red[0];

#pragma unroll
    for (int u = 0; u < 3; u++) {
        const int e = (u < 2) ? (n0 + u) : (512 + t);
        if (u == 2 && t >= 64) break;
        const int cil = e / 9;
        const int tap = e - cil * 9;
        const __half v = (wv[u] >= 0.0f) ? __float2half_rn(1.0f) : __float2half_rn(-1.0f);
        g_A[((size_t)(slice * 9 + tap) * NCOUT + co) * CING + cil] = v;
    }
}

// ---------------------------------------------------------------------------
// Kernel 1: HMMA implicit GEMM, M=64 tiles for 2 CTAs/SM (R16 mainloop,
// byte-identical math). Launched with PDL: starts while prep_w runs,
// stages the B halo (reads only x), then cudaGridDependencySynchronize()
// before consuming prep_w's outputs (g_A; g_sum zeroing consumed at the
// epilogue atomics, after the sync point).
// ---------------------------------------------------------------------------
__global__ void __launch_bounds__(256, 2) conv_mma_kernel(const float* __restrict__ x) {
    extern __shared__ char smem[];
    __half* bigB = reinterpret_cast<__half*>(smem + SM_B);

    const int t     = threadIdx.x;
    const int wid   = t >> 5;
    const int lane  = t & 31;
    const int coq   = blockIdx.x & 3;      // co quarter (64 couts)
    const int ptile = blockIdx.x >> 2;     // 0..7 (4 image rows each)
    const int g     = blockIdx.y;
    const int b     = blockIdx.z;
    const int img   = b * 4 + g;
    const int px0   = ptile * 128;

    const int wm = (wid >> 2) * 32;        // warp M offset (co): 0 or 32
    const int wn = (wid & 3) * 32;         // warp N offset (px): 0,32,64,96

    const uint32_t sB  = smem_u32(bigB);
    const uint32_t sA0 = smem_u32(smem + SM_A0);
    const uint32_t sA1 = smem_u32(smem + SM_A1);

    const int aRow = lane & 15;
    const int aCol = (lane >> 4) * 8;
    const int bRow = (lane & 7) + ((lane >> 4) & 1) * 8;
    const int bCol = ((lane >> 3) & 1) * 8;

    // --- Stage bigB directly from x (independent of prep_w) ---
    {
        const __half2 z2 = __halves2half2(__float2half_rn(0.f), __float2half_rn(0.f));
        for (int i = t; i < 768; i += 256) {        // borders wp 0/33
            int split = (i >= 384) ? 1 : 0;
            int r   = i - split * 384;
            int row = r >> 6;
            int q   = r & 63;
            int wp  = (q >> 5) ? 33 : 0;
            int chp = q & 31;
            *reinterpret_cast<__half2*>(
                bigB + split * BSPL + row * BROW + wp * CHS + chp * 2) = z2;
        }
        const float* xb = x + ((size_t)b * 256 + (size_t)g * 64) * HW;
        for (int i = t; i < 1536; i += 256) {       // interior
            int row = i >> 8;
            int r   = i & 255;
            int chp = r >> 3;
            int wq  = r & 7;
            int xh  = ptile * 4 + row - 1;
            float4 va, vb;
            if (xh >= 0 && xh < 32) {
                const float4* src = reinterpret_cast<const float4*>(
                    xb + (size_t)(chp * 2) * HW + (size_t)xh * 32) + wq;
                va = src[0];
                vb = src[256];
            } else {
                va = make_float4(0.f, 0.f, 0.f, 0.f);
                vb = va;
            }
            const float av[4] = { va.x, va.y, va.z, va.w };
            const float bv[4] = { vb.x, vb.y, vb.z, vb.w };
#pragma unroll
            for (int j = 0; j < 4; j++) {
                const int wp = wq * 4 + j + 1;
                const __half h0 = __float2half_rn(av[j]);
                const __half h1 = __float2half_rn(bv[j]);
                const __half l0 = __float2half_rn(av[j] - __half2float(h0));
                const __half l1 = __float2half_rn(bv[j] - __half2float(h1));
                *reinterpret_cast<__half2*>(
                    bigB + row * BROW + wp * CHS + chp * 2) = __halves2half2(h0, h1);
                *reinterpret_cast<__half2*>(
                    bigB + BSPL + row * BROW + wp * CHS + chp * 2) = __halves2half2(l0, l1);
            }
        }
    }

    // PDL: wait for prep_w (g_A + stats zeroing) before consuming them.
    cudaGridDependencySynchronize();

    // Stage A(tap=0) into buf0
    {
        const float4* srcA = reinterpret_cast<const float4*>(
            g_A + ((size_t)(g * 9) * NCOUT + coq * 64) * CING);
        __half* dst = reinterpret_cast<__half*>(smem + SM_A0);
        for (int i = t; i < 512; i += 256) {
            int row = i >> 3, j = i & 7;
            *reinterpret_cast<float4*>(dst + row * SROW + j * 8) = srcA[i];
        }
    }
    __syncthreads();

    float acc[8][4];     // per-tap sub-accumulator
    float acc2[8][4];    // cross-tap accumulator
#pragma unroll
    for (int i = 0; i < 8; i++)
#pragma unroll
        for (int j = 0; j < 4; j++) acc2[i][j] = 0.0f;

    const int pxb = wn + bRow;
    uint32_t bBase[2];
#pragma unroll
    for (int nb = 0; nb < 2; nb++) {
        const int px = pxb + nb * 16;
        bBase[nb] = sB + (((px >> 5) * BROW) + (px & 31) * CHS + bCol) * 2;
    }

    for (int tap = 0; tap < 9; tap++) {
        const int di = tap / 3, dj = tap - di * 3;
        const uint32_t sAcur = (tap & 1) ? sA1 : sA0;
        const uint32_t bOff = (di * BROW + dj * CHS) * 2;
        const uint32_t aAddr0 = sAcur + ((wm + 0  + aRow) * SROW + aCol) * 2;
        const uint32_t aAddr1 = sAcur + ((wm + 16 + aRow) * SROW + aCol) * 2;

        // prefetch A(tap+1) into the other buffer (overlaps mma)
        if (tap < 8) {
            const float4* srcA = reinterpret_cast<const float4*>(
                g_A + ((size_t)(g * 9 + tap + 1) * NCOUT + coq * 64) * CING);
            __half* dst = reinterpret_cast<__half*>(smem + ((tap & 1) ? SM_A0 : SM_A1));
            for (int i = t; i < 512; i += 256) {
                int row = i >> 3, j = i & 7;
                *reinterpret_cast<float4*>(dst + row * SROW + j * 8) = srcA[i];
            }
        }

#pragma unroll
        for (int split = 0; split < 2; split++) {
            const uint32_t bSplitOff = bOff + split * (BSPL * 2);
#pragma unroll
            for (int k = 0; k < 4; k++) {
                uint32_t a0[4], a1[4];
                ldsm_x4(a0[0], a0[1], a0[2], a0[3], aAddr0 + k * 32);
                ldsm_x4(a1[0], a1[1], a1[2], a1[3], aAddr1 + k * 32);
#pragma unroll
                for (int nb = 0; nb < 2; nb++) {
                    uint32_t r0, r1, r2, r3;
                    ldsm_x4(r0, r1, r2, r3, bBase[nb] + bSplitOff + k * 32);
                    if (split == 0 && k == 0) {
                        mma16816_z(acc[nb * 2][0], acc[nb * 2][1],
                                   acc[nb * 2][2], acc[nb * 2][3],
                                   a0[0], a0[1], a0[2], a0[3], r0, r1);
                        mma16816_z(acc[nb * 2 + 1][0], acc[nb * 2 + 1][1],
                                   acc[nb * 2 + 1][2], acc[nb * 2 + 1][3],
                                   a0[0], a0[1], a0[2], a0[3], r2, r3);
                        mma16816_z(acc[4 + nb * 2][0], acc[4 + nb * 2][1],
                                   acc[4 + nb * 2][2], acc[4 + nb * 2][3],
                                   a1[0], a1[1], a1[2], a1[3], r0, r1);
                        mma16816_z(acc[4 + nb * 2 + 1][0], acc[4 + nb * 2 + 1][1],
                                   acc[4 + nb * 2 + 1][2], acc[4 + nb * 2 + 1][3],
                                   a1[0], a1[1], a1[2], a1[3], r2, r3);
                    } else {
                        mma16816(acc[nb * 2][0], acc[nb * 2][1],
                                 acc[nb * 2][2], acc[nb * 2][3],
                                 a0[0], a0[1], a0[2], a0[3], r0, r1);
                        mma16816(acc[nb * 2 + 1][0], acc[nb * 2 + 1][1],
                                 acc[nb * 2 + 1][2], acc[nb * 2 + 1][3],
                                 a0[0], a0[1], a0[2], a0[3], r2, r3);
                        mma16816(acc[4 + nb * 2][0], acc[4 + nb * 2][1],
                                 acc[4 + nb * 2][2], acc[4 + nb * 2][3],
                                 a1[0], a1[1], a1[2], a1[3], r0, r1);
                        mma16816(acc[4 + nb * 2 + 1][0], acc[4 + nb * 2 + 1][1],
                                 acc[4 + nb * 2 + 1][2], acc[4 + nb * 2 + 1][3],
                                 a1[0], a1[1], a1[2], a1[3], r2, r3);
                    }
                }
            }
        }
        __syncthreads();   // A prefetch visible; this tap's A reads done

#pragma unroll
        for (int i = 0; i < 8; i++)
#pragma unroll
            for (int j = 0; j < 4; j++) acc2[i][j] += acc[i][j];
    }

    // --- Epilogue 1: bconv stores (streaming, evict-first) ---
    const int coBase = coq * 64 + wm;
#pragma unroll
    for (int mi = 0; mi < 2; mi++) {
#pragma unroll
        for (int ni = 0; ni < 4; ni++) {
            const int co_r = coBase + mi * 16 + (lane >> 2);
            const int px_c = px0 + wn + ni * 8 + (lane & 3) * 2;
            float* p0 = &g_bconv[((size_t)img * NCOUT + co_r) * HW + px_c];
            __stcs(reinterpret_cast<float2*>(p0),
                   make_float2(acc2[mi * 4 + ni][0], acc2[mi * 4 + ni][1]));
            __stcs(reinterpret_cast<float2*>(p0 + 8 * HW),
                   make_float2(acc2[mi * 4 + ni][2], acc2[mi * 4 + ni][3]));
        }
    }

    // --- Epilogue 2: fused BN stats ---
    float st1[4], st2[4];
#pragma unroll
    for (int mi = 0; mi < 2; mi++) {
#pragma unroll
        for (int half = 0; half < 2; half++) {
            float s1 = 0.f, s2 = 0.f;
#pragma unroll
            for (int ni = 0; ni < 4; ni++) {
                const float a = acc2[mi * 4 + ni][half * 2 + 0];
                const float c = acc2[mi * 4 + ni][half * 2 + 1];
                s1 += a + c;
                s2 += a * a + c * c;
            }
            st1[mi * 2 + half] = s1;
            st2[mi * 2 + half] = s2;
        }
    }
#pragma unroll
    for (int q = 0; q < 4; q++) {
#pragma unroll
        for (int o = 1; o <= 2; o <<= 1) {
            st1[q] += __shfl_xor_sync(0xFFFFFFFFu, st1[q], o);
            st2[q] += __shfl_xor_sync(0xFFFFFFFFu, st2[q], o);
        }
    }
    __syncthreads();   // ldsm reads done; safe to reuse smem
    float* sbuf = reinterpret_cast<float*>(smem);   // [64 co][4 nwarp][2]
    if ((lane & 3) == 0) {
#pragma unroll
        for (int q = 0; q < 4; q++) {
            const int mi = q >> 1, half = q & 1;
            const int co_l = wm + mi * 16 + half * 8 + (lane >> 2);
            sbuf[(co_l * 4 + (wid & 3)) * 2 + 0] = st1[q];
            sbuf[(co_l * 4 + (wid & 3)) * 2 + 1] = st2[q];
        }
    }
    __syncthreads();
    if (t < 64) {
        float s1 = 0.f, s2 = 0.f;
#pragma unroll
        for (int nw = 0; nw < 4; nw++) {
            s1 += sbuf[(t * 4 + nw) * 2 + 0];
            s2 += sbuf[(t * 4 + nw) * 2 + 1];
        }
        const int ch = g * NCOUT + coq * 64 + t;
        atomicAdd(&g_sum[ch],   (double)s1);
        atomicAdd(&g_sumsq[ch], (double)s2);
    }
}

// ---------------------------------------------------------------------------
// Kernel 2: sign + group merge + qrelu, BN finalize once per block,
// 8 batches per block, streaming reads. (Unchanged R16.)
// ---------------------------------------------------------------------------
__global__ void __launch_bounds__(256) merge_kernel(const float* __restrict__ gamma,
                                                    const float* __restrict__ beta,
                                                    float* __restrict__ out) {
    const int t   = threadIdx.x;
    const int co  = blockIdx.x & (NCOUT - 1);
    const int b0  = (blockIdx.x >> 8) * 8;      // batch octet start

    __shared__ float scA[4], scB[4];
    if (t < 4) {
        const int ch = t * NCOUT + co;   // g = t
        const double N = (double)NB * (double)HW;
        const double a = (((double)g_apart[co * 4 + 0] + (double)g_apart[co * 4 + 1])
                        + ((double)g_apart[co * 4 + 2] + (double)g_apart[co * 4 + 3]))
                       / 2304.0;
        const double mean_b = g_sum[ch] / N;
        const double var_b  = g_sumsq[ch] / N - mean_b * mean_b;
        const double inv    = rsqrt(a * a * var_b + 1e-5) * (double)gamma[ch];
        scA[t] = (float)(a * inv);
        scB[t] = (float)((double)beta[ch] - a * mean_b * inv);
    }
    __syncthreads();

    const float cA0 = scA[0], cB0 = scB[0];
    const float cA1 = scA[1], cB1 = scB[1];
    const float cA2 = scA[2], cB2 = scB[2];
    const float cA3 = scA[3], cB3 = scB[3];
    const float QMID = (8.0f / 15.0f) * 4.0f;

#pragma unroll
    for (int bb = 0; bb < 8; bb++) {
        const int b = b0 + bb;
        float4 v[NG];
#pragma unroll
        for (int g = 0; g < NG; g++) {
            const size_t idx = ((((size_t)b * NG + g) * NCOUT + co) * (HW / 4)) + t;
            v[g] = __ldcs(reinterpret_cast<const float4*>(g_bconv) + idx);
        }
        int y0, y1, y2, y3;
        y0  = (fmaf(v[0].x, cA0, cB0) >= 0.0f) ? 1 : -1;
        y1  = (fmaf(v[0].y, cA0, cB0) >= 0.0f) ? 1 : -1;
        y2  = (fmaf(v[0].z, cA0, cB0) >= 0.0f) ? 1 : -1;
        y3  = (fmaf(v[0].w, cA0, cB0) >= 0.0f) ? 1 : -1;
        y0 += (fmaf(v[1].x, cA1, cB1) >= 0.0f) ? 1 : -1;
        y1 += (fmaf(v[1].y, cA1, cB1) >= 0.0f) ? 1 : -1;
        y2 += (fmaf(v[1].z, cA1, cB1) >= 0.0f) ? 1 : -1;
        y3 += (fmaf(v[1].w, cA1, cB1) >= 0.0f) ? 1 : -1;
        y0 += (fmaf(v[2].x, cA2, cB2) >= 0.0f) ? 1 : -1;
        y1 += (fmaf(v[2].y, cA2, cB2) >= 0.0f) ? 1 : -1;
        y2 += (fmaf(v[2].z, cA2, cB2) >= 0.0f) ? 1 : -1;
        y3 += (fmaf(v[2].w, cA2, cB2) >= 0.0f) ? 1 : -1;
        y0 += (fmaf(v[3].x, cA3, cB3) >= 0.0f) ? 1 : -1;
        y1 += (fmaf(v[3].y, cA3, cB3) >= 0.0f) ? 1 : -1;
        y2 += (fmaf(v[3].z, cA3, cB3) >= 0.0f) ? 1 : -1;
        y3 += (fmaf(v[3].w, cA3, cB3) >= 0.0f) ? 1 : -1;

        float4 o;
        o.x = (y0 >= 4) ? 4.0f : ((y0 >= 2) ? QMID : 0.0f);
        o.y = (y1 >= 4) ? 4.0f : ((y1 >= 2) ? QMID : 0.0f);
        o.z = (y2 >= 4) ? 4.0f : ((y2 >= 2) ? QMID : 0.0f);
        o.w = (y3 >= 4) ? 4.0f : ((y3 >= 2) ? QMID : 0.0f);
        reinterpret_cast<float4*>(out)[((size_t)b * NCOUT + co) * 256 + t] = o;
    }
}

// ---------------------------------------------------------------------------
extern "C" void kernel_launch(void* const* d_in, const int* in_sizes, int n_in,
                              void* d_out, int out_size) {
    (void)in_sizes; (void)n_in; (void)out_size;
    const float* x     = (const float*)d_in[0];
    const float* w     = (const float*)d_in[1];
    const float* gamma = (const float*)d_in[2];
    const float* beta  = (const float*)d_in[3];
    float* out = (float*)d_out;

    // Host-side attribute set (idempotent, capture-safe, no device work)
    cudaFuncSetAttribute(conv_mma_kernel,
                         cudaFuncAttributeMaxDynamicSharedMemorySize, SM_TOT);

    prep_w_kernel<<<NCOUT * 4, 256>>>(w);

    // PDL launch: conv may start while prep_w runs; it synchronizes via
    // cudaGridDependencySynchronize() before consuming prep_w outputs.
    {
        cudaLaunchConfig_t cfg = {};
        cfg.gridDim = dim3(32, NG, NB);
        cfg.blockDim = dim3(256, 1, 1);
        cfg.dynamicSmemBytes = SM_TOT;
        cfg.stream = 0;
        cudaLaunchAttribute attrs[1];
        attrs[0].id = cudaLaunchAttributeProgrammaticStreamSerialization;
        attrs[0].val.programmaticStreamSerializationAllowed = 1;
        cfg.attrs = attrs;
        cfg.numAttrs = 1;
        cudaLaunchKernelEx(&cfg, conv_mma_kernel, x);
    }

    merge_kernel<<<NCOUT * 4, 256>>>(gamma, beta, out);
}